// round 2
// baseline (speedup 1.0000x reference)
#include <cuda_runtime.h>
#include <cuda_bf16.h>
#include <cstddef>

#define TT   20
#define BB   64
#define NNF  196
#define VDIM 512
#define HDIM 512
#define VOC  10000
#define G4   2048   // 4*HDIM
#define KSPL 8

// ---------------- static device scratch (no runtime allocation) ----------------
__device__ float g_fmean[BB * VDIM];
__device__ float g_ctx  [BB * VDIM];
__device__ float g_gctx [BB * G4];
__device__ float g_gpre [TT * BB * G4];          // 10.5 MB
__device__ float g_h    [BB * HDIM];
__device__ float g_c    [BB * HDIM];
__device__ float g_hall [TT * BB * HDIM];
__device__ float g_words[TT * BB * VOC];         // 51.2 MB
__device__ float g_gpart[KSPL * BB * G4];        // 4 MB k-split partials
__device__ int   g_rowmap[TT * BB];

// ---------------- attention + feature mean (step-invariant) ----------------
__global__ void __launch_bounds__(256) attn_kernel(const float* __restrict__ features,
                                                   const float* __restrict__ W_av) {
    const int b = blockIdx.x;
    __shared__ float sW[VDIM];
    __shared__ float sA[NNF];
    __shared__ float sred[8];
    __shared__ float s_max, s_inv;
    const int tid  = threadIdx.x;
    const int wid  = tid >> 5, lane = tid & 31;

    for (int i = tid; i < VDIM; i += 256) sW[i] = W_av[i];
    __syncthreads();

    const float* fb = features + (size_t)b * NNF * VDIM;

    // logits (b_av and att_h dropped: softmax is shift-invariant over n)
    for (int n = wid; n < NNF; n += 8) {
        const float* fr = fb + (size_t)n * VDIM;
        float s = 0.f;
        for (int k = lane; k < VDIM; k += 32) s = fmaf(fr[k], sW[k], s);
        #pragma unroll
        for (int o = 16; o; o >>= 1) s += __shfl_down_sync(0xffffffffu, s, o);
        if (!lane) sA[n] = s;
    }
    __syncthreads();

    // softmax over N=196: max
    float m = -3.0e38f;
    for (int n = tid; n < NNF; n += 256) m = fmaxf(m, sA[n]);
    #pragma unroll
    for (int o = 16; o; o >>= 1) m = fmaxf(m, __shfl_down_sync(0xffffffffu, m, o));
    if (!lane) sred[wid] = m;
    __syncthreads();
    if (tid == 0) {
        float mm = sred[0];
        #pragma unroll
        for (int i = 1; i < 8; i++) mm = fmaxf(mm, sred[i]);
        s_max = mm;
    }
    __syncthreads();
    const float mm = s_max;

    float s = 0.f;
    for (int n = tid; n < NNF; n += 256) { float e = __expf(sA[n] - mm); sA[n] = e; s += e; }
    #pragma unroll
    for (int o = 16; o; o >>= 1) s += __shfl_down_sync(0xffffffffu, s, o);
    if (!lane) sred[wid] = s;
    __syncthreads();
    if (tid == 0) {
        float ss = 0.f;
        #pragma unroll
        for (int i = 0; i < 8; i++) ss += sred[i];
        s_inv = 1.f / ss;
    }
    __syncthreads();
    const float inv = s_inv;

    // ctx[b,v] = sum_n attn[n]*f[n,v];  fmean[b,v] = mean_n f[n,v]
    for (int v = tid; v < VDIM; v += 256) {
        float ac = 0.f, am = 0.f;
        #pragma unroll 4
        for (int n = 0; n < NNF; n++) {
            float f = fb[(size_t)n * VDIM + v];
            ac = fmaf(sA[n], f, ac);
            am += f;
        }
        g_ctx  [b * VDIM + v] = ac * inv;
        g_fmean[b * VDIM + v] = am * (1.f / (float)NNF);
    }
}

// ---------------- rowmap: r = t*64+b -> token id ----------------
__global__ void rowmap_kernel(const int* __restrict__ captions) {
    int r = blockIdx.x * 256 + threadIdx.x;
    if (r < TT * BB) {
        int b = r & 63, t = r >> 6;
        g_rowmap[r] = captions[b * TT + t];
    }
}

// ---------------- generic fp32 GEMM: C[m,n] = sum_k A[row(m),k]*B[n,k] ----------------
// BM=64, BN=128, BK=16, 256 threads, 4x8 microtile. Optional gather on A rows,
// optional K-split via blockIdx.z (each z writes C + z*cz_stride over its K chunk),
// optional bias(n) x2 and add-matrix (applied only on z==0).
__global__ void __launch_bounds__(256) gemm_tn(
    const float* __restrict__ A, int lda, const int* __restrict__ gather,
    const float* __restrict__ B, int ldb,
    float* __restrict__ C, int ldc, long long cz_stride,
    int M, int N, int kTotal, int ksplit,
    const float* __restrict__ bias0, const float* __restrict__ bias1,
    const float* __restrict__ addC, int ldadd, int addmask)
{
    __shared__ __align__(16) float As[16][64];
    __shared__ __align__(16) float Bs[16][128];
    const int tid = threadIdx.x;
    const int m0  = blockIdx.x * 64;
    const int n0  = blockIdx.y * 128;
    const int z   = blockIdx.z;
    const int kchunk = kTotal / ksplit;
    const int k0beg  = z * kchunk;
    const int k0end  = k0beg + kchunk;

    float* Cz = C + (long long)z * cz_stride;

    const int tn = (tid & 15) * 8;   // 0..120
    const int tm = (tid >> 4) * 4;   // 0..60

    float acc[4][8];
    #pragma unroll
    for (int i = 0; i < 4; i++)
        #pragma unroll
        for (int j = 0; j < 8; j++) acc[i][j] = 0.f;

    // A staging: 64 rows x 4 float4 -> 1 per thread
    const int arow = tid >> 2;
    const int akv  = (tid & 3) * 4;
    int grow = m0 + arow;
    if (gather) grow = gather[grow];
    const float* Arow = A + (size_t)grow * lda;

    // B staging: 128 rows x 4 float4 -> 2 per thread (same row, k halves)
    const int brow = tid >> 1;
    const int bkv  = (tid & 1) * 8;
    const bool bok = (n0 + brow) < N;
    const float* Brow = B + (size_t)(n0 + brow) * ldb;

    for (int k0 = k0beg; k0 < k0end; k0 += 16) {
        float4 av = *(const float4*)(Arow + k0 + akv);
        float4 b0 = make_float4(0.f, 0.f, 0.f, 0.f);
        float4 b1 = make_float4(0.f, 0.f, 0.f, 0.f);
        if (bok) {
            b0 = *(const float4*)(Brow + k0 + bkv);
            b1 = *(const float4*)(Brow + k0 + bkv + 4);
        }
        __syncthreads();
        As[akv + 0][arow] = av.x;
        As[akv + 1][arow] = av.y;
        As[akv + 2][arow] = av.z;
        As[akv + 3][arow] = av.w;
        Bs[bkv + 0][brow] = b0.x;
        Bs[bkv + 1][brow] = b0.y;
        Bs[bkv + 2][brow] = b0.z;
        Bs[bkv + 3][brow] = b0.w;
        Bs[bkv + 4][brow] = b1.x;
        Bs[bkv + 5][brow] = b1.y;
        Bs[bkv + 6][brow] = b1.z;
        Bs[bkv + 7][brow] = b1.w;
        __syncthreads();

        #pragma unroll
        for (int kk = 0; kk < 16; kk++) {
            float4 a01 = *(const float4*)&As[kk][tm];
            float4 bv0 = *(const float4*)&Bs[kk][tn];
            float4 bv1 = *(const float4*)&Bs[kk][tn + 4];
            float a[4] = {a01.x, a01.y, a01.z, a01.w};
            float bb[8] = {bv0.x, bv0.y, bv0.z, bv0.w, bv1.x, bv1.y, bv1.z, bv1.w};
            #pragma unroll
            for (int i = 0; i < 4; i++)
                #pragma unroll
                for (int j = 0; j < 8; j++)
                    acc[i][j] = fmaf(a[i], bb[j], acc[i][j]);
        }
    }

    const bool doadd = (z == 0);
    #pragma unroll
    for (int i = 0; i < 4; i++) {
        const int m = m0 + tm + i;
        #pragma unroll
        for (int j = 0; j < 8; j++) {
            const int n = n0 + tn + j;
            if (n < N) {
                float v = acc[i][j];
                if (doadd) {
                    if (bias0) v += bias0[n];
                    if (bias1) v += bias1[n];
                    if (addC)  v += addC[(size_t)(m & addmask) * ldadd + n];
                }
                Cz[(size_t)m * ldc + n] = v;
            }
        }
    }
}

// ---------------- reduce k-split partials + LSTM cell update ----------------
__global__ void __launch_bounds__(256) cell_kernel(int t) {
    const int id = blockIdx.x * 256 + threadIdx.x;   // 0..32767
    const int b = id >> 9, u = id & 511;
    float gi = 0.f, gf = 0.f, gg = 0.f, go = 0.f;
    #pragma unroll
    for (int z = 0; z < KSPL; z++) {
        const float* p = g_gpart + (size_t)z * BB * G4 + (size_t)b * G4;
        gi += p[u];
        gf += p[u + 512];
        gg += p[u + 1024];
        go += p[u + 1536];
    }
    const float c  = g_c[id];
    const float si = 1.f / (1.f + __expf(-gi));
    const float sf = 1.f / (1.f + __expf(-gf));
    const float so = 1.f / (1.f + __expf(-go));
    const float tg = tanhf(gg);
    const float cn = sf * c + si * tg;
    const float h  = so * tanhf(cn);
    g_c[id] = cn;
    g_h[id] = h;
    g_hall[(size_t)t * BB * HDIM + id] = h;
}

// ---------------- fused log_softmax + softmax over V=10000 ----------------
__global__ void __launch_bounds__(256) softmax_kernel(float* __restrict__ out) {
    const int r = blockIdx.x;                  // 0..1279 (t*64+b)
    const float* x  = g_words + (size_t)r * VOC;
    float* ols = out + (size_t)r * VOC;
    float* osm = out + (size_t)TT * BB * VOC + (size_t)r * VOC;

    float m = -3.0e38f, s = 0.f;
    for (int i = threadIdx.x; i < VOC; i += 256) {
        float v = x[i];
        if (v > m) { s = s * __expf(m - v) + 1.f; m = v; }
        else       { s += __expf(v - m); }
    }
    #pragma unroll
    for (int o = 16; o; o >>= 1) {
        float m2 = __shfl_down_sync(0xffffffffu, m, o);
        float s2 = __shfl_down_sync(0xffffffffu, s, o);
        float mx = fmaxf(m, m2);
        s = s * __expf(m - mx) + s2 * __expf(m2 - mx);
        m = mx;
    }
    __shared__ float sm[8], ss[8];
    __shared__ float bM, bS;
    const int wid = threadIdx.x >> 5, lane = threadIdx.x & 31;
    if (!lane) { sm[wid] = m; ss[wid] = s; }
    __syncthreads();
    if (threadIdx.x == 0) {
        float M = sm[0], S = ss[0];
        #pragma unroll
        for (int i = 1; i < 8; i++) {
            float mx = fmaxf(M, sm[i]);
            S = S * __expf(M - mx) + ss[i] * __expf(sm[i] - mx);
            M = mx;
        }
        bM = M; bS = S;
    }
    __syncthreads();
    const float M = bM;
    const float Sinv = 1.f / bS;
    const float lg = __logf(bS);
    for (int i = threadIdx.x; i < VOC; i += 256) {
        float v = x[i] - M;
        ols[i] = v - lg;
        osm[i] = __expf(v) * Sinv;
    }
}

// ---------------- launch ----------------
extern "C" void kernel_launch(void* const* d_in, const int* in_sizes, int n_in,
                              void* d_out, int out_size) {
    (void)in_sizes; (void)n_in; (void)out_size;
    const float* features = (const float*)d_in[0];
    const int*   captions = (const int*)  d_in[1];
    const float* W_init_h = (const float*)d_in[2];
    const float* W_init_c = (const float*)d_in[3];
    const float* W_av     = (const float*)d_in[4];
    // d_in[5] b_av, d_in[6] W_ah, d_in[7] b_ah : dead (softmax shift-invariance)
    const float* embed    = (const float*)d_in[8];
    const float* W_ih     = (const float*)d_in[9];
    const float* W_hh     = (const float*)d_in[10];
    const float* b_ih     = (const float*)d_in[11];
    const float* b_hh     = (const float*)d_in[12];
    const float* W_out    = (const float*)d_in[13];
    const float* b_out    = (const float*)d_in[14];
    float* out = (float*)d_out;

    float *fmean, *ctx, *gctx, *gpre, *h, *c, *hall, *words, *gpart;
    int* rowmap;
    cudaGetSymbolAddress((void**)&fmean,  g_fmean);
    cudaGetSymbolAddress((void**)&ctx,    g_ctx);
    cudaGetSymbolAddress((void**)&gctx,   g_gctx);
    cudaGetSymbolAddress((void**)&gpre,   g_gpre);
    cudaGetSymbolAddress((void**)&h,      g_h);
    cudaGetSymbolAddress((void**)&c,      g_c);
    cudaGetSymbolAddress((void**)&hall,   g_hall);
    cudaGetSymbolAddress((void**)&words,  g_words);
    cudaGetSymbolAddress((void**)&gpart,  g_gpart);
    cudaGetSymbolAddress((void**)&rowmap, g_rowmap);

    // 1) attention context + feature mean
    attn_kernel<<<BB, 256>>>(features, W_av);
    rowmap_kernel<<<(TT * BB + 255) / 256, 256>>>(captions);

    // 2) h0 = fmean @ W_init_h^T ; c0 = fmean @ W_init_c^T
    gemm_tn<<<dim3(1, HDIM / 128, 1), 256>>>(fmean, VDIM, nullptr, W_init_h, VDIM,
        h, HDIM, 0, BB, HDIM, VDIM, 1, nullptr, nullptr, nullptr, 0, 0);
    gemm_tn<<<dim3(1, HDIM / 128, 1), 256>>>(fmean, VDIM, nullptr, W_init_c, VDIM,
        c, HDIM, 0, BB, HDIM, VDIM, 1, nullptr, nullptr, nullptr, 0, 0);

    // 3) gctx = ctx @ W_ih[:, :512]^T + b_ih + b_hh
    gemm_tn<<<dim3(1, G4 / 128, 1), 256>>>(ctx, VDIM, nullptr, W_ih, VDIM + HDIM,
        gctx, G4, 0, BB, G4, VDIM, 1, b_ih, b_hh, nullptr, 0, 0);

    // 4) gpre[t*64+b] = embed[tok] @ W_ih[:, 512:]^T + gctx[b]
    gemm_tn<<<dim3(TT * BB / 64, G4 / 128, 1), 256>>>(embed, 512, rowmap,
        W_ih + 512, VDIM + HDIM, gpre, G4, 0, TT * BB, G4, 512, 1,
        nullptr, nullptr, gctx, G4, 63);

    // 5) recurrence: 20 x (k-split GEMM h@W_hh^T + fused cell)
    for (int t = 0; t < TT; t++) {
        gemm_tn<<<dim3(1, G4 / 128, KSPL), 256>>>(h, HDIM, nullptr, W_hh, HDIM,
            gpart, G4, (long long)BB * G4, BB, G4, HDIM, KSPL,
            nullptr, nullptr, gpre + (size_t)t * BB * G4, G4, 0x7fffffff);
        cell_kernel<<<(BB * HDIM) / 256, 256>>>(t);
    }

    // 6) words = hall @ W_out^T + b_out   [1280 x 10000 x 512]
    gemm_tn<<<dim3(TT * BB / 64, (VOC + 127) / 128, 1), 256>>>(hall, HDIM, nullptr,
        W_out, HDIM, words, VOC, 0, TT * BB, VOC, HDIM, 1,
        b_out, nullptr, nullptr, 0, 0);

    // 7) fused log_softmax + softmax
    softmax_kernel<<<TT * BB, 256>>>(out);
}

// round 4
// speedup vs baseline: 1.0142x; 1.0142x over previous
#include <cuda_runtime.h>
#include <cuda_bf16.h>
#include <cstdint>
#include <cstddef>

#define TT   20
#define BB   64
#define NNF  196
#define VDIM 512
#define HDIM 512
#define VOC  10000
#define G4   2048   // 4*HDIM
#define KSPL 16

// ---------------- static device scratch (no runtime allocation) ----------------
__device__ float g_fmean[BB * VDIM];
__device__ float g_ctx  [BB * VDIM];
__device__ float g_gctx [BB * G4];
__device__ float g_gpre [TT * BB * G4];          // 10.5 MB
__device__ float g_h    [BB * HDIM];
__device__ float g_c    [BB * HDIM];
__device__ float g_hall [TT * BB * HDIM];
__device__ float g_words[TT * BB * VOC];         // 51.2 MB
__device__ float g_gpart[KSPL * BB * G4];        // 8 MB k-split partials
__device__ int   g_rowmap[TT * BB];

// bf16 hi/lo split buffers for mma GEMMs (K=512 everywhere)
__device__ __nv_bfloat16 g_Wout_hi[VOC * 512], g_Wout_lo[VOC * 512];
__device__ __nv_bfloat16 g_Wih_hi [G4  * 512], g_Wih_lo [G4  * 512];
__device__ __nv_bfloat16 g_emb_hi [TT * BB * 512], g_emb_lo [TT * BB * 512];
__device__ __nv_bfloat16 g_hall_hi[TT * BB * 512], g_hall_lo[TT * BB * 512];

// ============ mma.sync split-bf16 GEMM: C[m,n] = sum_k A[m,k]*B[n,k] ==========
// BM=128, BN=64, BK=32; 8 warps (4x2); warp tile 32x32 = 2x4 m16n8k16 tiles.
// 3 passes per mma site: Ahi*Bhi + Alo*Bhi + Ahi*Blo  (rel err ~2^-16).
#define ASTR 40   // padded bf16 row stride (80B) -> conflict-free 32-bit LDS

__device__ __forceinline__ void mma_bf16(float* d, const uint32_t* a, const uint32_t* b) {
    asm volatile(
        "mma.sync.aligned.m16n8k16.row.col.f32.bf16.bf16.f32 "
        "{%0,%1,%2,%3}, {%4,%5,%6,%7}, {%8,%9}, {%0,%1,%2,%3};"
        : "+f"(d[0]), "+f"(d[1]), "+f"(d[2]), "+f"(d[3])
        : "r"(a[0]), "r"(a[1]), "r"(a[2]), "r"(a[3]), "r"(b[0]), "r"(b[1]));
}

__global__ void __launch_bounds__(256) gemm_mma(
    const __nv_bfloat16* __restrict__ Ahi, const __nv_bfloat16* __restrict__ Alo,
    const __nv_bfloat16* __restrict__ Bhi, const __nv_bfloat16* __restrict__ Blo,
    float* __restrict__ C, int N, int ldc,
    const float* __restrict__ bias,
    const float* __restrict__ addC, int ldadd, int addmask)
{
    __shared__ __align__(16) __nv_bfloat16 sAh[128 * ASTR];
    __shared__ __align__(16) __nv_bfloat16 sAl[128 * ASTR];
    __shared__ __align__(16) __nv_bfloat16 sBh[64 * ASTR];
    __shared__ __align__(16) __nv_bfloat16 sBl[64 * ASTR];

    const int tid  = threadIdx.x;
    const int lane = tid & 31;
    const int w    = tid >> 5;
    const int wm   = w >> 1;          // 0..3
    const int wn   = w & 1;           // 0..1
    const int m0   = blockIdx.x * 128;
    const int n0   = blockIdx.y * 64;
    const int mbase = wm * 32;
    const int nbase = wn * 32;
    const int g = lane >> 2;          // 0..7
    const int q = lane & 3;           // 0..3

    float acc[2][4][4];
    #pragma unroll
    for (int mt = 0; mt < 2; mt++)
        #pragma unroll
        for (int nt = 0; nt < 4; nt++)
            #pragma unroll
            for (int r = 0; r < 4; r++) acc[mt][nt][r] = 0.f;

    for (int k0 = 0; k0 < 512; k0 += 32) {
        // stage A: 128 rows x 32 bf16 -> 512 x 16B per buffer (2 per thread)
        #pragma unroll
        for (int i = tid; i < 512; i += 256) {
            const int r = i >> 2, kq = (i & 3) * 8;
            const size_t go = (size_t)(m0 + r) * 512 + k0 + kq;
            *(uint4*)&sAh[r * ASTR + kq] = *(const uint4*)(Ahi + go);
            *(uint4*)&sAl[r * ASTR + kq] = *(const uint4*)(Alo + go);
        }
        // stage B: 64 rows x 32 bf16 -> 256 x 16B per buffer (1 per thread)
        {
            const int i = tid;
            const int r = i >> 2, kq = (i & 3) * 8;
            uint4 vh = make_uint4(0u, 0u, 0u, 0u);
            uint4 vl = make_uint4(0u, 0u, 0u, 0u);
            if (n0 + r < N) {
                const size_t go = (size_t)(n0 + r) * 512 + k0 + kq;
                vh = *(const uint4*)(Bhi + go);
                vl = *(const uint4*)(Blo + go);
            }
            *(uint4*)&sBh[r * ASTR + kq] = vh;
            *(uint4*)&sBl[r * ASTR + kq] = vl;
        }
        __syncthreads();

        #pragma unroll
        for (int kk = 0; kk < 32; kk += 16) {
            uint32_t ah[2][4], al[2][4];
            #pragma unroll
            for (int mt = 0; mt < 2; mt++) {
                const int r0 = mbase + mt * 16 + g;
                const int c0 = kk + q * 2;
                ah[mt][0] = *(const uint32_t*)&sAh[r0 * ASTR + c0];
                ah[mt][1] = *(const uint32_t*)&sAh[(r0 + 8) * ASTR + c0];
                ah[mt][2] = *(const uint32_t*)&sAh[r0 * ASTR + c0 + 8];
                ah[mt][3] = *(const uint32_t*)&sAh[(r0 + 8) * ASTR + c0 + 8];
                al[mt][0] = *(const uint32_t*)&sAl[r0 * ASTR + c0];
                al[mt][1] = *(const uint32_t*)&sAl[(r0 + 8) * ASTR + c0];
                al[mt][2] = *(const uint32_t*)&sAl[r0 * ASTR + c0 + 8];
                al[mt][3] = *(const uint32_t*)&sAl[(r0 + 8) * ASTR + c0 + 8];
            }
            uint32_t bh[4][2], bl[4][2];
            #pragma unroll
            for (int nt = 0; nt < 4; nt++) {
                const int n = nbase + nt * 8 + g;
                const int c0 = kk + q * 2;
                bh[nt][0] = *(const uint32_t*)&sBh[n * ASTR + c0];
                bh[nt][1] = *(const uint32_t*)&sBh[n * ASTR + c0 + 8];
                bl[nt][0] = *(const uint32_t*)&sBl[n * ASTR + c0];
                bl[nt][1] = *(const uint32_t*)&sBl[n * ASTR + c0 + 8];
            }
            #pragma unroll
            for (int mt = 0; mt < 2; mt++)
                #pragma unroll
                for (int nt = 0; nt < 4; nt++) {
                    mma_bf16(acc[mt][nt], ah[mt], bh[nt]);
                    mma_bf16(acc[mt][nt], al[mt], bh[nt]);
                    mma_bf16(acc[mt][nt], ah[mt], bl[nt]);
                }
        }
        __syncthreads();
    }

    // epilogue: float2 stores (rows m, m+8; cols n..n+1)
    #pragma unroll
    for (int mt = 0; mt < 2; mt++) {
        #pragma unroll
        for (int nt = 0; nt < 4; nt++) {
            const int n = n0 + nbase + nt * 8 + q * 2;
            if (n < N) {
                #pragma unroll
                for (int half = 0; half < 2; half++) {
                    const int m = m0 + mbase + mt * 16 + g + half * 8;
                    float v0 = acc[mt][nt][half * 2 + 0];
                    float v1 = acc[mt][nt][half * 2 + 1];
                    if (bias) { v0 += bias[n]; v1 += bias[n + 1]; }
                    if (addC) {
                        const float* ar = addC + (size_t)(m & addmask) * ldadd + n;
                        v0 += ar[0]; v1 += ar[1];
                    }
                    *(float2*)(C + (size_t)m * ldc + n) = make_float2(v0, v1);
                }
            }
        }
    }
}

// ---------------- fp32 -> bf16 hi/lo split (K fixed at 512) ----------------
__global__ void __launch_bounds__(256) cvt_split(
    const float* __restrict__ src, int ld, int koff, const int* __restrict__ gather,
    __nv_bfloat16* __restrict__ hi, __nv_bfloat16* __restrict__ lo, int total)
{
    const int i = blockIdx.x * 256 + threadIdx.x;
    if (i < total) {
        const int m = i >> 9, k = i & 511;
        const int row = gather ? gather[m] : m;
        const float x = src[(size_t)row * ld + koff + k];
        const __nv_bfloat16 h = __float2bfloat16(x);
        hi[i] = h;
        lo[i] = __float2bfloat16(x - __bfloat162float(h));
    }
}

// ---------------- attention + feature mean (step-invariant) ----------------
__global__ void __launch_bounds__(256) attn_kernel(const float* __restrict__ features,
                                                   const float* __restrict__ W_av) {
    const int b = blockIdx.x;
    __shared__ float sW[VDIM];
    __shared__ float sA[NNF];
    __shared__ float sred[8];
    __shared__ float s_max, s_inv;
    const int tid  = threadIdx.x;
    const int wid  = tid >> 5, lane = tid & 31;

    for (int i = tid; i < VDIM; i += 256) sW[i] = W_av[i];
    __syncthreads();

    const float* fb = features + (size_t)b * NNF * VDIM;

    for (int n = wid; n < NNF; n += 8) {
        const float* fr = fb + (size_t)n * VDIM;
        float s = 0.f;
        for (int k = lane; k < VDIM; k += 32) s = fmaf(fr[k], sW[k], s);
        #pragma unroll
        for (int o = 16; o; o >>= 1) s += __shfl_down_sync(0xffffffffu, s, o);
        if (!lane) sA[n] = s;
    }
    __syncthreads();

    float m = -3.0e38f;
    for (int n = tid; n < NNF; n += 256) m = fmaxf(m, sA[n]);
    #pragma unroll
    for (int o = 16; o; o >>= 1) m = fmaxf(m, __shfl_down_sync(0xffffffffu, m, o));
    if (!lane) sred[wid] = m;
    __syncthreads();
    if (tid == 0) {
        float mm = sred[0];
        #pragma unroll
        for (int i = 1; i < 8; i++) mm = fmaxf(mm, sred[i]);
        s_max = mm;
    }
    __syncthreads();
    const float mm = s_max;

    float s = 0.f;
    for (int n = tid; n < NNF; n += 256) { float e = __expf(sA[n] - mm); sA[n] = e; s += e; }
    #pragma unroll
    for (int o = 16; o; o >>= 1) s += __shfl_down_sync(0xffffffffu, s, o);
    if (!lane) sred[wid] = s;
    __syncthreads();
    if (tid == 0) {
        float ss = 0.f;
        #pragma unroll
        for (int i = 0; i < 8; i++) ss += sred[i];
        s_inv = 1.f / ss;
    }
    __syncthreads();
    const float inv = s_inv;

    for (int v = tid; v < VDIM; v += 256) {
        float ac = 0.f, am = 0.f;
        #pragma unroll 4
        for (int n = 0; n < NNF; n++) {
            float f = fb[(size_t)n * VDIM + v];
            ac = fmaf(sA[n], f, ac);
            am += f;
        }
        g_ctx  [b * VDIM + v] = ac * inv;
        g_fmean[b * VDIM + v] = am * (1.f / (float)NNF);
    }
}

// ---------------- rowmap: r = t*64+b -> token id ----------------
__global__ void rowmap_kernel(const int* __restrict__ captions) {
    int r = blockIdx.x * 256 + threadIdx.x;
    if (r < TT * BB) {
        int b = r & 63, t = r >> 6;
        g_rowmap[r] = captions[b * TT + t];
    }
}

// ---------------- SIMT fp32 GEMM (small/sequential pieces) ----------------
__global__ void __launch_bounds__(256) gemm_tn(
    const float* __restrict__ A, int lda, const int* __restrict__ gather,
    const float* __restrict__ B, int ldb,
    float* __restrict__ C, int ldc, long long cz_stride,
    int M, int N, int kTotal, int ksplit,
    const float* __restrict__ bias0, const float* __restrict__ bias1,
    const float* __restrict__ addC, int ldadd, int addmask)
{
    __shared__ __align__(16) float As[16][64];
    __shared__ __align__(16) float Bs[16][128];
    const int tid = threadIdx.x;
    const int m0  = blockIdx.x * 64;
    const int n0  = blockIdx.y * 128;
    const int z   = blockIdx.z;
    const int kchunk = kTotal / ksplit;
    const int k0beg  = z * kchunk;
    const int k0end  = k0beg + kchunk;

    float* Cz = C + (long long)z * cz_stride;

    const int tn = (tid & 15) * 8;
    const int tm = (tid >> 4) * 4;

    float acc[4][8];
    #pragma unroll
    for (int i = 0; i < 4; i++)
        #pragma unroll
        for (int j = 0; j < 8; j++) acc[i][j] = 0.f;

    const int arow = tid >> 2;
    const int akv  = (tid & 3) * 4;
    int grow = m0 + arow;
    if (gather) grow = gather[grow];
    const float* Arow = A + (size_t)grow * lda;

    const int brow = tid >> 1;
    const int bkv  = (tid & 1) * 8;
    const bool bok = (n0 + brow) < N;
    const float* Brow = B + (size_t)(n0 + brow) * ldb;

    for (int k0 = k0beg; k0 < k0end; k0 += 16) {
        float4 av = *(const float4*)(Arow + k0 + akv);
        float4 b0 = make_float4(0.f, 0.f, 0.f, 0.f);
        float4 b1 = make_float4(0.f, 0.f, 0.f, 0.f);
        if (bok) {
            b0 = *(const float4*)(Brow + k0 + bkv);
            b1 = *(const float4*)(Brow + k0 + bkv + 4);
        }
        __syncthreads();
        As[akv + 0][arow] = av.x;
        As[akv + 1][arow] = av.y;
        As[akv + 2][arow] = av.z;
        As[akv + 3][arow] = av.w;
        Bs[bkv + 0][brow] = b0.x;
        Bs[bkv + 1][brow] = b0.y;
        Bs[bkv + 2][brow] = b0.z;
        Bs[bkv + 3][brow] = b0.w;
        Bs[bkv + 4][brow] = b1.x;
        Bs[bkv + 5][brow] = b1.y;
        Bs[bkv + 6][brow] = b1.z;
        Bs[bkv + 7][brow] = b1.w;
        __syncthreads();

        #pragma unroll
        for (int kk = 0; kk < 16; kk++) {
            float4 a01 = *(const float4*)&As[kk][tm];
            float4 bv0 = *(const float4*)&Bs[kk][tn];
            float4 bv1 = *(const float4*)&Bs[kk][tn + 4];
            float a[4] = {a01.x, a01.y, a01.z, a01.w};
            float bb[8] = {bv0.x, bv0.y, bv0.z, bv0.w, bv1.x, bv1.y, bv1.z, bv1.w};
            #pragma unroll
            for (int i = 0; i < 4; i++)
                #pragma unroll
                for (int j = 0; j < 8; j++)
                    acc[i][j] = fmaf(a[i], bb[j], acc[i][j]);
        }
    }

    const bool doadd = (z == 0);
    #pragma unroll
    for (int i = 0; i < 4; i++) {
        const int m = m0 + tm + i;
        #pragma unroll
        for (int j = 0; j < 8; j++) {
            const int n = n0 + tn + j;
            if (n < N) {
                float v = acc[i][j];
                if (doadd) {
                    if (bias0) v += bias0[n];
                    if (bias1) v += bias1[n];
                    if (addC)  v += addC[(size_t)(m & addmask) * ldadd + n];
                }
                Cz[(size_t)m * ldc + n] = v;
            }
        }
    }
}

// ---------------- z-partial reduce ----------------
__global__ void __launch_bounds__(256) reduce_kernel(float* __restrict__ dst,
                                                     const float* __restrict__ src,
                                                     int n, int zc, int zstride) {
    int i = blockIdx.x * 256 + threadIdx.x;
    if (i < n) {
        float s = 0.f;
        for (int j = 0; j < zc; j++) s += src[(size_t)j * zstride + i];
        dst[i] = s;
    }
}

// ---------------- reduce k-split partials + LSTM cell update ----------------
__global__ void __launch_bounds__(256) cell_kernel(int t) {
    const int id = blockIdx.x * 256 + threadIdx.x;   // 0..32767
    const int b = id >> 9, u = id & 511;
    float gi = 0.f, gf = 0.f, gg = 0.f, go = 0.f;
    #pragma unroll
    for (int z = 0; z < KSPL; z++) {
        const float* p = g_gpart + (size_t)z * BB * G4 + (size_t)b * G4;
        gi += p[u];
        gf += p[u + 512];
        gg += p[u + 1024];
        go += p[u + 1536];
    }
    const float c  = g_c[id];
    const float si = 1.f / (1.f + __expf(-gi));
    const float sf = 1.f / (1.f + __expf(-gf));
    const float so = 1.f / (1.f + __expf(-go));
    const float tg = tanhf(gg);
    const float cn = sf * c + si * tg;
    const float h  = so * tanhf(cn);
    g_c[id] = cn;
    g_h[id] = h;
    g_hall[(size_t)t * BB * HDIM + id] = h;
}

// ---------------- fused log_softmax + softmax over V=10000 ----------------
__global__ void __launch_bounds__(256) softmax_kernel(float* __restrict__ out) {
    const int r = blockIdx.x;
    const float* x  = g_words + (size_t)r * VOC;
    float* ols = out + (size_t)r * VOC;
    float* osm = out + (size_t)TT * BB * VOC + (size_t)r * VOC;

    float m = -3.0e38f, s = 0.f;
    for (int i = threadIdx.x; i < VOC; i += 256) {
        float v = x[i];
        if (v > m) { s = s * __expf(m - v) + 1.f; m = v; }
        else       { s += __expf(v - m); }
    }
    #pragma unroll
    for (int o = 16; o; o >>= 1) {
        float m2 = __shfl_down_sync(0xffffffffu, m, o);
        float s2 = __shfl_down_sync(0xffffffffu, s, o);
        float mx = fmaxf(m, m2);
        s = s * __expf(m - mx) + s2 * __expf(m2 - mx);
        m = mx;
    }
    __shared__ float sm[8], ss[8];
    __shared__ float bM, bS;
    const int wid = threadIdx.x >> 5, lane = threadIdx.x & 31;
    if (!lane) { sm[wid] = m; ss[wid] = s; }
    __syncthreads();
    if (threadIdx.x == 0) {
        float M = sm[0], S = ss[0];
        #pragma unroll
        for (int i = 1; i < 8; i++) {
            float mx = fmaxf(M, sm[i]);
            S = S * __expf(M - mx) + ss[i] * __expf(sm[i] - mx);
            M = mx;
        }
        bM = M; bS = S;
    }
    __syncthreads();
    const float M = bM;
    const float Sinv = 1.f / bS;
    const float lg = __logf(bS);
    for (int i = threadIdx.x; i < VOC; i += 256) {
        float v = x[i] - M;
        ols[i] = v - lg;
        osm[i] = __expf(v) * Sinv;
    }
}

// ---------------- launch ----------------
extern "C" void kernel_launch(void* const* d_in, const int* in_sizes, int n_in,
                              void* d_out, int out_size) {
    (void)in_sizes; (void)n_in; (void)out_size;
    const float* features = (const float*)d_in[0];
    const int*   captions = (const int*)  d_in[1];
    const float* W_init_h = (const float*)d_in[2];
    const float* W_init_c = (const float*)d_in[3];
    const float* W_av     = (const float*)d_in[4];
    // d_in[5] b_av, d_in[6] W_ah, d_in[7] b_ah : dead (softmax shift-invariance)
    const float* embed    = (const float*)d_in[8];
    const float* W_ih     = (const float*)d_in[9];
    const float* W_hh     = (const float*)d_in[10];
    const float* b_ih     = (const float*)d_in[11];
    const float* b_hh     = (const float*)d_in[12];
    const float* W_out    = (const float*)d_in[13];
    const float* b_out    = (const float*)d_in[14];
    float* out = (float*)d_out;

    float *fmean, *ctx, *gctx, *gpre, *h, *c, *hall, *words, *gpart;
    int* rowmap;
    __nv_bfloat16 *wout_hi, *wout_lo, *wih_hi, *wih_lo, *emb_hi, *emb_lo, *hall_hi, *hall_lo;
    cudaGetSymbolAddress((void**)&fmean,   g_fmean);
    cudaGetSymbolAddress((void**)&ctx,     g_ctx);
    cudaGetSymbolAddress((void**)&gctx,    g_gctx);
    cudaGetSymbolAddress((void**)&gpre,    g_gpre);
    cudaGetSymbolAddress((void**)&h,       g_h);
    cudaGetSymbolAddress((void**)&c,       g_c);
    cudaGetSymbolAddress((void**)&hall,    g_hall);
    cudaGetSymbolAddress((void**)&words,   g_words);
    cudaGetSymbolAddress((void**)&gpart,   g_gpart);
    cudaGetSymbolAddress((void**)&rowmap,  g_rowmap);
    cudaGetSymbolAddress((void**)&wout_hi, g_Wout_hi);
    cudaGetSymbolAddress((void**)&wout_lo, g_Wout_lo);
    cudaGetSymbolAddress((void**)&wih_hi,  g_Wih_hi);
    cudaGetSymbolAddress((void**)&wih_lo,  g_Wih_lo);
    cudaGetSymbolAddress((void**)&emb_hi,  g_emb_hi);
    cudaGetSymbolAddress((void**)&emb_lo,  g_emb_lo);
    cudaGetSymbolAddress((void**)&hall_hi, g_hall_hi);
    cudaGetSymbolAddress((void**)&hall_lo, g_hall_lo);

    // 1) attention context + feature mean; rowmap
    attn_kernel<<<BB, 256>>>(features, W_av);
    rowmap_kernel<<<(TT * BB + 255) / 256, 256>>>(captions);

    // 2) bf16 hi/lo conversions (weights + gathered embeddings)
    cvt_split<<<(VOC * 512 + 255) / 256, 256>>>(W_out, 512, 0, nullptr, wout_hi, wout_lo, VOC * 512);
    cvt_split<<<(G4 * 512 + 255) / 256, 256>>>(W_ih, VDIM + 512, 512, nullptr, wih_hi, wih_lo, G4 * 512);
    cvt_split<<<(TT * BB * 512 + 255) / 256, 256>>>(embed, 512, 0, rowmap, emb_hi, emb_lo, TT * BB * 512);

    // 3) h0/c0 via k-split SIMT GEMM + reduce
    gemm_tn<<<dim3(1, 4, 8), 256>>>(fmean, VDIM, nullptr, W_init_h, VDIM,
        gpart, HDIM, (long long)BB * HDIM, BB, HDIM, VDIM, 8,
        nullptr, nullptr, nullptr, 0, 0);
    reduce_kernel<<<(BB * HDIM + 255) / 256, 256>>>(h, gpart, BB * HDIM, 8, BB * HDIM);
    gemm_tn<<<dim3(1, 4, 8), 256>>>(fmean, VDIM, nullptr, W_init_c, VDIM,
        gpart, HDIM, (long long)BB * HDIM, BB, HDIM, VDIM, 8,
        nullptr, nullptr, nullptr, 0, 0);
    reduce_kernel<<<(BB * HDIM + 255) / 256, 256>>>(c, gpart, BB * HDIM, 8, BB * HDIM);

    // 4) gctx = ctx @ W_ih[:, :512]^T + b_ih + b_hh
    gemm_tn<<<dim3(1, G4 / 128, 1), 256>>>(ctx, VDIM, nullptr, W_ih, VDIM + HDIM,
        gctx, G4, 0, BB, G4, VDIM, 1, b_ih, b_hh, nullptr, 0, 0);

    // 5) gpre = gathered_embed @ W_ih_right^T + gctx  (mma.sync bf16 split)
    gemm_mma<<<dim3(TT * BB / 128, G4 / 64), 256>>>(
        emb_hi, emb_lo, wih_hi, wih_lo, gpre, G4, G4, nullptr, gctx, G4, 63);

    // 6) recurrence: 20 x (k-split GEMM h@W_hh^T + fused cell)
    for (int t = 0; t < TT; t++) {
        gemm_tn<<<dim3(1, G4 / 128, KSPL), 256>>>(h, HDIM, nullptr, W_hh, HDIM,
            gpart, G4, (long long)BB * G4, BB, G4, HDIM, KSPL,
            nullptr, nullptr, gpre + (size_t)t * BB * G4, G4, 0x7fffffff);
        cell_kernel<<<(BB * HDIM) / 256, 256>>>(t);
    }

    // 7) words = hall @ W_out^T + b_out (mma.sync bf16 split)
    cvt_split<<<(TT * BB * 512 + 255) / 256, 256>>>(hall, 512, 0, nullptr, hall_hi, hall_lo, TT * BB * 512);
    gemm_mma<<<dim3(TT * BB / 128, (VOC + 63) / 64), 256>>>(
        hall_hi, hall_lo, wout_hi, wout_lo, words, VOC, VOC, b_out, nullptr, 0, 0);

    // 8) fused log_softmax + softmax
    softmax_kernel<<<TT * BB, 256>>>(out);
}

// round 5
// speedup vs baseline: 1.7535x; 1.7290x over previous
#include <cuda_runtime.h>
#include <cuda_bf16.h>
#include <cstdint>
#include <cstddef>

#define TT   20
#define BB   64
#define NNF  196
#define VOC  10000
#define G4   2048
#define NBLK 128          // persistent LSTM grid (<= SM count, 1 block/SM)

// ---------------- static device scratch ----------------
__device__ float g_fmean[BB * 512];
__device__ float g_ctx  [BB * 512];
__device__ float g_attw [BB * NNF];
__device__ float g_gpre [TT * BB * G4];
__device__ float g_words[TT * BB * VOC];
__device__ float g_hbuf [2][BB * 512];
__device__ int   g_rowmap[TT * BB];
__device__ unsigned long long g_bar;   // monotonic across replays

__device__ __nv_bfloat16 g_Wout_hi[VOC * 512],  g_Wout_lo[VOC * 512];
__device__ __nv_bfloat16 g_Wih_hi [G4 * 1024],  g_Wih_lo [G4 * 1024];
__device__ __nv_bfloat16 g_A_hi   [TT * BB * 1024], g_A_lo[TT * BB * 1024];
__device__ __nv_bfloat16 g_hall_hi[TT * BB * 512],  g_hall_lo[TT * BB * 512];

// ============ mma.sync split-bf16 GEMM: C[m,n] = sum_k A[m,k]*B[n,k] ==========
#define ASTR 40

__device__ __forceinline__ void mma_bf16(float* d, const uint32_t* a, const uint32_t* b) {
    asm volatile(
        "mma.sync.aligned.m16n8k16.row.col.f32.bf16.bf16.f32 "
        "{%0,%1,%2,%3}, {%4,%5,%6,%7}, {%8,%9}, {%0,%1,%2,%3};"
        : "+f"(d[0]), "+f"(d[1]), "+f"(d[2]), "+f"(d[3])
        : "r"(a[0]), "r"(a[1]), "r"(a[2]), "r"(a[3]), "r"(b[0]), "r"(b[1]));
}

__global__ void __launch_bounds__(256) gemm_mma(
    const __nv_bfloat16* __restrict__ Ahi, const __nv_bfloat16* __restrict__ Alo,
    const __nv_bfloat16* __restrict__ Bhi, const __nv_bfloat16* __restrict__ Blo,
    float* __restrict__ C, int N, int ldc, int K,
    const float* __restrict__ bias0, const float* __restrict__ bias1)
{
    __shared__ __align__(16) __nv_bfloat16 sAh[128 * ASTR];
    __shared__ __align__(16) __nv_bfloat16 sAl[128 * ASTR];
    __shared__ __align__(16) __nv_bfloat16 sBh[64 * ASTR];
    __shared__ __align__(16) __nv_bfloat16 sBl[64 * ASTR];

    const int tid  = threadIdx.x;
    const int lane = tid & 31;
    const int w    = tid >> 5;
    const int wm   = w >> 1;
    const int wn   = w & 1;
    const int m0   = blockIdx.x * 128;
    const int n0   = blockIdx.y * 64;
    const int mbase = wm * 32;
    const int nbase = wn * 32;
    const int g = lane >> 2;
    const int q = lane & 3;

    float acc[2][4][4];
    #pragma unroll
    for (int mt = 0; mt < 2; mt++)
        #pragma unroll
        for (int nt = 0; nt < 4; nt++)
            #pragma unroll
            for (int r = 0; r < 4; r++) acc[mt][nt][r] = 0.f;

    for (int k0 = 0; k0 < K; k0 += 32) {
        #pragma unroll
        for (int i = tid; i < 512; i += 256) {
            const int r = i >> 2, kq = (i & 3) * 8;
            const size_t go = (size_t)(m0 + r) * K + k0 + kq;
            *(uint4*)&sAh[r * ASTR + kq] = *(const uint4*)(Ahi + go);
            *(uint4*)&sAl[r * ASTR + kq] = *(const uint4*)(Alo + go);
        }
        {
            const int i = tid;
            const int r = i >> 2, kq = (i & 3) * 8;
            uint4 vh = make_uint4(0u, 0u, 0u, 0u);
            uint4 vl = make_uint4(0u, 0u, 0u, 0u);
            if (n0 + r < N) {
                const size_t go = (size_t)(n0 + r) * K + k0 + kq;
                vh = *(const uint4*)(Bhi + go);
                vl = *(const uint4*)(Blo + go);
            }
            *(uint4*)&sBh[r * ASTR + kq] = vh;
            *(uint4*)&sBl[r * ASTR + kq] = vl;
        }
        __syncthreads();

        #pragma unroll
        for (int kk = 0; kk < 32; kk += 16) {
            uint32_t ah[2][4], al[2][4];
            #pragma unroll
            for (int mt = 0; mt < 2; mt++) {
                const int r0 = mbase + mt * 16 + g;
                const int c0 = kk + q * 2;
                ah[mt][0] = *(const uint32_t*)&sAh[r0 * ASTR + c0];
                ah[mt][1] = *(const uint32_t*)&sAh[(r0 + 8) * ASTR + c0];
                ah[mt][2] = *(const uint32_t*)&sAh[r0 * ASTR + c0 + 8];
                ah[mt][3] = *(const uint32_t*)&sAh[(r0 + 8) * ASTR + c0 + 8];
                al[mt][0] = *(const uint32_t*)&sAl[r0 * ASTR + c0];
                al[mt][1] = *(const uint32_t*)&sAl[(r0 + 8) * ASTR + c0];
                al[mt][2] = *(const uint32_t*)&sAl[r0 * ASTR + c0 + 8];
                al[mt][3] = *(const uint32_t*)&sAl[(r0 + 8) * ASTR + c0 + 8];
            }
            uint32_t bh[4][2], bl[4][2];
            #pragma unroll
            for (int nt = 0; nt < 4; nt++) {
                const int n = nbase + nt * 8 + g;
                const int c0 = kk + q * 2;
                bh[nt][0] = *(const uint32_t*)&sBh[n * ASTR + c0];
                bh[nt][1] = *(const uint32_t*)&sBh[n * ASTR + c0 + 8];
                bl[nt][0] = *(const uint32_t*)&sBl[n * ASTR + c0];
                bl[nt][1] = *(const uint32_t*)&sBl[n * ASTR + c0 + 8];
            }
            #pragma unroll
            for (int mt = 0; mt < 2; mt++)
                #pragma unroll
                for (int nt = 0; nt < 4; nt++) {
                    mma_bf16(acc[mt][nt], ah[mt], bh[nt]);
                    mma_bf16(acc[mt][nt], al[mt], bh[nt]);
                    mma_bf16(acc[mt][nt], ah[mt], bl[nt]);
                }
        }
        __syncthreads();
    }

    #pragma unroll
    for (int mt = 0; mt < 2; mt++) {
        #pragma unroll
        for (int nt = 0; nt < 4; nt++) {
            const int n = n0 + nbase + nt * 8 + q * 2;
            if (n < N) {
                #pragma unroll
                for (int half = 0; half < 2; half++) {
                    const int m = m0 + mbase + mt * 16 + g + half * 8;
                    float v0 = acc[mt][nt][half * 2 + 0];
                    float v1 = acc[mt][nt][half * 2 + 1];
                    if (bias0) { v0 += bias0[n]; v1 += bias0[n + 1]; }
                    if (bias1) { v0 += bias1[n]; v1 += bias1[n + 1]; }
                    *(float2*)(C + (size_t)m * ldc + n) = make_float2(v0, v1);
                }
            }
        }
    }
}

// ---------------- fp32 -> bf16 hi/lo (generic pow2 K) ----------------
__global__ void __launch_bounds__(256) cvt_k(
    const float* __restrict__ src, int ld, int kshift,
    __nv_bfloat16* __restrict__ hi, __nv_bfloat16* __restrict__ lo, int total)
{
    const int i = blockIdx.x * 256 + threadIdx.x;
    if (i < total) {
        const int m = i >> kshift, k = i & ((1 << kshift) - 1);
        const float x = src[(size_t)m * ld + k];
        const __nv_bfloat16 h = __float2bfloat16(x);
        hi[i] = h;
        lo[i] = __float2bfloat16(x - __bfloat162float(h));
    }
}

// ---------------- build concat A = [ctx(b) | embed(tok)] as bf16 hi/lo ----------------
__global__ void __launch_bounds__(256) cvt_concat(const float* __restrict__ embed) {
    const int i = blockIdx.x * 256 + threadIdx.x;
    if (i < TT * BB * 1024) {
        const int r = i >> 10, k = i & 1023;
        const int b = r & 63;
        float x;
        if (k < 512) x = g_ctx[b * 512 + k];
        else         x = embed[(size_t)g_rowmap[r] * 512 + (k - 512)];
        const __nv_bfloat16 h = __float2bfloat16(x);
        g_A_hi[i] = h;
        g_A_lo[i] = __float2bfloat16(x - __bfloat162float(h));
    }
}

// ---------------- attention logits + softmax weights ----------------
__global__ void __launch_bounds__(256) attn_logits(const float* __restrict__ features,
                                                   const float* __restrict__ W_av) {
    const int b = blockIdx.x;
    __shared__ float sW[512];
    __shared__ float sA[NNF];
    __shared__ float sred[8];
    __shared__ float s_max, s_inv;
    const int tid = threadIdx.x;
    const int wid = tid >> 5, lane = tid & 31;

    for (int i = tid; i < 512; i += 256) sW[i] = W_av[i];
    __syncthreads();

    const float* fb = features + (size_t)b * NNF * 512;

    for (int n = wid; n < NNF; n += 8) {
        const float* fr = fb + (size_t)n * 512;
        float s0 = 0.f, s1 = 0.f, s2 = 0.f, s3 = 0.f;
        #pragma unroll
        for (int i = 0; i < 4; i++) {
            const int o = lane + i * 128;
            s0 = fmaf(fr[o],      sW[o],      s0);
            s1 = fmaf(fr[o + 32], sW[o + 32], s1);
            s2 = fmaf(fr[o + 64], sW[o + 64], s2);
            s3 = fmaf(fr[o + 96], sW[o + 96], s3);
        }
        float s = (s0 + s1) + (s2 + s3);
        #pragma unroll
        for (int o = 16; o; o >>= 1) s += __shfl_down_sync(0xffffffffu, s, o);
        if (!lane) sA[n] = s;
    }
    __syncthreads();

    float m = -3.0e38f;
    for (int n = tid; n < NNF; n += 256) m = fmaxf(m, sA[n]);
    #pragma unroll
    for (int o = 16; o; o >>= 1) m = fmaxf(m, __shfl_down_sync(0xffffffffu, m, o));
    if (!lane) sred[wid] = m;
    __syncthreads();
    if (tid == 0) {
        float mm = sred[0];
        #pragma unroll
        for (int i = 1; i < 8; i++) mm = fmaxf(mm, sred[i]);
        s_max = mm;
    }
    __syncthreads();
    const float mm = s_max;

    float s = 0.f;
    for (int n = tid; n < NNF; n += 256) { float e = __expf(sA[n] - mm); sA[n] = e; s += e; }
    #pragma unroll
    for (int o = 16; o; o >>= 1) s += __shfl_down_sync(0xffffffffu, s, o);
    if (!lane) sred[wid] = s;
    __syncthreads();
    if (tid == 0) {
        float ss = 0.f;
        #pragma unroll
        for (int i = 0; i < 8; i++) ss += sred[i];
        s_inv = 1.f / ss;
    }
    __syncthreads();
    const float inv = s_inv;
    for (int n = tid; n < NNF; n += 256) g_attw[b * NNF + n] = sA[n] * inv;
}

// ---------------- ctx + fmean (wide, ILP) ----------------
__global__ void __launch_bounds__(128) attn_ctx(const float* __restrict__ features) {
    const int b = blockIdx.x;
    const int v = blockIdx.y * 128 + threadIdx.x;
    __shared__ float sw[NNF];
    for (int i = threadIdx.x; i < NNF; i += 128) sw[i] = g_attw[b * NNF + i];
    __syncthreads();

    const float* fp = features + (size_t)b * NNF * 512 + v;
    float ac0 = 0.f, ac1 = 0.f, ac2 = 0.f, ac3 = 0.f;
    float am0 = 0.f, am1 = 0.f, am2 = 0.f, am3 = 0.f;
    #pragma unroll 4
    for (int n = 0; n < NNF; n += 4) {
        float f0 = fp[(size_t)(n + 0) * 512];
        float f1 = fp[(size_t)(n + 1) * 512];
        float f2 = fp[(size_t)(n + 2) * 512];
        float f3 = fp[(size_t)(n + 3) * 512];
        ac0 = fmaf(sw[n + 0], f0, ac0); am0 += f0;
        ac1 = fmaf(sw[n + 1], f1, ac1); am1 += f1;
        ac2 = fmaf(sw[n + 2], f2, ac2); am2 += f2;
        ac3 = fmaf(sw[n + 3], f3, ac3); am3 += f3;
    }
    g_ctx  [b * 512 + v] = (ac0 + ac1) + (ac2 + ac3);
    g_fmean[b * 512 + v] = ((am0 + am1) + (am2 + am3)) * (1.f / (float)NNF);
}

// ---------------- rowmap ----------------
__global__ void rowmap_kernel(const int* __restrict__ captions) {
    int r = blockIdx.x * 256 + threadIdx.x;
    if (r < TT * BB) {
        int b = r & 63, t = r >> 6;
        g_rowmap[r] = captions[b * TT + t];
    }
}

// ================= persistent LSTM (phase0 init + 20 steps, 1 launch) =========
__device__ __forceinline__ void gbar() {
    __syncthreads();
    if (threadIdx.x == 0) {
        unsigned long long old = atomicAdd(&g_bar, 1ULL);
        unsigned long long tgt = old - (old & (unsigned long long)(NBLK - 1)) + (unsigned long long)NBLK;
        unsigned long long cur;
        do {
            asm volatile("ld.global.acquire.gpu.u64 %0, [%1];" : "=l"(cur) : "l"(&g_bar));
            if (cur < tgt) __nanosleep(64);
        } while (cur < tgt);
    }
    __syncthreads();
}

// dots: warp w owns gate-rows w and w+8; lane ks owns k-set {128j + 4ks .. +3}
#define DOTS()                                                                 \
    for (int b = 0; b < BB; b++) {                                             \
        float a0 = 0.f, a1 = 0.f;                                              \
        _Pragma("unroll")                                                      \
        for (int j = 0; j < 4; j++) {                                          \
            float4 hv = *(const float4*)&hs[b * 512 + j * 128 + ks * 4];       \
            a0 = fmaf(W0[j*4+0], hv.x, a0); a0 = fmaf(W0[j*4+1], hv.y, a0);    \
            a0 = fmaf(W0[j*4+2], hv.z, a0); a0 = fmaf(W0[j*4+3], hv.w, a0);    \
            a1 = fmaf(W1[j*4+0], hv.x, a1); a1 = fmaf(W1[j*4+1], hv.y, a1);    \
            a1 = fmaf(W1[j*4+2], hv.z, a1); a1 = fmaf(W1[j*4+3], hv.w, a1);    \
        }                                                                      \
        _Pragma("unroll")                                                      \
        for (int o = 16; o; o >>= 1) {                                         \
            a0 += __shfl_xor_sync(0xffffffffu, a0, o);                         \
            a1 += __shfl_xor_sync(0xffffffffu, a1, o);                         \
        }                                                                      \
        if (ks == 0) { gates[w * 64 + b] += a0; gates[(w + 8) * 64 + b] += a1; } \
    }

__global__ void __launch_bounds__(256, 1) lstm_kernel(
    const float* __restrict__ Winit_h, const float* __restrict__ Winit_c,
    const float* __restrict__ Whh)
{
    extern __shared__ float smem[];
    float* hs    = smem;              // [64][512]
    float* gates = smem + BB * 512;   // [16][64]

    const int tid = threadIdx.x;
    const int w   = tid >> 5;
    const int ks  = tid & 31;
    const int bc  = tid & 63;
    const int uu  = tid >> 6;
    const int u0  = blockIdx.x * 4;

    float W0[16], W1[16];

    // ---- phase 0: h0/c0 from fmean ----
    {
        const float* s0 = (w < 4) ? (Winit_h + (size_t)(u0 + w) * 512)
                                  : (Winit_c + (size_t)(u0 + w - 4) * 512);
        #pragma unroll
        for (int j = 0; j < 4; j++) {
            float4 v = *(const float4*)(s0 + j * 128 + ks * 4);
            W0[j*4+0] = v.x; W0[j*4+1] = v.y; W0[j*4+2] = v.z; W0[j*4+3] = v.w;
            W1[j*4+0] = 0.f; W1[j*4+1] = 0.f; W1[j*4+2] = 0.f; W1[j*4+3] = 0.f;
        }
    }
    {
        const float4* src = (const float4*)g_fmean;
        float4* dst = (float4*)hs;
        for (int i = tid; i < BB * 128; i += 256) dst[i] = src[i];
    }
    for (int i = tid; i < 1024; i += 256) gates[i] = 0.f;
    __syncthreads();

    DOTS();
    __syncthreads();

    float c  = gates[(4 + uu) * 64 + bc];
    {
        float h0 = gates[uu * 64 + bc];
        g_hbuf[0][bc * 512 + u0 + uu] = h0;
    }
    __threadfence();
    gbar();

    // ---- steady-state weights: rows (w>>2)*512+u0+(w&3) and +2*512 ----
    {
        const float* r0p = Whh + (size_t)((w >> 2) * 512 + u0 + (w & 3)) * 512;
        const float* r1p = Whh + (size_t)(((w >> 2) + 2) * 512 + u0 + (w & 3)) * 512;
        #pragma unroll
        for (int j = 0; j < 4; j++) {
            float4 v0 = *(const float4*)(r0p + j * 128 + ks * 4);
            float4 v1 = *(const float4*)(r1p + j * 128 + ks * 4);
            W0[j*4+0] = v0.x; W0[j*4+1] = v0.y; W0[j*4+2] = v0.z; W0[j*4+3] = v0.w;
            W1[j*4+0] = v1.x; W1[j*4+1] = v1.y; W1[j*4+2] = v1.z; W1[j*4+3] = v1.w;
        }
    }

    for (int t = 0; t < TT; t++) {
        // reload hs from ping-pong buffer
        {
            const float4* src = (const float4*)g_hbuf[t & 1];
            float4* dst = (float4*)hs;
            for (int i = tid; i < BB * 128; i += 256) dst[i] = src[i];
        }
        // preload gpre (+biases already folded) into gates
        {
            const float* gp = g_gpre + (size_t)t * BB * G4 + (size_t)bc * G4 + u0 + uu;
            #pragma unroll
            for (int i = 0; i < 4; i++) gates[(i * 4 + uu) * 64 + bc] = gp[i * 512];
        }
        __syncthreads();

        DOTS();
        __syncthreads();

        const float gi = gates[(0 + uu) * 64 + bc];
        const float gf = gates[(4 + uu) * 64 + bc];
        const float gg = gates[(8 + uu) * 64 + bc];
        const float go = gates[(12 + uu) * 64 + bc];
        const float si = 1.f / (1.f + __expf(-gi));
        const float sf = 1.f / (1.f + __expf(-gf));
        const float so = 1.f / (1.f + __expf(-go));
        c = sf * c + si * tanhf(gg);
        const float hnew = so * tanhf(c);

        g_hbuf[(t + 1) & 1][bc * 512 + u0 + uu] = hnew;
        const __nv_bfloat16 hb = __float2bfloat16(hnew);
        g_hall_hi[(size_t)(t * 64 + bc) * 512 + u0 + uu] = hb;
        g_hall_lo[(size_t)(t * 64 + bc) * 512 + u0 + uu] =
            __float2bfloat16(hnew - __bfloat162float(hb));

        __threadfence();
        if (t < TT - 1) gbar();
        else __syncthreads();
    }
}

// ---------------- fused log_softmax + softmax over V=10000 ----------------
__global__ void __launch_bounds__(256) softmax_kernel(float* __restrict__ out) {
    const int r = blockIdx.x;
    const float* x  = g_words + (size_t)r * VOC;
    float* ols = out + (size_t)r * VOC;
    float* osm = out + (size_t)TT * BB * VOC + (size_t)r * VOC;

    float m = -3.0e38f, s = 0.f;
    for (int i = threadIdx.x; i < VOC; i += 256) {
        float v = x[i];
        if (v > m) { s = s * __expf(m - v) + 1.f; m = v; }
        else       { s += __expf(v - m); }
    }
    #pragma unroll
    for (int o = 16; o; o >>= 1) {
        float m2 = __shfl_down_sync(0xffffffffu, m, o);
        float s2 = __shfl_down_sync(0xffffffffu, s, o);
        float mx = fmaxf(m, m2);
        s = s * __expf(m - mx) + s2 * __expf(m2 - mx);
        m = mx;
    }
    __shared__ float sm[8], ss[8];
    __shared__ float bM, bS;
    const int wid = threadIdx.x >> 5, lane = threadIdx.x & 31;
    if (!lane) { sm[wid] = m; ss[wid] = s; }
    __syncthreads();
    if (threadIdx.x == 0) {
        float M = sm[0], S = ss[0];
        #pragma unroll
        for (int i = 1; i < 8; i++) {
            float mx = fmaxf(M, sm[i]);
            S = S * __expf(M - mx) + ss[i] * __expf(sm[i] - mx);
            M = mx;
        }
        bM = M; bS = S;
    }
    __syncthreads();
    const float M = bM;
    const float Sinv = 1.f / bS;
    const float lg = __logf(bS);
    for (int i = threadIdx.x; i < VOC; i += 256) {
        float v = x[i] - M;
        ols[i] = v - lg;
        osm[i] = __expf(v) * Sinv;
    }
}

// ---------------- launch ----------------
extern "C" void kernel_launch(void* const* d_in, const int* in_sizes, int n_in,
                              void* d_out, int out_size) {
    (void)in_sizes; (void)n_in; (void)out_size;
    const float* features = (const float*)d_in[0];
    const int*   captions = (const int*)  d_in[1];
    const float* W_init_h = (const float*)d_in[2];
    const float* W_init_c = (const float*)d_in[3];
    const float* W_av     = (const float*)d_in[4];
    // d_in[5] b_av, d_in[6] W_ah, d_in[7] b_ah : dead (softmax shift-invariance)
    const float* embed    = (const float*)d_in[8];
    const float* W_ih     = (const float*)d_in[9];
    const float* W_hh     = (const float*)d_in[10];
    const float* b_ih     = (const float*)d_in[11];
    const float* b_hh     = (const float*)d_in[12];
    const float* W_out    = (const float*)d_in[13];
    const float* b_out    = (const float*)d_in[14];
    float* out = (float*)d_out;

    float *gpre, *words;
    __nv_bfloat16 *wout_hi, *wout_lo, *wih_hi, *wih_lo, *a_hi, *a_lo, *hall_hi, *hall_lo;
    cudaGetSymbolAddress((void**)&gpre,    g_gpre);
    cudaGetSymbolAddress((void**)&words,   g_words);
    cudaGetSymbolAddress((void**)&wout_hi, g_Wout_hi);
    cudaGetSymbolAddress((void**)&wout_lo, g_Wout_lo);
    cudaGetSymbolAddress((void**)&wih_hi,  g_Wih_hi);
    cudaGetSymbolAddress((void**)&wih_lo,  g_Wih_lo);
    cudaGetSymbolAddress((void**)&a_hi,    g_A_hi);
    cudaGetSymbolAddress((void**)&a_lo,    g_A_lo);
    cudaGetSymbolAddress((void**)&hall_hi, g_hall_hi);
    cudaGetSymbolAddress((void**)&hall_lo, g_hall_lo);

    const int LSTM_SMEM = (BB * 512 + 16 * 64) * 4;   // 135168 B
    cudaFuncSetAttribute(lstm_kernel, cudaFuncAttributeMaxDynamicSharedMemorySize, LSTM_SMEM);

    // 1) attention weights, then ctx + fmean (wide)
    attn_logits<<<BB, 256>>>(features, W_av);
    attn_ctx<<<dim3(BB, 4), 128>>>(features);
    rowmap_kernel<<<(TT * BB + 255) / 256, 256>>>(captions);

    // 2) weight conversions
    cvt_k<<<(VOC * 512 + 255) / 256, 256>>>(W_out, 512, 9, wout_hi, wout_lo, VOC * 512);
    cvt_k<<<(G4 * 1024 + 255) / 256, 256>>>(W_ih, 1024, 10, wih_hi, wih_lo, G4 * 1024);
    cvt_concat<<<(TT * BB * 1024 + 255) / 256, 256>>>(embed);

    // 3) gpre = [ctx|emb] @ W_ih^T + b_ih + b_hh   (K=1024, tensor cores)
    gemm_mma<<<dim3(TT * BB / 128, G4 / 64), 256>>>(
        a_hi, a_lo, wih_hi, wih_lo, gpre, G4, G4, 1024, b_ih, b_hh);

    // 4) persistent LSTM: h0/c0 + 20 steps, writes hall hi/lo directly
    lstm_kernel<<<NBLK, 256, LSTM_SMEM>>>(W_init_h, W_init_c, W_hh);

    // 5) words = hall @ W_out^T + b_out (K=512, tensor cores)
    gemm_mma<<<dim3(TT * BB / 128, (VOC + 63) / 64), 256>>>(
        hall_hi, hall_lo, wout_hi, wout_lo, words, VOC, VOC, 512, b_out, nullptr);

    // 6) fused log_softmax + softmax
    softmax_kernel<<<TT * BB, 256>>>(out);
}

// round 6
// speedup vs baseline: 1.9142x; 1.0916x over previous
#include <cuda_runtime.h>
#include <cuda_bf16.h>
#include <cstdint>
#include <cstddef>

#define TT   20
#define BB   64
#define NNF  196
#define VOC  10000
#define G4   2048
#define NBLK 128          // persistent LSTM grid (<= SM count, 1 block/SM)

// ---------------- static device scratch ----------------
__device__ float g_fmean[BB * 512];
__device__ float g_ctx  [BB * 512];
__device__ float g_attw [BB * NNF];
__device__ float g_gpre [TT * BB * G4];
__device__ float g_words[TT * BB * VOC];
__device__ float g_hbuf [2][BB * 512];
__device__ int   g_rowmap[TT * BB];
__device__ unsigned long long g_bar;   // monotonic across replays

__device__ __nv_bfloat16 g_Wout_hi[VOC * 512],  g_Wout_lo[VOC * 512];
__device__ __nv_bfloat16 g_Wih_hi [G4 * 1024],  g_Wih_lo [G4 * 1024];
__device__ __nv_bfloat16 g_A_hi   [TT * BB * 1024], g_A_lo[TT * BB * 1024];
__device__ __nv_bfloat16 g_hall_hi[TT * BB * 512],  g_hall_lo[TT * BB * 512];

// ---------------- helpers ----------------
__device__ __forceinline__ uint32_t smem_u32(const void* p) {
    uint32_t a;
    asm("{ .reg .u64 t; cvta.to.shared.u64 t, %1; cvt.u32.u64 %0, t; }"
        : "=r"(a) : "l"(p));
    return a;
}
__device__ __forceinline__ void ldm_x4(uint32_t* r, uint32_t addr) {
    asm volatile("ldmatrix.sync.aligned.m8n8.x4.shared.b16 {%0,%1,%2,%3}, [%4];"
                 : "=r"(r[0]), "=r"(r[1]), "=r"(r[2]), "=r"(r[3]) : "r"(addr));
}
__device__ __forceinline__ void mma_bf16(float* d, const uint32_t* a, const uint32_t* b) {
    asm volatile(
        "mma.sync.aligned.m16n8k16.row.col.f32.bf16.bf16.f32 "
        "{%0,%1,%2,%3}, {%4,%5,%6,%7}, {%8,%9}, {%0,%1,%2,%3};"
        : "+f"(d[0]), "+f"(d[1]), "+f"(d[2]), "+f"(d[3])
        : "r"(a[0]), "r"(a[1]), "r"(a[2]), "r"(a[3]), "r"(b[0]), "r"(b[1]));
}

// ============ mma.sync split-bf16 GEMM: C[m,n] = sum_k A[m,k]*B[n,k] ==========
// BM=128, BN=64, BK=32; 8 warps (4x2); warp tile 32x32.
// ldmatrix fragment loads + register prefetch double-buffering.
#define ASTR 40   // padded bf16 row stride (80B): conflict-free for ldmatrix

__global__ void __launch_bounds__(256) gemm_mma(
    const __nv_bfloat16* __restrict__ Ahi, const __nv_bfloat16* __restrict__ Alo,
    const __nv_bfloat16* __restrict__ Bhi, const __nv_bfloat16* __restrict__ Blo,
    float* __restrict__ C, int N, int ldc, int K,
    const float* __restrict__ bias0, const float* __restrict__ bias1)
{
    __shared__ __align__(16) __nv_bfloat16 sAh[128 * ASTR];
    __shared__ __align__(16) __nv_bfloat16 sAl[128 * ASTR];
    __shared__ __align__(16) __nv_bfloat16 sBh[64 * ASTR];
    __shared__ __align__(16) __nv_bfloat16 sBl[64 * ASTR];

    const int tid  = threadIdx.x;
    const int lane = tid & 31;
    const int w    = tid >> 5;
    const int wm   = w >> 1;
    const int wn   = w & 1;
    const int m0   = blockIdx.x * 128;
    const int n0   = blockIdx.y * 64;
    const int mbase = wm * 32;
    const int nbase = wn * 32;
    const int g = lane >> 2;
    const int q = lane & 3;

    // staging coords
    const int ar0 = tid >> 2;           // A rows: ar0 and ar0+64
    const int akq = (tid & 3) * 8;
    const int br  = tid >> 2;           // B row (64 rows, 1 uint4/thread/buf)
    const bool bok = (n0 + br) < N;

    // ldmatrix per-lane base offsets (bytes)
    const uint32_t baseAh = smem_u32(sAh), baseAl = smem_u32(sAl);
    const uint32_t baseBh = smem_u32(sBh), baseBl = smem_u32(sBl);
    const int l7 = lane & 7;
    // A: lanes 0-7 rows r0..r0+7 kLo | 8-15 rows+8 kLo | 16-23 rows kHi | 24-31 rows+8 kHi
    const uint32_t aRow = mbase + l7 + ((lane >> 3) & 1) * 8;
    const uint32_t aKof = (lane >> 4) * 16;      // bytes
    // B: lanes 0-7 rows nb..+7 kLo | 8-15 same rows kHi | 16-23 rows+8 kLo | 24-31 rows+8 kHi
    const uint32_t bRow = nbase + l7 + (lane >> 4) * 8;
    const uint32_t bKof = ((lane >> 3) & 1) * 16; // bytes

    float acc[2][4][4];
    #pragma unroll
    for (int mt = 0; mt < 2; mt++)
        #pragma unroll
        for (int nt = 0; nt < 4; nt++)
            #pragma unroll
            for (int r = 0; r < 4; r++) acc[mt][nt][r] = 0.f;

    // prefetch registers
    uint4 pAh0, pAh1, pAl0, pAl1, pBh, pBl;
    {
        const size_t g0 = (size_t)(m0 + ar0) * K + akq;
        const size_t g1 = (size_t)(m0 + ar0 + 64) * K + akq;
        pAh0 = *(const uint4*)(Ahi + g0); pAh1 = *(const uint4*)(Ahi + g1);
        pAl0 = *(const uint4*)(Alo + g0); pAl1 = *(const uint4*)(Alo + g1);
        pBh = make_uint4(0u,0u,0u,0u); pBl = pBh;
        if (bok) {
            const size_t gb = (size_t)(n0 + br) * K + akq;
            pBh = *(const uint4*)(Bhi + gb);
            pBl = *(const uint4*)(Blo + gb);
        }
    }

    for (int k0 = 0; k0 < K; k0 += 32) {
        __syncthreads();   // previous compute done, smem reusable
        *(uint4*)&sAh[ar0 * ASTR + akq]        = pAh0;
        *(uint4*)&sAh[(ar0 + 64) * ASTR + akq] = pAh1;
        *(uint4*)&sAl[ar0 * ASTR + akq]        = pAl0;
        *(uint4*)&sAl[(ar0 + 64) * ASTR + akq] = pAl1;
        *(uint4*)&sBh[br * ASTR + akq] = pBh;
        *(uint4*)&sBl[br * ASTR + akq] = pBl;
        __syncthreads();

        if (k0 + 32 < K) {
            const int kn = k0 + 32;
            const size_t g0 = (size_t)(m0 + ar0) * K + kn + akq;
            const size_t g1 = (size_t)(m0 + ar0 + 64) * K + kn + akq;
            pAh0 = *(const uint4*)(Ahi + g0); pAh1 = *(const uint4*)(Ahi + g1);
            pAl0 = *(const uint4*)(Alo + g0); pAl1 = *(const uint4*)(Alo + g1);
            if (bok) {
                const size_t gb = (size_t)(n0 + br) * K + kn + akq;
                pBh = *(const uint4*)(Bhi + gb);
                pBl = *(const uint4*)(Blo + gb);
            }
        }

        #pragma unroll
        for (int kk = 0; kk < 32; kk += 16) {
            const uint32_t kb = kk * 2;
            uint32_t ah[2][4], al[2][4], bh[4][2], bl[4][2];
            #pragma unroll
            for (int mt = 0; mt < 2; mt++) {
                const uint32_t ro = (aRow + mt * 16) * (ASTR * 2) + kb + aKof;
                ldm_x4(ah[mt], baseAh + ro);
                ldm_x4(al[mt], baseAl + ro);
            }
            #pragma unroll
            for (int np = 0; np < 2; np++) {
                const uint32_t ro = (bRow + np * 16) * (ASTR * 2) + kb + bKof;
                uint32_t tb[4], tl[4];
                ldm_x4(tb, baseBh + ro);
                ldm_x4(tl, baseBl + ro);
                bh[np*2][0] = tb[0]; bh[np*2][1] = tb[1];
                bh[np*2+1][0] = tb[2]; bh[np*2+1][1] = tb[3];
                bl[np*2][0] = tl[0]; bl[np*2][1] = tl[1];
                bl[np*2+1][0] = tl[2]; bl[np*2+1][1] = tl[3];
            }
            #pragma unroll
            for (int mt = 0; mt < 2; mt++)
                #pragma unroll
                for (int nt = 0; nt < 4; nt++) {
                    mma_bf16(acc[mt][nt], ah[mt], bh[nt]);
                    mma_bf16(acc[mt][nt], al[mt], bh[nt]);
                    mma_bf16(acc[mt][nt], ah[mt], bl[nt]);
                }
        }
    }

    #pragma unroll
    for (int mt = 0; mt < 2; mt++) {
        #pragma unroll
        for (int nt = 0; nt < 4; nt++) {
            const int n = n0 + nbase + nt * 8 + q * 2;
            if (n < N) {
                #pragma unroll
                for (int half = 0; half < 2; half++) {
                    const int m = m0 + mbase + mt * 16 + g + half * 8;
                    float v0 = acc[mt][nt][half * 2 + 0];
                    float v1 = acc[mt][nt][half * 2 + 1];
                    if (bias0) { v0 += bias0[n]; v1 += bias0[n + 1]; }
                    if (bias1) { v0 += bias1[n]; v1 += bias1[n + 1]; }
                    *(float2*)(C + (size_t)m * ldc + n) = make_float2(v0, v1);
                }
            }
        }
    }
}

// ---------------- fp32 -> bf16 hi/lo, 8 elems/thread (contiguous) ----------------
__global__ void __launch_bounds__(256) cvt_k8(
    const float* __restrict__ src,
    __nv_bfloat16* __restrict__ hi, __nv_bfloat16* __restrict__ lo, int total)
{
    const int i = (blockIdx.x * 256 + threadIdx.x) * 8;
    if (i < total) {
        float4 x0 = *(const float4*)(src + i);
        float4 x1 = *(const float4*)(src + i + 4);
        float xs[8] = {x0.x, x0.y, x0.z, x0.w, x1.x, x1.y, x1.z, x1.w};
        __nv_bfloat16 h8[8], l8[8];
        #pragma unroll
        for (int j = 0; j < 8; j++) {
            __nv_bfloat16 h = __float2bfloat16(xs[j]);
            h8[j] = h;
            l8[j] = __float2bfloat16(xs[j] - __bfloat162float(h));
        }
        *(uint4*)(hi + i) = *(const uint4*)h8;
        *(uint4*)(lo + i) = *(const uint4*)l8;
    }
}

// ---------------- concat A = [ctx(b) | embed(tok)] bf16 hi/lo, 8/thread ----------------
__global__ void __launch_bounds__(256) cvt_concat8(const float* __restrict__ embed) {
    const int i = (blockIdx.x * 256 + threadIdx.x) * 8;
    if (i < TT * BB * 1024) {
        const int r = i >> 10, k = i & 1023;
        const float* sp = (k < 512)
            ? (g_ctx + (r & 63) * 512 + k)
            : (embed + (size_t)g_rowmap[r] * 512 + (k - 512));
        float4 x0 = *(const float4*)sp;
        float4 x1 = *(const float4*)(sp + 4);
        float xs[8] = {x0.x, x0.y, x0.z, x0.w, x1.x, x1.y, x1.z, x1.w};
        __nv_bfloat16 h8[8], l8[8];
        #pragma unroll
        for (int j = 0; j < 8; j++) {
            __nv_bfloat16 h = __float2bfloat16(xs[j]);
            h8[j] = h;
            l8[j] = __float2bfloat16(xs[j] - __bfloat162float(h));
        }
        *(uint4*)(g_A_hi + i) = *(const uint4*)h8;
        *(uint4*)(g_A_lo + i) = *(const uint4*)l8;
    }
}

// ---------------- attention logits + softmax weights ----------------
__global__ void __launch_bounds__(256) attn_logits(const float* __restrict__ features,
                                                   const float* __restrict__ W_av) {
    const int b = blockIdx.x;
    __shared__ float sW[512];
    __shared__ float sA[NNF];
    __shared__ float sred[8];
    __shared__ float s_max, s_inv;
    const int tid = threadIdx.x;
    const int wid = tid >> 5, lane = tid & 31;

    for (int i = tid; i < 512; i += 256) sW[i] = W_av[i];
    __syncthreads();

    const float* fb = features + (size_t)b * NNF * 512;

    for (int n = wid; n < NNF; n += 8) {
        const float* fr = fb + (size_t)n * 512;
        float s0 = 0.f, s1 = 0.f, s2 = 0.f, s3 = 0.f;
        #pragma unroll
        for (int i = 0; i < 4; i++) {
            const int o = lane + i * 128;
            s0 = fmaf(fr[o],      sW[o],      s0);
            s1 = fmaf(fr[o + 32], sW[o + 32], s1);
            s2 = fmaf(fr[o + 64], sW[o + 64], s2);
            s3 = fmaf(fr[o + 96], sW[o + 96], s3);
        }
        float s = (s0 + s1) + (s2 + s3);
        #pragma unroll
        for (int o = 16; o; o >>= 1) s += __shfl_down_sync(0xffffffffu, s, o);
        if (!lane) sA[n] = s;
    }
    __syncthreads();

    float m = -3.0e38f;
    for (int n = tid; n < NNF; n += 256) m = fmaxf(m, sA[n]);
    #pragma unroll
    for (int o = 16; o; o >>= 1) m = fmaxf(m, __shfl_down_sync(0xffffffffu, m, o));
    if (!lane) sred[wid] = m;
    __syncthreads();
    if (tid == 0) {
        float mm = sred[0];
        #pragma unroll
        for (int i = 1; i < 8; i++) mm = fmaxf(mm, sred[i]);
        s_max = mm;
    }
    __syncthreads();
    const float mm = s_max;

    float s = 0.f;
    for (int n = tid; n < NNF; n += 256) { float e = __expf(sA[n] - mm); sA[n] = e; s += e; }
    #pragma unroll
    for (int o = 16; o; o >>= 1) s += __shfl_down_sync(0xffffffffu, s, o);
    if (!lane) sred[wid] = s;
    __syncthreads();
    if (tid == 0) {
        float ss = 0.f;
        #pragma unroll
        for (int i = 0; i < 8; i++) ss += sred[i];
        s_inv = 1.f / ss;
    }
    __syncthreads();
    const float inv = s_inv;
    for (int n = tid; n < NNF; n += 256) g_attw[b * NNF + n] = sA[n] * inv;
}

// ---------------- ctx + fmean (wide, ILP) ----------------
__global__ void __launch_bounds__(128) attn_ctx(const float* __restrict__ features) {
    const int b = blockIdx.x;
    const int v = blockIdx.y * 128 + threadIdx.x;
    __shared__ float sw[NNF];
    for (int i = threadIdx.x; i < NNF; i += 128) sw[i] = g_attw[b * NNF + i];
    __syncthreads();

    const float* fp = features + (size_t)b * NNF * 512 + v;
    float ac0 = 0.f, ac1 = 0.f, ac2 = 0.f, ac3 = 0.f;
    float am0 = 0.f, am1 = 0.f, am2 = 0.f, am3 = 0.f;
    #pragma unroll 4
    for (int n = 0; n < NNF; n += 4) {
        float f0 = fp[(size_t)(n + 0) * 512];
        float f1 = fp[(size_t)(n + 1) * 512];
        float f2 = fp[(size_t)(n + 2) * 512];
        float f3 = fp[(size_t)(n + 3) * 512];
        ac0 = fmaf(sw[n + 0], f0, ac0); am0 += f0;
        ac1 = fmaf(sw[n + 1], f1, ac1); am1 += f1;
        ac2 = fmaf(sw[n + 2], f2, ac2); am2 += f2;
        ac3 = fmaf(sw[n + 3], f3, ac3); am3 += f3;
    }
    g_ctx  [b * 512 + v] = (ac0 + ac1) + (ac2 + ac3);
    g_fmean[b * 512 + v] = ((am0 + am1) + (am2 + am3)) * (1.f / (float)NNF);
}

// ---------------- rowmap ----------------
__global__ void rowmap_kernel(const int* __restrict__ captions) {
    int r = blockIdx.x * 256 + threadIdx.x;
    if (r < TT * BB) {
        int b = r & 63, t = r >> 6;
        g_rowmap[r] = captions[b * TT + t];
    }
}

// ================= persistent LSTM (phase0 init + 20 steps, 1 launch) =========
__device__ __forceinline__ void gbar() {
    __syncthreads();
    if (threadIdx.x == 0) {
        unsigned long long old = atomicAdd(&g_bar, 1ULL);
        unsigned long long tgt = old - (old & (unsigned long long)(NBLK - 1)) + (unsigned long long)NBLK;
        unsigned long long cur;
        do {
            asm volatile("ld.global.acquire.gpu.u64 %0, [%1];" : "=l"(cur) : "l"(&g_bar));
        } while (cur < tgt);
    }
    __syncthreads();
}

#define DOTS()                                                                 \
    for (int b = 0; b < BB; b++) {                                             \
        float a0 = 0.f, a1 = 0.f;                                              \
        _Pragma("unroll")                                                      \
        for (int j = 0; j < 4; j++) {                                          \
            float4 hv = *(const float4*)&hs[b * 512 + j * 128 + ks * 4];       \
            a0 = fmaf(W0[j*4+0], hv.x, a0); a0 = fmaf(W0[j*4+1], hv.y, a0);    \
            a0 = fmaf(W0[j*4+2], hv.z, a0); a0 = fmaf(W0[j*4+3], hv.w, a0);    \
            a1 = fmaf(W1[j*4+0], hv.x, a1); a1 = fmaf(W1[j*4+1], hv.y, a1);    \
            a1 = fmaf(W1[j*4+2], hv.z, a1); a1 = fmaf(W1[j*4+3], hv.w, a1);    \
        }                                                                      \
        _Pragma("unroll")                                                      \
        for (int o = 16; o; o >>= 1) {                                         \
            a0 += __shfl_xor_sync(0xffffffffu, a0, o);                         \
            a1 += __shfl_xor_sync(0xffffffffu, a1, o);                         \
        }                                                                      \
        if (ks == 0) { gates[w * 64 + b] += a0; gates[(w + 8) * 64 + b] += a1; } \
    }

__global__ void __launch_bounds__(256, 1) lstm_kernel(
    const float* __restrict__ Winit_h, const float* __restrict__ Winit_c,
    const float* __restrict__ Whh)
{
    extern __shared__ float smem[];
    float* hs    = smem;              // [64][512]
    float* gates = smem + BB * 512;   // [16][64]

    const int tid = threadIdx.x;
    const int w   = tid >> 5;
    const int ks  = tid & 31;
    const int bc  = tid & 63;
    const int uu  = tid >> 6;
    const int u0  = blockIdx.x * 4;

    float W0[16], W1[16];

    // ---- phase 0: h0/c0 from fmean ----
    {
        const float* s0 = (w < 4) ? (Winit_h + (size_t)(u0 + w) * 512)
                                  : (Winit_c + (size_t)(u0 + w - 4) * 512);
        #pragma unroll
        for (int j = 0; j < 4; j++) {
            float4 v = *(const float4*)(s0 + j * 128 + ks * 4);
            W0[j*4+0] = v.x; W0[j*4+1] = v.y; W0[j*4+2] = v.z; W0[j*4+3] = v.w;
            W1[j*4+0] = 0.f; W1[j*4+1] = 0.f; W1[j*4+2] = 0.f; W1[j*4+3] = 0.f;
        }
    }
    {
        const float4* src = (const float4*)g_fmean;
        float4* dst = (float4*)hs;
        for (int i = tid; i < BB * 128; i += 256) dst[i] = src[i];
    }
    for (int i = tid; i < 1024; i += 256) gates[i] = 0.f;
    __syncthreads();

    DOTS();
    __syncthreads();

    float c  = gates[(4 + uu) * 64 + bc];
    {
        float h0 = gates[uu * 64 + bc];
        g_hbuf[0][bc * 512 + u0 + uu] = h0;
    }

    // prefetch gpre for t=0
    float gp[4];
    {
        const float* gpp = g_gpre + (size_t)bc * G4 + u0 + uu;
        #pragma unroll
        for (int i = 0; i < 4; i++) gp[i] = gpp[i * 512];
    }
    __threadfence();
    gbar();

    // ---- steady-state weights ----
    {
        const float* r0p = Whh + (size_t)((w >> 2) * 512 + u0 + (w & 3)) * 512;
        const float* r1p = Whh + (size_t)(((w >> 2) + 2) * 512 + u0 + (w & 3)) * 512;
        #pragma unroll
        for (int j = 0; j < 4; j++) {
            float4 v0 = *(const float4*)(r0p + j * 128 + ks * 4);
            float4 v1 = *(const float4*)(r1p + j * 128 + ks * 4);
            W0[j*4+0] = v0.x; W0[j*4+1] = v0.y; W0[j*4+2] = v0.z; W0[j*4+3] = v0.w;
            W1[j*4+0] = v1.x; W1[j*4+1] = v1.y; W1[j*4+2] = v1.z; W1[j*4+3] = v1.w;
        }
    }

    for (int t = 0; t < TT; t++) {
        {
            const float4* src = (const float4*)g_hbuf[t & 1];
            float4* dst = (float4*)hs;
            for (int i = tid; i < BB * 128; i += 256) dst[i] = src[i];
        }
        #pragma unroll
        for (int i = 0; i < 4; i++) gates[(i * 4 + uu) * 64 + bc] = gp[i];
        __syncthreads();

        DOTS();
        __syncthreads();

        const float gi = gates[(0 + uu) * 64 + bc];
        const float gf = gates[(4 + uu) * 64 + bc];
        const float gg = gates[(8 + uu) * 64 + bc];
        const float go = gates[(12 + uu) * 64 + bc];
        const float si = 1.f / (1.f + __expf(-gi));
        const float sf = 1.f / (1.f + __expf(-gf));
        const float so = 1.f / (1.f + __expf(-go));
        c = sf * c + si * tanhf(gg);
        const float hnew = so * tanhf(c);

        g_hbuf[(t + 1) & 1][bc * 512 + u0 + uu] = hnew;
        const __nv_bfloat16 hb = __float2bfloat16(hnew);
        g_hall_hi[(size_t)(t * 64 + bc) * 512 + u0 + uu] = hb;
        g_hall_lo[(size_t)(t * 64 + bc) * 512 + u0 + uu] =
            __float2bfloat16(hnew - __bfloat162float(hb));

        if (t < TT - 1) {
            // prefetch next step's gpre (independent of h)
            const float* gpp = g_gpre + (size_t)(t + 1) * BB * G4 + (size_t)bc * G4 + u0 + uu;
            #pragma unroll
            for (int i = 0; i < 4; i++) gp[i] = gpp[i * 512];
            __threadfence();
            gbar();
        } else {
            __syncthreads();
        }
    }
}

// ---------------- fused log_softmax + softmax over V=10000 (float4) ----------------
__global__ void __launch_bounds__(256) softmax_kernel(float* __restrict__ out) {
    const int r = blockIdx.x;
    const float4* x4 = (const float4*)(g_words + (size_t)r * VOC);
    float4* ols = (float4*)(out + (size_t)r * VOC);
    float4* osm = (float4*)(out + (size_t)TT * BB * VOC + (size_t)r * VOC);

    float m = -3.0e38f, s = 0.f;
    for (int i = threadIdx.x; i < VOC / 4; i += 256) {
        float4 v = x4[i];
        float m4 = fmaxf(fmaxf(v.x, v.y), fmaxf(v.z, v.w));
        float mn = fmaxf(m, m4);
        s = s * __expf(m - mn) + __expf(v.x - mn) + __expf(v.y - mn)
                               + __expf(v.z - mn) + __expf(v.w - mn);
        m = mn;
    }
    #pragma unroll
    for (int o = 16; o; o >>= 1) {
        float m2 = __shfl_down_sync(0xffffffffu, m, o);
        float s2 = __shfl_down_sync(0xffffffffu, s, o);
        float mx = fmaxf(m, m2);
        s = s * __expf(m - mx) + s2 * __expf(m2 - mx);
        m = mx;
    }
    __shared__ float sm[8], ss[8];
    __shared__ float bM, bS;
    const int wid = threadIdx.x >> 5, lane = threadIdx.x & 31;
    if (!lane) { sm[wid] = m; ss[wid] = s; }
    __syncthreads();
    if (threadIdx.x == 0) {
        float M = sm[0], S = ss[0];
        #pragma unroll
        for (int i = 1; i < 8; i++) {
            float mx = fmaxf(M, sm[i]);
            S = S * __expf(M - mx) + ss[i] * __expf(sm[i] - mx);
            M = mx;
        }
        bM = M; bS = S;
    }
    __syncthreads();
    const float M = bM;
    const float Sinv = 1.f / bS;
    const float lg = __logf(bS);
    for (int i = threadIdx.x; i < VOC / 4; i += 256) {
        float4 v = x4[i];
        float4 l4, p4;
        l4.x = v.x - M - lg; p4.x = __expf(v.x - M) * Sinv;
        l4.y = v.y - M - lg; p4.y = __expf(v.y - M) * Sinv;
        l4.z = v.z - M - lg; p4.z = __expf(v.z - M) * Sinv;
        l4.w = v.w - M - lg; p4.w = __expf(v.w - M) * Sinv;
        ols[i] = l4;
        osm[i] = p4;
    }
}

// ---------------- launch ----------------
extern "C" void kernel_launch(void* const* d_in, const int* in_sizes, int n_in,
                              void* d_out, int out_size) {
    (void)in_sizes; (void)n_in; (void)out_size;
    const float* features = (const float*)d_in[0];
    const int*   captions = (const int*)  d_in[1];
    const float* W_init_h = (const float*)d_in[2];
    const float* W_init_c = (const float*)d_in[3];
    const float* W_av     = (const float*)d_in[4];
    // d_in[5] b_av, d_in[6] W_ah, d_in[7] b_ah : dead (softmax shift-invariance)
    const float* embed    = (const float*)d_in[8];
    const float* W_ih     = (const float*)d_in[9];
    const float* W_hh     = (const float*)d_in[10];
    const float* b_ih     = (const float*)d_in[11];
    const float* b_hh     = (const float*)d_in[12];
    const float* W_out    = (const float*)d_in[13];
    const float* b_out    = (const float*)d_in[14];
    float* out = (float*)d_out;

    float *gpre, *words;
    __nv_bfloat16 *wout_hi, *wout_lo, *wih_hi, *wih_lo, *a_hi, *a_lo, *hall_hi, *hall_lo;
    cudaGetSymbolAddress((void**)&gpre,    g_gpre);
    cudaGetSymbolAddress((void**)&words,   g_words);
    cudaGetSymbolAddress((void**)&wout_hi, g_Wout_hi);
    cudaGetSymbolAddress((void**)&wout_lo, g_Wout_lo);
    cudaGetSymbolAddress((void**)&wih_hi,  g_Wih_hi);
    cudaGetSymbolAddress((void**)&wih_lo,  g_Wih_lo);
    cudaGetSymbolAddress((void**)&a_hi,    g_A_hi);
    cudaGetSymbolAddress((void**)&a_lo,    g_A_lo);
    cudaGetSymbolAddress((void**)&hall_hi, g_hall_hi);
    cudaGetSymbolAddress((void**)&hall_lo, g_hall_lo);

    const int LSTM_SMEM = (BB * 512 + 16 * 64) * 4;   // 135168 B
    cudaFuncSetAttribute(lstm_kernel, cudaFuncAttributeMaxDynamicSharedMemorySize, LSTM_SMEM);

    // 1) attention weights, then ctx + fmean (wide)
    attn_logits<<<BB, 256>>>(features, W_av);
    attn_ctx<<<dim3(BB, 4), 128>>>(features);
    rowmap_kernel<<<(TT * BB + 255) / 256, 256>>>(captions);

    // 2) weight conversions (vectorized; W_out and W_ih rows are fully contiguous)
    cvt_k8<<<(VOC * 512 / 8 + 255) / 256, 256>>>(W_out, wout_hi, wout_lo, VOC * 512);
    cvt_k8<<<(G4 * 1024 / 8 + 255) / 256, 256>>>(W_ih, wih_hi, wih_lo, G4 * 1024);
    cvt_concat8<<<(TT * BB * 1024 / 8 + 255) / 256, 256>>>(embed);

    // 3) gpre = [ctx|emb] @ W_ih^T + b_ih + b_hh   (K=1024, HMMA)
    gemm_mma<<<dim3(TT * BB / 128, G4 / 64), 256>>>(
        a_hi, a_lo, wih_hi, wih_lo, gpre, G4, G4, 1024, b_ih, b_hh);

    // 4) persistent LSTM: h0/c0 + 20 steps, writes hall hi/lo directly
    lstm_kernel<<<NBLK, 256, LSTM_SMEM>>>(W_init_h, W_init_c, W_hh);

    // 5) words = hall @ W_out^T + b_out (K=512, HMMA)
    gemm_mma<<<dim3(TT * BB / 128, (VOC + 63) / 64), 256>>>(
        hall_hi, hall_lo, wout_hi, wout_lo, words, VOC, VOC, 512, b_out, nullptr);

    // 6) fused log_softmax + softmax
    softmax_kernel<<<TT * BB, 256>>>(out);
}

// round 7
// speedup vs baseline: 1.9788x; 1.0337x over previous
#include <cuda_runtime.h>
#include <cuda_bf16.h>
#include <cstdint>
#include <cstddef>

#define TT   20
#define BB   64
#define NNF  196
#define VOC  10000
#define G4   2048
#define NBLK 128          // persistent LSTM grid (<= SM count, 1 block/SM)

// ---------------- static device scratch ----------------
__device__ float g_fmean[BB * 512];
__device__ float g_ctx  [BB * 512];
__device__ float g_attw [BB * NNF];
__device__ float g_gpre [TT * BB * G4];
__device__ float g_words[TT * BB * VOC];
__device__ float g_hbuf [2][BB * 512];
__device__ int   g_rowmap[TT * BB];
__device__ unsigned long long g_bar;   // monotonic across replays

__device__ __nv_bfloat16 g_Wout_hi[VOC * 512],  g_Wout_lo[VOC * 512];
__device__ __nv_bfloat16 g_Wih_hi [G4 * 1024],  g_Wih_lo [G4 * 1024];
__device__ __nv_bfloat16 g_A_hi   [TT * BB * 1024], g_A_lo[TT * BB * 1024];
__device__ __nv_bfloat16 g_hall_hi[TT * BB * 512],  g_hall_lo[TT * BB * 512];

// ---------------- helpers ----------------
__device__ __forceinline__ uint32_t smem_u32(const void* p) {
    uint32_t a;
    asm("{ .reg .u64 t; cvta.to.shared.u64 t, %1; cvt.u32.u64 %0, t; }"
        : "=r"(a) : "l"(p));
    return a;
}
__device__ __forceinline__ void ldm_x4(uint32_t* r, uint32_t addr) {
    asm volatile("ldmatrix.sync.aligned.m8n8.x4.shared.b16 {%0,%1,%2,%3}, [%4];"
                 : "=r"(r[0]), "=r"(r[1]), "=r"(r[2]), "=r"(r[3]) : "r"(addr));
}
__device__ __forceinline__ void mma_bf16(float* d, const uint32_t* a, const uint32_t* b) {
    asm volatile(
        "mma.sync.aligned.m16n8k16.row.col.f32.bf16.bf16.f32 "
        "{%0,%1,%2,%3}, {%4,%5,%6,%7}, {%8,%9}, {%0,%1,%2,%3};"
        : "+f"(d[0]), "+f"(d[1]), "+f"(d[2]), "+f"(d[3])
        : "r"(a[0]), "r"(a[1]), "r"(a[2]), "r"(a[3]), "r"(b[0]), "r"(b[1]));
}
__device__ __forceinline__ void cpa16(uint32_t dst, const void* src, int srcsz) {
    asm volatile("cp.async.cg.shared.global [%0], [%1], 16, %2;"
                 :: "r"(dst), "l"(src), "r"(srcsz));
}
__device__ __forceinline__ void cpa_commit() {
    asm volatile("cp.async.commit_group;");
}
template<int NG> __device__ __forceinline__ void cpa_wait() {
    asm volatile("cp.async.wait_group %0;" :: "n"(NG));
}

// ============ mma.sync split-bf16 GEMM: C[m,n] = sum_k A[m,k]*B[n,k] ==========
// BM=128, BN=128, BK=32; 8 warps (4x2); warp tile 32x64.
// cp.async 2-stage double buffer; ldmatrix fragments; 3 mma passes (hi/lo split).
#define ASTR 40                         // padded bf16 row stride (80B)
#define BUFB (128 * ASTR * 2)           // one operand buffer: 10240 bytes
#define STAGEB (4 * BUFB)               // Ah|Al|Bh|Bl per stage: 40960 bytes

__global__ void __launch_bounds__(256) gemm_mma(
    const __nv_bfloat16* __restrict__ Ahi, const __nv_bfloat16* __restrict__ Alo,
    const __nv_bfloat16* __restrict__ Bhi, const __nv_bfloat16* __restrict__ Blo,
    float* __restrict__ C, int N, int ldc, int K,
    const float* __restrict__ bias0, const float* __restrict__ bias1)
{
    extern __shared__ __align__(16) __nv_bfloat16 dsm[];
    const uint32_t smb = smem_u32(dsm);

    const int tid  = threadIdx.x;
    const int lane = tid & 31;
    const int w    = tid >> 5;
    const int wm   = w >> 1;                // 0..3
    const int wn   = w & 1;                 // 0..1
    const int m0   = blockIdx.x * 128;
    const int n0   = blockIdx.y * 128;
    const int mbase = wm * 32;
    const int nbase = wn * 64;
    const int g = lane >> 2;
    const int q = lane & 3;

    // staging: chunk i in [0,512): row r=i>>2, k-offset kq=(i&3)*8 (elements)
    const int i0 = tid, i1 = tid + 256;
    const int r0s = i0 >> 2, k0s = (i0 & 3) * 8;
    const int r1s = i1 >> 2, k1s = (i1 & 3) * 8;
    const int bsz0 = (n0 + r0s) < N ? 16 : 0;
    const int bsz1 = (n0 + r1s) < N ? 16 : 0;
    const uint32_t d0 = (uint32_t)(r0s * ASTR + k0s) * 2;
    const uint32_t d1 = (uint32_t)(r1s * ASTR + k1s) * 2;

    // ldmatrix per-lane coords
    const int l7 = lane & 7;
    const uint32_t aRow = mbase + l7 + ((lane >> 3) & 1) * 8;
    const uint32_t aKof = (lane >> 4) * 16;          // bytes
    const uint32_t bRow = nbase + l7 + (lane >> 4) * 8;
    const uint32_t bKof = ((lane >> 3) & 1) * 16;    // bytes

    float acc[2][8][4];
    #pragma unroll
    for (int mt = 0; mt < 2; mt++)
        #pragma unroll
        for (int nt = 0; nt < 8; nt++)
            #pragma unroll
            for (int r = 0; r < 4; r++) acc[mt][nt][r] = 0.f;

    const int nk = K / 32;

    // stage loader
    auto load_stage = [&](int kt, int s) {
        const int k0 = kt * 32;
        const uint32_t sb = smb + (uint32_t)s * STAGEB;
        const size_t ga0 = (size_t)(m0 + r0s) * K + k0 + k0s;
        const size_t ga1 = (size_t)(m0 + r1s) * K + k0 + k1s;
        cpa16(sb + d0,            Ahi + ga0, 16);
        cpa16(sb + d1,            Ahi + ga1, 16);
        cpa16(sb + BUFB + d0,     Alo + ga0, 16);
        cpa16(sb + BUFB + d1,     Alo + ga1, 16);
        const size_t gb0 = (size_t)(n0 + r0s) * K + k0 + k0s;
        const size_t gb1 = (size_t)(n0 + r1s) * K + k0 + k1s;
        cpa16(sb + 2 * BUFB + d0, Bhi + gb0, bsz0);
        cpa16(sb + 2 * BUFB + d1, Bhi + gb1, bsz1);
        cpa16(sb + 3 * BUFB + d0, Blo + gb0, bsz0);
        cpa16(sb + 3 * BUFB + d1, Blo + gb1, bsz1);
        cpa_commit();
    };

    load_stage(0, 0);

    for (int kt = 0; kt < nk; kt++) {
        if (kt + 1 < nk) load_stage(kt + 1, (kt + 1) & 1);
        if (kt + 1 < nk) cpa_wait<1>(); else cpa_wait<0>();
        __syncthreads();

        const uint32_t sb = smb + (uint32_t)(kt & 1) * STAGEB;
        const uint32_t bAh = sb, bAl = sb + BUFB, bBh = sb + 2 * BUFB, bBl = sb + 3 * BUFB;

        #pragma unroll
        for (int kk = 0; kk < 2; kk++) {
            const uint32_t kb = kk * 32;   // 16 bf16 = 32 bytes
            uint32_t ah[2][4], al[2][4];
            #pragma unroll
            for (int mt = 0; mt < 2; mt++) {
                const uint32_t ro = (aRow + mt * 16) * (ASTR * 2) + kb + aKof;
                ldm_x4(ah[mt], bAh + ro);
                ldm_x4(al[mt], bAl + ro);
            }
            #pragma unroll
            for (int np = 0; np < 4; np++) {
                const uint32_t ro = (bRow + np * 16) * (ASTR * 2) + kb + bKof;
                uint32_t tb[4], tl[4];
                ldm_x4(tb, bBh + ro);
                ldm_x4(tl, bBl + ro);
                uint32_t bh0[2] = {tb[0], tb[1]}, bh1[2] = {tb[2], tb[3]};
                uint32_t bl0[2] = {tl[0], tl[1]}, bl1[2] = {tl[2], tl[3]};
                #pragma unroll
                for (int mt = 0; mt < 2; mt++) {
                    mma_bf16(acc[mt][np * 2 + 0], ah[mt], bh0);
                    mma_bf16(acc[mt][np * 2 + 0], al[mt], bh0);
                    mma_bf16(acc[mt][np * 2 + 0], ah[mt], bl0);
                    mma_bf16(acc[mt][np * 2 + 1], ah[mt], bh1);
                    mma_bf16(acc[mt][np * 2 + 1], al[mt], bh1);
                    mma_bf16(acc[mt][np * 2 + 1], ah[mt], bl1);
                }
            }
        }
        __syncthreads();
    }

    #pragma unroll
    for (int mt = 0; mt < 2; mt++) {
        #pragma unroll
        for (int nt = 0; nt < 8; nt++) {
            const int n = n0 + nbase + nt * 8 + q * 2;
            if (n < N) {
                #pragma unroll
                for (int half = 0; half < 2; half++) {
                    const int m = m0 + mbase + mt * 16 + g + half * 8;
                    float v0 = acc[mt][nt][half * 2 + 0];
                    float v1 = acc[mt][nt][half * 2 + 1];
                    if (bias0) { v0 += bias0[n]; v1 += bias0[n + 1]; }
                    if (bias1) { v0 += bias1[n]; v1 += bias1[n + 1]; }
                    *(float2*)(C + (size_t)m * ldc + n) = make_float2(v0, v1);
                }
            }
        }
    }
}

// ---------------- fp32 -> bf16 hi/lo, 8 elems/thread (contiguous) ----------------
__global__ void __launch_bounds__(256) cvt_k8(
    const float* __restrict__ src,
    __nv_bfloat16* __restrict__ hi, __nv_bfloat16* __restrict__ lo, int total)
{
    const int i = (blockIdx.x * 256 + threadIdx.x) * 8;
    if (i < total) {
        float4 x0 = *(const float4*)(src + i);
        float4 x1 = *(const float4*)(src + i + 4);
        float xs[8] = {x0.x, x0.y, x0.z, x0.w, x1.x, x1.y, x1.z, x1.w};
        __nv_bfloat16 h8[8], l8[8];
        #pragma unroll
        for (int j = 0; j < 8; j++) {
            __nv_bfloat16 h = __float2bfloat16(xs[j]);
            h8[j] = h;
            l8[j] = __float2bfloat16(xs[j] - __bfloat162float(h));
        }
        *(uint4*)(hi + i) = *(const uint4*)h8;
        *(uint4*)(lo + i) = *(const uint4*)l8;
    }
}

// ---------------- concat A = [ctx(b) | embed(tok)] bf16 hi/lo, 8/thread ----------------
__global__ void __launch_bounds__(256) cvt_concat8(const float* __restrict__ embed) {
    const int i = (blockIdx.x * 256 + threadIdx.x) * 8;
    if (i < TT * BB * 1024) {
        const int r = i >> 10, k = i & 1023;
        const float* sp = (k < 512)
            ? (g_ctx + (r & 63) * 512 + k)
            : (embed + (size_t)g_rowmap[r] * 512 + (k - 512));
        float4 x0 = *(const float4*)sp;
        float4 x1 = *(const float4*)(sp + 4);
        float xs[8] = {x0.x, x0.y, x0.z, x0.w, x1.x, x1.y, x1.z, x1.w};
        __nv_bfloat16 h8[8], l8[8];
        #pragma unroll
        for (int j = 0; j < 8; j++) {
            __nv_bfloat16 h = __float2bfloat16(xs[j]);
            h8[j] = h;
            l8[j] = __float2bfloat16(xs[j] - __bfloat162float(h));
        }
        *(uint4*)(g_A_hi + i) = *(const uint4*)h8;
        *(uint4*)(g_A_lo + i) = *(const uint4*)l8;
    }
}

// ---------------- attention logits + softmax weights ----------------
__global__ void __launch_bounds__(256) attn_logits(const float* __restrict__ features,
                                                   const float* __restrict__ W_av) {
    const int b = blockIdx.x;
    __shared__ float sW[512];
    __shared__ float sA[NNF];
    __shared__ float sred[8];
    __shared__ float s_max, s_inv;
    const int tid = threadIdx.x;
    const int wid = tid >> 5, lane = tid & 31;

    for (int i = tid; i < 512; i += 256) sW[i] = W_av[i];
    __syncthreads();

    const float* fb = features + (size_t)b * NNF * 512;

    for (int n = wid; n < NNF; n += 8) {
        const float* fr = fb + (size_t)n * 512;
        float s0 = 0.f, s1 = 0.f, s2 = 0.f, s3 = 0.f;
        #pragma unroll
        for (int i = 0; i < 4; i++) {
            const int o = lane + i * 128;
            s0 = fmaf(fr[o],      sW[o],      s0);
            s1 = fmaf(fr[o + 32], sW[o + 32], s1);
            s2 = fmaf(fr[o + 64], sW[o + 64], s2);
            s3 = fmaf(fr[o + 96], sW[o + 96], s3);
        }
        float s = (s0 + s1) + (s2 + s3);
        #pragma unroll
        for (int o = 16; o; o >>= 1) s += __shfl_down_sync(0xffffffffu, s, o);
        if (!lane) sA[n] = s;
    }
    __syncthreads();

    float m = -3.0e38f;
    for (int n = tid; n < NNF; n += 256) m = fmaxf(m, sA[n]);
    #pragma unroll
    for (int o = 16; o; o >>= 1) m = fmaxf(m, __shfl_down_sync(0xffffffffu, m, o));
    if (!lane) sred[wid] = m;
    __syncthreads();
    if (tid == 0) {
        float mm = sred[0];
        #pragma unroll
        for (int i = 1; i < 8; i++) mm = fmaxf(mm, sred[i]);
        s_max = mm;
    }
    __syncthreads();
    const float mm = s_max;

    float s = 0.f;
    for (int n = tid; n < NNF; n += 256) { float e = __expf(sA[n] - mm); sA[n] = e; s += e; }
    #pragma unroll
    for (int o = 16; o; o >>= 1) s += __shfl_down_sync(0xffffffffu, s, o);
    if (!lane) sred[wid] = s;
    __syncthreads();
    if (tid == 0) {
        float ss = 0.f;
        #pragma unroll
        for (int i = 0; i < 8; i++) ss += sred[i];
        s_inv = 1.f / ss;
    }
    __syncthreads();
    const float inv = s_inv;
    for (int n = tid; n < NNF; n += 256) g_attw[b * NNF + n] = sA[n] * inv;
}

// ---------------- ctx + fmean (wide, ILP) ----------------
__global__ void __launch_bounds__(128) attn_ctx(const float* __restrict__ features) {
    const int b = blockIdx.x;
    const int v = blockIdx.y * 128 + threadIdx.x;
    __shared__ float sw[NNF];
    for (int i = threadIdx.x; i < NNF; i += 128) sw[i] = g_attw[b * NNF + i];
    __syncthreads();

    const float* fp = features + (size_t)b * NNF * 512 + v;
    float ac0 = 0.f, ac1 = 0.f, ac2 = 0.f, ac3 = 0.f;
    float am0 = 0.f, am1 = 0.f, am2 = 0.f, am3 = 0.f;
    #pragma unroll 4
    for (int n = 0; n < NNF; n += 4) {
        float f0 = fp[(size_t)(n + 0) * 512];
        float f1 = fp[(size_t)(n + 1) * 512];
        float f2 = fp[(size_t)(n + 2) * 512];
        float f3 = fp[(size_t)(n + 3) * 512];
        ac0 = fmaf(sw[n + 0], f0, ac0); am0 += f0;
        ac1 = fmaf(sw[n + 1], f1, ac1); am1 += f1;
        ac2 = fmaf(sw[n + 2], f2, ac2); am2 += f2;
        ac3 = fmaf(sw[n + 3], f3, ac3); am3 += f3;
    }
    g_ctx  [b * 512 + v] = (ac0 + ac1) + (ac2 + ac3);
    g_fmean[b * 512 + v] = ((am0 + am1) + (am2 + am3)) * (1.f / (float)NNF);
}

// ---------------- rowmap ----------------
__global__ void rowmap_kernel(const int* __restrict__ captions) {
    int r = blockIdx.x * 256 + threadIdx.x;
    if (r < TT * BB) {
        int b = r & 63, t = r >> 6;
        g_rowmap[r] = captions[b * TT + t];
    }
}

// ================= persistent LSTM (phase0 init + 20 steps, 1 launch) =========
__device__ __forceinline__ void gbar() {
    __syncthreads();
    if (threadIdx.x == 0) {
        unsigned long long old = atomicAdd(&g_bar, 1ULL);
        unsigned long long tgt = old - (old & (unsigned long long)(NBLK - 1)) + (unsigned long long)NBLK;
        unsigned long long cur;
        do {
            asm volatile("ld.global.acquire.gpu.u64 %0, [%1];" : "=l"(cur) : "l"(&g_bar));
        } while (cur < tgt);
    }
    __syncthreads();
}

#define DOTS()                                                                 \
    for (int b = 0; b < BB; b++) {                                             \
        float a0 = 0.f, a1 = 0.f;                                              \
        _Pragma("unroll")                                                      \
        for (int j = 0; j < 4; j++) {                                          \
            float4 hv = *(const float4*)&hs[b * 512 + j * 128 + ks * 4];       \
            a0 = fmaf(W0[j*4+0], hv.x, a0); a0 = fmaf(W0[j*4+1], hv.y, a0);    \
            a0 = fmaf(W0[j*4+2], hv.z, a0); a0 = fmaf(W0[j*4+3], hv.w, a0);    \
            a1 = fmaf(W1[j*4+0], hv.x, a1); a1 = fmaf(W1[j*4+1], hv.y, a1);    \
            a1 = fmaf(W1[j*4+2], hv.z, a1); a1 = fmaf(W1[j*4+3], hv.w, a1);    \
        }                                                                      \
        _Pragma("unroll")                                                      \
        for (int o = 16; o; o >>= 1) {                                         \
            a0 += __shfl_xor_sync(0xffffffffu, a0, o);                         \
            a1 += __shfl_xor_sync(0xffffffffu, a1, o);                         \
        }                                                                      \
        if (ks == 0) { gates[w * 64 + b] += a0; gates[(w + 8) * 64 + b] += a1; } \
    }

__global__ void __launch_bounds__(256, 1) lstm_kernel(
    const float* __restrict__ Winit_h, const float* __restrict__ Winit_c,
    const float* __restrict__ Whh)
{
    extern __shared__ float smemf[];
    float* hs    = smemf;             // [64][512]
    float* gates = smemf + BB * 512;  // [16][64]

    const int tid = threadIdx.x;
    const int w   = tid >> 5;
    const int ks  = tid & 31;
    const int bc  = tid & 63;
    const int uu  = tid >> 6;
    const int u0  = blockIdx.x * 4;

    float W0[16], W1[16];

    // ---- phase 0: h0/c0 from fmean ----
    {
        const float* s0 = (w < 4) ? (Winit_h + (size_t)(u0 + w) * 512)
                                  : (Winit_c + (size_t)(u0 + w - 4) * 512);
        #pragma unroll
        for (int j = 0; j < 4; j++) {
            float4 v = *(const float4*)(s0 + j * 128 + ks * 4);
            W0[j*4+0] = v.x; W0[j*4+1] = v.y; W0[j*4+2] = v.z; W0[j*4+3] = v.w;
            W1[j*4+0] = 0.f; W1[j*4+1] = 0.f; W1[j*4+2] = 0.f; W1[j*4+3] = 0.f;
        }
    }
    {
        const float4* src = (const float4*)g_fmean;
        float4* dst = (float4*)hs;
        for (int i = tid; i < BB * 128; i += 256) dst[i] = src[i];
    }
    for (int i = tid; i < 1024; i += 256) gates[i] = 0.f;
    __syncthreads();

    DOTS();
    __syncthreads();

    float c  = gates[(4 + uu) * 64 + bc];
    {
        float h0 = gates[uu * 64 + bc];
        g_hbuf[0][bc * 512 + u0 + uu] = h0;
    }

    // prefetch gpre for t=0
    float gp[4];
    {
        const float* gpp = g_gpre + (size_t)bc * G4 + u0 + uu;
        #pragma unroll
        for (int i = 0; i < 4; i++) gp[i] = gpp[i * 512];
    }
    __threadfence();
    gbar();

    // ---- steady-state weights ----
    {
        const float* r0p = Whh + (size_t)((w >> 2) * 512 + u0 + (w & 3)) * 512;
        const float* r1p = Whh + (size_t)(((w >> 2) + 2) * 512 + u0 + (w & 3)) * 512;
        #pragma unroll
        for (int j = 0; j < 4; j++) {
            float4 v0 = *(const float4*)(r0p + j * 128 + ks * 4);
            float4 v1 = *(const float4*)(r1p + j * 128 + ks * 4);
            W0[j*4+0] = v0.x; W0[j*4+1] = v0.y; W0[j*4+2] = v0.z; W0[j*4+3] = v0.w;
            W1[j*4+0] = v1.x; W1[j*4+1] = v1.y; W1[j*4+2] = v1.z; W1[j*4+3] = v1.w;
        }
    }

    for (int t = 0; t < TT; t++) {
        {
            const float4* src = (const float4*)g_hbuf[t & 1];
            float4* dst = (float4*)hs;
            for (int i = tid; i < BB * 128; i += 256) dst[i] = src[i];
        }
        #pragma unroll
        for (int i = 0; i < 4; i++) gates[(i * 4 + uu) * 64 + bc] = gp[i];
        __syncthreads();

        DOTS();
        __syncthreads();

        const float gi = gates[(0 + uu) * 64 + bc];
        const float gf = gates[(4 + uu) * 64 + bc];
        const float gg = gates[(8 + uu) * 64 + bc];
        const float go = gates[(12 + uu) * 64 + bc];
        const float si = 1.f / (1.f + __expf(-gi));
        const float sf = 1.f / (1.f + __expf(-gf));
        const float so = 1.f / (1.f + __expf(-go));
        c = sf * c + si * tanhf(gg);
        const float hnew = so * tanhf(c);

        g_hbuf[(t + 1) & 1][bc * 512 + u0 + uu] = hnew;
        const __nv_bfloat16 hb = __float2bfloat16(hnew);
        g_hall_hi[(size_t)(t * 64 + bc) * 512 + u0 + uu] = hb;
        g_hall_lo[(size_t)(t * 64 + bc) * 512 + u0 + uu] =
            __float2bfloat16(hnew - __bfloat162float(hb));

        if (t < TT - 1) {
            const float* gpp = g_gpre + (size_t)(t + 1) * BB * G4 + (size_t)bc * G4 + u0 + uu;
            #pragma unroll
            for (int i = 0; i < 4; i++) gp[i] = gpp[i * 512];
            __threadfence();
            gbar();
        } else {
            __syncthreads();
        }
    }
}

// ---------------- fused log_softmax + softmax over V=10000 (float4) ----------------
__global__ void __launch_bounds__(256) softmax_kernel(float* __restrict__ out) {
    const int r = blockIdx.x;
    const float4* x4 = (const float4*)(g_words + (size_t)r * VOC);
    float4* ols = (float4*)(out + (size_t)r * VOC);
    float4* osm = (float4*)(out + (size_t)TT * BB * VOC + (size_t)r * VOC);

    float m = -3.0e38f, s = 0.f;
    for (int i = threadIdx.x; i < VOC / 4; i += 256) {
        float4 v = x4[i];
        float m4 = fmaxf(fmaxf(v.x, v.y), fmaxf(v.z, v.w));
        float mn = fmaxf(m, m4);
        s = s * __expf(m - mn) + __expf(v.x - mn) + __expf(v.y - mn)
                               + __expf(v.z - mn) + __expf(v.w - mn);
        m = mn;
    }
    #pragma unroll
    for (int o = 16; o; o >>= 1) {
        float m2 = __shfl_down_sync(0xffffffffu, m, o);
        float s2 = __shfl_down_sync(0xffffffffu, s, o);
        float mx = fmaxf(m, m2);
        s = s * __expf(m - mx) + s2 * __expf(m2 - mx);
        m = mx;
    }
    __shared__ float sm[8], ss[8];
    __shared__ float bM, bS;
    const int wid = threadIdx.x >> 5, lane = threadIdx.x & 31;
    if (!lane) { sm[wid] = m; ss[wid] = s; }
    __syncthreads();
    if (threadIdx.x == 0) {
        float M = sm[0], S = ss[0];
        #pragma unroll
        for (int i = 1; i < 8; i++) {
            float mx = fmaxf(M, sm[i]);
            S = S * __expf(M - mx) + ss[i] * __expf(sm[i] - mx);
            M = mx;
        }
        bM = M; bS = S;
    }
    __syncthreads();
    const float M = bM;
    const float Sinv = 1.f / bS;
    const float lg = __logf(bS);
    for (int i = threadIdx.x; i < VOC / 4; i += 256) {
        float4 v = x4[i];
        float4 l4, p4;
        l4.x = v.x - M - lg; p4.x = __expf(v.x - M) * Sinv;
        l4.y = v.y - M - lg; p4.y = __expf(v.y - M) * Sinv;
        l4.z = v.z - M - lg; p4.z = __expf(v.z - M) * Sinv;
        l4.w = v.w - M - lg; p4.w = __expf(v.w - M) * Sinv;
        ols[i] = l4;
        osm[i] = p4;
    }
}

// ---------------- launch ----------------
extern "C" void kernel_launch(void* const* d_in, const int* in_sizes, int n_in,
                              void* d_out, int out_size) {
    (void)in_sizes; (void)n_in; (void)out_size;
    const float* features = (const float*)d_in[0];
    const int*   captions = (const int*)  d_in[1];
    const float* W_init_h = (const float*)d_in[2];
    const float* W_init_c = (const float*)d_in[3];
    const float* W_av     = (const float*)d_in[4];
    // d_in[5] b_av, d_in[6] W_ah, d_in[7] b_ah : dead (softmax shift-invariance)
    const float* embed    = (const float*)d_in[8];
    const float* W_ih     = (const float*)d_in[9];
    const float* W_hh     = (const float*)d_in[10];
    const float* b_ih     = (const float*)d_in[11];
    const float* b_hh     = (const float*)d_in[12];
    const float* W_out    = (const float*)d_in[13];
    const float* b_out    = (const float*)d_in[14];
    float* out = (float*)d_out;

    float *gpre, *words;
    __nv_bfloat16 *wout_hi, *wout_lo, *wih_hi, *wih_lo, *a_hi, *a_lo, *hall_hi, *hall_lo;
    cudaGetSymbolAddress((void**)&gpre,    g_gpre);
    cudaGetSymbolAddress((void**)&words,   g_words);
    cudaGetSymbolAddress((void**)&wout_hi, g_Wout_hi);
    cudaGetSymbolAddress((void**)&wout_lo, g_Wout_lo);
    cudaGetSymbolAddress((void**)&wih_hi,  g_Wih_hi);
    cudaGetSymbolAddress((void**)&wih_lo,  g_Wih_lo);
    cudaGetSymbolAddress((void**)&a_hi,    g_A_hi);
    cudaGetSymbolAddress((void**)&a_lo,    g_A_lo);
    cudaGetSymbolAddress((void**)&hall_hi, g_hall_hi);
    cudaGetSymbolAddress((void**)&hall_lo, g_hall_lo);

    const int LSTM_SMEM = (BB * 512 + 16 * 64) * 4;   // 135168 B
    cudaFuncSetAttribute(lstm_kernel, cudaFuncAttributeMaxDynamicSharedMemorySize, LSTM_SMEM);
    const int GEMM_SMEM = 2 * STAGEB;                 // 81920 B
    cudaFuncSetAttribute(gemm_mma, cudaFuncAttributeMaxDynamicSharedMemorySize, GEMM_SMEM);

    // 1-3) attention weights, ctx+fmean, rowmap
    attn_logits<<<BB, 256>>>(features, W_av);
    attn_ctx<<<dim3(BB, 4), 128>>>(features);
    rowmap_kernel<<<(TT * BB + 255) / 256, 256>>>(captions);

    // 4-5) concat A + W_ih conversion
    cvt_concat8<<<(TT * BB * 1024 / 8 + 255) / 256, 256>>>(embed);
    cvt_k8<<<(G4 * 1024 / 8 + 255) / 256, 256>>>(W_ih, wih_hi, wih_lo, G4 * 1024);

    // 6) gpre = [ctx|emb] @ W_ih^T + b_ih + b_hh   (K=1024)  <- ncu -s 5 lands here
    gemm_mma<<<dim3(TT * BB / 128, G4 / 128), 256, GEMM_SMEM>>>(
        a_hi, a_lo, wih_hi, wih_lo, gpre, G4, G4, 1024, b_ih, b_hh);

    // 7) persistent LSTM
    lstm_kernel<<<NBLK, 256, LSTM_SMEM>>>(W_init_h, W_init_c, W_hh);

    // 8) W_out conversion (independent, placed late)
    cvt_k8<<<(VOC * 512 / 8 + 255) / 256, 256>>>(W_out, wout_hi, wout_lo, VOC * 512);

    // 9) words = hall @ W_out^T + b_out (K=512)
    gemm_mma<<<dim3(TT * BB / 128, (VOC + 127) / 128), 256, GEMM_SMEM>>>(
        hall_hi, hall_lo, wout_hi, wout_lo, words, VOC, VOC, 512, b_out, nullptr);

    // 10) fused log_softmax + softmax
    softmax_kernel<<<TT * BB, 256>>>(out);
}

// round 8
// speedup vs baseline: 2.1698x; 1.0965x over previous
#include <cuda_runtime.h>
#include <cuda_fp16.h>
#include <cstdint>
#include <cstddef>

#define TT   20
#define BB   64
#define NNF  196
#define VOC  10000
#define G4   2048
#define NBLK 128          // persistent LSTM grid (<= SM count, 1 block/SM)

// ---------------- static device scratch ----------------
__device__ float g_fmean[BB * 512];
__device__ float g_ctx  [BB * 512];
__device__ float g_attw [BB * NNF];
__device__ float g_gpre [TT * BB * G4];
__device__ float g_words[TT * BB * VOC];
__device__ float g_hbuf [2][BB * 512];
__device__ int   g_rowmap[TT * BB];
__device__ unsigned long long g_bar;   // monotonic across replays

// fp16 split operands: A-side keeps hi+lo, B-side hi only (2-pass split-fp16)
__device__ __half g_Wout_hi[VOC * 512];
__device__ __half g_Wih_hi [G4 * 1024];
__device__ __half g_A_hi   [TT * BB * 1024], g_A_lo[TT * BB * 1024];
__device__ __half g_hall_hi[TT * BB * 512],  g_hall_lo[TT * BB * 512];

// ---------------- helpers ----------------
__device__ __forceinline__ uint32_t smem_u32(const void* p) {
    uint32_t a;
    asm("{ .reg .u64 t; cvta.to.shared.u64 t, %1; cvt.u32.u64 %0, t; }"
        : "=r"(a) : "l"(p));
    return a;
}
__device__ __forceinline__ void ldm_x4(uint32_t* r, uint32_t addr) {
    asm volatile("ldmatrix.sync.aligned.m8n8.x4.shared.b16 {%0,%1,%2,%3}, [%4];"
                 : "=r"(r[0]), "=r"(r[1]), "=r"(r[2]), "=r"(r[3]) : "r"(addr));
}
__device__ __forceinline__ void mma_fp16(float* d, const uint32_t* a, const uint32_t* b) {
    asm volatile(
        "mma.sync.aligned.m16n8k16.row.col.f32.f16.f16.f32 "
        "{%0,%1,%2,%3}, {%4,%5,%6,%7}, {%8,%9}, {%0,%1,%2,%3};"
        : "+f"(d[0]), "+f"(d[1]), "+f"(d[2]), "+f"(d[3])
        : "r"(a[0]), "r"(a[1]), "r"(a[2]), "r"(a[3]), "r"(b[0]), "r"(b[1]));
}
__device__ __forceinline__ void cpa16(uint32_t dst, const void* src, int srcsz) {
    asm volatile("cp.async.cg.shared.global [%0], [%1], 16, %2;"
                 :: "r"(dst), "l"(src), "r"(srcsz));
}
__device__ __forceinline__ void cpa_commit() {
    asm volatile("cp.async.commit_group;");
}
template<int NG> __device__ __forceinline__ void cpa_wait() {
    asm volatile("cp.async.wait_group %0;" :: "n"(NG));
}

// ============ 2-pass split-fp16 GEMM: C[m,n] = sum_k A[m,k]*B[n,k] ==========
// BM=128, BN=128, BK=32; 8 warps (4x2); warp tile 32x64.
// cp.async 2-stage double buffer; acc = Ahi*Bhi + Alo*Bhi (residual ~2^-12).
#define ASTR 40                         // padded fp16 row stride (80B)
#define BUFB (128 * ASTR * 2)           // one operand buffer: 10240 bytes
#define STAGEB (3 * BUFB)               // Ah|Al|Bh per stage: 30720 bytes

__global__ void __launch_bounds__(256) gemm_mma(
    const __half* __restrict__ Ahi, const __half* __restrict__ Alo,
    const __half* __restrict__ Bhi,
    float* __restrict__ C, int N, int ldc, int K,
    const float* __restrict__ bias0, const float* __restrict__ bias1)
{
    extern __shared__ __align__(16) __half dsm[];
    const uint32_t smb = smem_u32(dsm);

    const int tid  = threadIdx.x;
    const int lane = tid & 31;
    const int w    = tid >> 5;
    const int wm   = w >> 1;                // 0..3
    const int wn   = w & 1;                 // 0..1
    const int m0   = blockIdx.x * 128;
    const int n0   = blockIdx.y * 128;
    const int mbase = wm * 32;
    const int nbase = wn * 64;
    const int g = lane >> 2;
    const int q = lane & 3;

    // staging: chunk i in [0,512): row r=i>>2, k-offset kq=(i&3)*8 (elements)
    const int i0 = tid, i1 = tid + 256;
    const int r0s = i0 >> 2, k0s = (i0 & 3) * 8;
    const int r1s = i1 >> 2, k1s = (i1 & 3) * 8;
    const int bsz0 = (n0 + r0s) < N ? 16 : 0;
    const int bsz1 = (n0 + r1s) < N ? 16 : 0;
    const uint32_t d0 = (uint32_t)(r0s * ASTR + k0s) * 2;
    const uint32_t d1 = (uint32_t)(r1s * ASTR + k1s) * 2;

    // ldmatrix per-lane coords
    const int l7 = lane & 7;
    const uint32_t aRow = mbase + l7 + ((lane >> 3) & 1) * 8;
    const uint32_t aKof = (lane >> 4) * 16;          // bytes
    const uint32_t bRow = nbase + l7 + (lane >> 4) * 8;
    const uint32_t bKof = ((lane >> 3) & 1) * 16;    // bytes

    float acc[2][8][4];
    #pragma unroll
    for (int mt = 0; mt < 2; mt++)
        #pragma unroll
        for (int nt = 0; nt < 8; nt++)
            #pragma unroll
            for (int r = 0; r < 4; r++) acc[mt][nt][r] = 0.f;

    const int nk = K / 32;

    auto load_stage = [&](int kt, int s) {
        const int k0 = kt * 32;
        const uint32_t sb = smb + (uint32_t)s * STAGEB;
        const size_t ga0 = (size_t)(m0 + r0s) * K + k0 + k0s;
        const size_t ga1 = (size_t)(m0 + r1s) * K + k0 + k1s;
        cpa16(sb + d0,            Ahi + ga0, 16);
        cpa16(sb + d1,            Ahi + ga1, 16);
        cpa16(sb + BUFB + d0,     Alo + ga0, 16);
        cpa16(sb + BUFB + d1,     Alo + ga1, 16);
        const size_t gb0 = (size_t)(n0 + r0s) * K + k0 + k0s;
        const size_t gb1 = (size_t)(n0 + r1s) * K + k0 + k1s;
        cpa16(sb + 2 * BUFB + d0, Bhi + gb0, bsz0);
        cpa16(sb + 2 * BUFB + d1, Bhi + gb1, bsz1);
        cpa_commit();
    };

    load_stage(0, 0);

    for (int kt = 0; kt < nk; kt++) {
        if (kt + 1 < nk) load_stage(kt + 1, (kt + 1) & 1);
        if (kt + 1 < nk) cpa_wait<1>(); else cpa_wait<0>();
        __syncthreads();

        const uint32_t sb = smb + (uint32_t)(kt & 1) * STAGEB;
        const uint32_t bAh = sb, bAl = sb + BUFB, bBh = sb + 2 * BUFB;

        #pragma unroll
        for (int kk = 0; kk < 2; kk++) {
            const uint32_t kb = kk * 32;   // 16 fp16 = 32 bytes
            uint32_t ah[2][4], al[2][4];
            #pragma unroll
            for (int mt = 0; mt < 2; mt++) {
                const uint32_t ro = (aRow + mt * 16) * (ASTR * 2) + kb + aKof;
                ldm_x4(ah[mt], bAh + ro);
                ldm_x4(al[mt], bAl + ro);
            }
            #pragma unroll
            for (int np = 0; np < 4; np++) {
                const uint32_t ro = (bRow + np * 16) * (ASTR * 2) + kb + bKof;
                uint32_t tb[4];
                ldm_x4(tb, bBh + ro);
                uint32_t bh0[2] = {tb[0], tb[1]}, bh1[2] = {tb[2], tb[3]};
                #pragma unroll
                for (int mt = 0; mt < 2; mt++) {
                    mma_fp16(acc[mt][np * 2 + 0], ah[mt], bh0);
                    mma_fp16(acc[mt][np * 2 + 0], al[mt], bh0);
                    mma_fp16(acc[mt][np * 2 + 1], ah[mt], bh1);
                    mma_fp16(acc[mt][np * 2 + 1], al[mt], bh1);
                }
            }
        }
        __syncthreads();
    }

    #pragma unroll
    for (int mt = 0; mt < 2; mt++) {
        #pragma unroll
        for (int nt = 0; nt < 8; nt++) {
            const int n = n0 + nbase + nt * 8 + q * 2;
            if (n < N) {
                #pragma unroll
                for (int half = 0; half < 2; half++) {
                    const int m = m0 + mbase + mt * 16 + g + half * 8;
                    float v0 = acc[mt][nt][half * 2 + 0];
                    float v1 = acc[mt][nt][half * 2 + 1];
                    if (bias0) { v0 += bias0[n]; v1 += bias0[n + 1]; }
                    if (bias1) { v0 += bias1[n]; v1 += bias1[n + 1]; }
                    *(float2*)(C + (size_t)m * ldc + n) = make_float2(v0, v1);
                }
            }
        }
    }
}

// ---------------- fp32 -> fp16 hi only, 8 elems/thread ----------------
__global__ void __launch_bounds__(256) cvt_hi8(
    const float* __restrict__ src, __half* __restrict__ hi, int total)
{
    const int i = (blockIdx.x * 256 + threadIdx.x) * 8;
    if (i < total) {
        float4 x0 = *(const float4*)(src + i);
        float4 x1 = *(const float4*)(src + i + 4);
        float xs[8] = {x0.x, x0.y, x0.z, x0.w, x1.x, x1.y, x1.z, x1.w};
        __half h8[8];
        #pragma unroll
        for (int j = 0; j < 8; j++) h8[j] = __float2half_rn(xs[j]);
        *(uint4*)(hi + i) = *(const uint4*)h8;
    }
}

// ---------------- concat A = [ctx(b) | embed(tok)] fp16 hi/lo, 8/thread ----------------
__global__ void __launch_bounds__(256) cvt_concat8(const float* __restrict__ embed) {
    const int i = (blockIdx.x * 256 + threadIdx.x) * 8;
    if (i < TT * BB * 1024) {
        const int r = i >> 10, k = i & 1023;
        const float* sp = (k < 512)
            ? (g_ctx + (r & 63) * 512 + k)
            : (embed + (size_t)g_rowmap[r] * 512 + (k - 512));
        float4 x0 = *(const float4*)sp;
        float4 x1 = *(const float4*)(sp + 4);
        float xs[8] = {x0.x, x0.y, x0.z, x0.w, x1.x, x1.y, x1.z, x1.w};
        __half h8[8], l8[8];
        #pragma unroll
        for (int j = 0; j < 8; j++) {
            __half h = __float2half_rn(xs[j]);
            h8[j] = h;
            l8[j] = __float2half_rn(xs[j] - __half2float(h));
        }
        *(uint4*)(g_A_hi + i) = *(const uint4*)h8;
        *(uint4*)(g_A_lo + i) = *(const uint4*)l8;
    }
}

// ---------------- attention logits + softmax weights ----------------
__global__ void __launch_bounds__(256) attn_logits(const float* __restrict__ features,
                                                   const float* __restrict__ W_av) {
    const int b = blockIdx.x;
    __shared__ float sW[512];
    __shared__ float sA[NNF];
    __shared__ float sred[8];
    __shared__ float s_max, s_inv;
    const int tid = threadIdx.x;
    const int wid = tid >> 5, lane = tid & 31;

    for (int i = tid; i < 512; i += 256) sW[i] = W_av[i];
    __syncthreads();

    const float* fb = features + (size_t)b * NNF * 512;

    for (int n = wid; n < NNF; n += 8) {
        const float* fr = fb + (size_t)n * 512;
        float s0 = 0.f, s1 = 0.f, s2 = 0.f, s3 = 0.f;
        #pragma unroll
        for (int i = 0; i < 4; i++) {
            const int o = lane + i * 128;
            s0 = fmaf(fr[o],      sW[o],      s0);
            s1 = fmaf(fr[o + 32], sW[o + 32], s1);
            s2 = fmaf(fr[o + 64], sW[o + 64], s2);
            s3 = fmaf(fr[o + 96], sW[o + 96], s3);
        }
        float s = (s0 + s1) + (s2 + s3);
        #pragma unroll
        for (int o = 16; o; o >>= 1) s += __shfl_down_sync(0xffffffffu, s, o);
        if (!lane) sA[n] = s;
    }
    __syncthreads();

    float m = -3.0e38f;
    for (int n = tid; n < NNF; n += 256) m = fmaxf(m, sA[n]);
    #pragma unroll
    for (int o = 16; o; o >>= 1) m = fmaxf(m, __shfl_down_sync(0xffffffffu, m, o));
    if (!lane) sred[wid] = m;
    __syncthreads();
    if (tid == 0) {
        float mm = sred[0];
        #pragma unroll
        for (int i = 1; i < 8; i++) mm = fmaxf(mm, sred[i]);
        s_max = mm;
    }
    __syncthreads();
    const float mm = s_max;

    float s = 0.f;
    for (int n = tid; n < NNF; n += 256) { float e = __expf(sA[n] - mm); sA[n] = e; s += e; }
    #pragma unroll
    for (int o = 16; o; o >>= 1) s += __shfl_down_sync(0xffffffffu, s, o);
    if (!lane) sred[wid] = s;
    __syncthreads();
    if (tid == 0) {
        float ss = 0.f;
        #pragma unroll
        for (int i = 0; i < 8; i++) ss += sred[i];
        s_inv = 1.f / ss;
    }
    __syncthreads();
    const float inv = s_inv;
    for (int n = tid; n < NNF; n += 256) g_attw[b * NNF + n] = sA[n] * inv;
}

// ---------------- ctx + fmean (wide, ILP) ----------------
__global__ void __launch_bounds__(128) attn_ctx(const float* __restrict__ features) {
    const int b = blockIdx.x;
    const int v = blockIdx.y * 128 + threadIdx.x;
    __shared__ float sw[NNF];
    for (int i = threadIdx.x; i < NNF; i += 128) sw[i] = g_attw[b * NNF + i];
    __syncthreads();

    const float* fp = features + (size_t)b * NNF * 512 + v;
    float ac0 = 0.f, ac1 = 0.f, ac2 = 0.f, ac3 = 0.f;
    float am0 = 0.f, am1 = 0.f, am2 = 0.f, am3 = 0.f;
    #pragma unroll 4
    for (int n = 0; n < NNF; n += 4) {
        float f0 = fp[(size_t)(n + 0) * 512];
        float f1 = fp[(size_t)(n + 1) * 512];
        float f2 = fp[(size_t)(n + 2) * 512];
        float f3 = fp[(size_t)(n + 3) * 512];
        ac0 = fmaf(sw[n + 0], f0, ac0); am0 += f0;
        ac1 = fmaf(sw[n + 1], f1, ac1); am1 += f1;
        ac2 = fmaf(sw[n + 2], f2, ac2); am2 += f2;
        ac3 = fmaf(sw[n + 3], f3, ac3); am3 += f3;
    }
    g_ctx  [b * 512 + v] = (ac0 + ac1) + (ac2 + ac3);
    g_fmean[b * 512 + v] = ((am0 + am1) + (am2 + am3)) * (1.f / (float)NNF);
}

// ---------------- rowmap ----------------
__global__ void rowmap_kernel(const int* __restrict__ captions) {
    int r = blockIdx.x * 256 + threadIdx.x;
    if (r < TT * BB) {
        int b = r & 63, t = r >> 6;
        g_rowmap[r] = captions[b * TT + t];
    }
}

// ================= persistent LSTM (phase0 init + 20 steps, 1 launch) =========
__device__ __forceinline__ void gbar() {
    __syncthreads();
    if (threadIdx.x == 0) {
        unsigned long long old = atomicAdd(&g_bar, 1ULL);
        unsigned long long tgt = old - (old & (unsigned long long)(NBLK - 1)) + (unsigned long long)NBLK;
        unsigned long long cur;
        do {
            asm volatile("ld.global.acquire.gpu.u64 %0, [%1];" : "=l"(cur) : "l"(&g_bar));
        } while (cur < tgt);
    }
    __syncthreads();
}

#define DOTS()                                                                 \
    for (int b = 0; b < BB; b++) {                                             \
        float a0 = 0.f, a1 = 0.f;                                              \
        _Pragma("unroll")                                                      \
        for (int j = 0; j < 4; j++) {                                          \
            float4 hv = *(const float4*)&hs[b * 512 + j * 128 + ks * 4];       \
            a0 = fmaf(W0[j*4+0], hv.x, a0); a0 = fmaf(W0[j*4+1], hv.y, a0);    \
            a0 = fmaf(W0[j*4+2], hv.z, a0); a0 = fmaf(W0[j*4+3], hv.w, a0);    \
            a1 = fmaf(W1[j*4+0], hv.x, a1); a1 = fmaf(W1[j*4+1], hv.y, a1);    \
            a1 = fmaf(W1[j*4+2], hv.z, a1); a1 = fmaf(W1[j*4+3], hv.w, a1);    \
        }                                                                      \
        _Pragma("unroll")                                                      \
        for (int o = 16; o; o >>= 1) {                                         \
            a0 += __shfl_xor_sync(0xffffffffu, a0, o);                         \
            a1 += __shfl_xor_sync(0xffffffffu, a1, o);                         \
        }                                                                      \
        if (ks == 0) { gates[w * 64 + b] += a0; gates[(w + 8) * 64 + b] += a1; } \
    }

__global__ void __launch_bounds__(256, 1) lstm_kernel(
    const float* __restrict__ Winit_h, const float* __restrict__ Winit_c,
    const float* __restrict__ Whh)
{
    extern __shared__ float smemf[];
    float* hs    = smemf;             // [64][512]
    float* gates = smemf + BB * 512;  // [16][64]

    const int tid = threadIdx.x;
    const int w   = tid >> 5;
    const int ks  = tid & 31;
    const int bc  = tid & 63;
    const int uu  = tid >> 6;
    const int u0  = blockIdx.x * 4;

    float W0[16], W1[16];

    // ---- phase 0: h0/c0 from fmean ----
    {
        const float* s0 = (w < 4) ? (Winit_h + (size_t)(u0 + w) * 512)
                                  : (Winit_c + (size_t)(u0 + w - 4) * 512);
        #pragma unroll
        for (int j = 0; j < 4; j++) {
            float4 v = *(const float4*)(s0 + j * 128 + ks * 4);
            W0[j*4+0] = v.x; W0[j*4+1] = v.y; W0[j*4+2] = v.z; W0[j*4+3] = v.w;
            W1[j*4+0] = 0.f; W1[j*4+1] = 0.f; W1[j*4+2] = 0.f; W1[j*4+3] = 0.f;
        }
    }
    {
        const float4* src = (const float4*)g_fmean;
        float4* dst = (float4*)hs;
        for (int i = tid; i < BB * 128; i += 256) dst[i] = src[i];
    }
    for (int i = tid; i < 1024; i += 256) gates[i] = 0.f;
    __syncthreads();

    DOTS();
    __syncthreads();

    float c  = gates[(4 + uu) * 64 + bc];
    {
        float h0 = gates[uu * 64 + bc];
        g_hbuf[0][bc * 512 + u0 + uu] = h0;
    }

    float gp[4];
    {
        const float* gpp = g_gpre + (size_t)bc * G4 + u0 + uu;
        #pragma unroll
        for (int i = 0; i < 4; i++) gp[i] = gpp[i * 512];
    }
    __threadfence();
    gbar();

    // ---- steady-state weights ----
    {
        const float* r0p = Whh + (size_t)((w >> 2) * 512 + u0 + (w & 3)) * 512;
        const float* r1p = Whh + (size_t)(((w >> 2) + 2) * 512 + u0 + (w & 3)) * 512;
        #pragma unroll
        for (int j = 0; j < 4; j++) {
            float4 v0 = *(const float4*)(r0p + j * 128 + ks * 4);
            float4 v1 = *(const float4*)(r1p + j * 128 + ks * 4);
            W0[j*4+0] = v0.x; W0[j*4+1] = v0.y; W0[j*4+2] = v0.z; W0[j*4+3] = v0.w;
            W1[j*4+0] = v1.x; W1[j*4+1] = v1.y; W1[j*4+2] = v1.z; W1[j*4+3] = v1.w;
        }
    }

    for (int t = 0; t < TT; t++) {
        {
            const float4* src = (const float4*)g_hbuf[t & 1];
            float4* dst = (float4*)hs;
            for (int i = tid; i < BB * 128; i += 256) dst[i] = src[i];
        }
        #pragma unroll
        for (int i = 0; i < 4; i++) gates[(i * 4 + uu) * 64 + bc] = gp[i];
        __syncthreads();

        DOTS();
        __syncthreads();

        const float gi = gates[(0 + uu) * 64 + bc];
        const float gf = gates[(4 + uu) * 64 + bc];
        const float gg = gates[(8 + uu) * 64 + bc];
        const float go = gates[(12 + uu) * 64 + bc];
        const float si = 1.f / (1.f + __expf(-gi));
        const float sf = 1.f / (1.f + __expf(-gf));
        const float so = 1.f / (1.f + __expf(-go));
        c = sf * c + si * tanhf(gg);
        const float hnew = so * tanhf(c);

        g_hbuf[(t + 1) & 1][bc * 512 + u0 + uu] = hnew;
        const __half hb = __float2half_rn(hnew);
        g_hall_hi[(size_t)(t * 64 + bc) * 512 + u0 + uu] = hb;
        g_hall_lo[(size_t)(t * 64 + bc) * 512 + u0 + uu] =
            __float2half_rn(hnew - __half2float(hb));

        if (t < TT - 1) {
            const float* gpp = g_gpre + (size_t)(t + 1) * BB * G4 + (size_t)bc * G4 + u0 + uu;
            #pragma unroll
            for (int i = 0; i < 4; i++) gp[i] = gpp[i * 512];
            __threadfence();
            gbar();
        } else {
            __syncthreads();
        }
    }
}

// ---------------- fused log_softmax + softmax over V=10000 (float4) ----------------
__global__ void __launch_bounds__(256) softmax_kernel(float* __restrict__ out) {
    const int r = blockIdx.x;
    const float4* x4 = (const float4*)(g_words + (size_t)r * VOC);
    float4* ols = (float4*)(out + (size_t)r * VOC);
    float4* osm = (float4*)(out + (size_t)TT * BB * VOC + (size_t)r * VOC);

    float m = -3.0e38f, s = 0.f;
    for (int i = threadIdx.x; i < VOC / 4; i += 256) {
        float4 v = x4[i];
        float m4 = fmaxf(fmaxf(v.x, v.y), fmaxf(v.z, v.w));
        float mn = fmaxf(m, m4);
        s = s * __expf(m - mn) + __expf(v.x - mn) + __expf(v.y - mn)
                               + __expf(v.z - mn) + __expf(v.w - mn);
        m = mn;
    }
    #pragma unroll
    for (int o = 16; o; o >>= 1) {
        float m2 = __shfl_down_sync(0xffffffffu, m, o);
        float s2 = __shfl_down_sync(0xffffffffu, s, o);
        float mx = fmaxf(m, m2);
        s = s * __expf(m - mx) + s2 * __expf(m2 - mx);
        m = mx;
    }
    __shared__ float sm[8], ss[8];
    __shared__ float bM, bS;
    const int wid = threadIdx.x >> 5, lane = threadIdx.x & 31;
    if (!lane) { sm[wid] = m; ss[wid] = s; }
    __syncthreads();
    if (threadIdx.x == 0) {
        float M = sm[0], S = ss[0];
        #pragma unroll
        for (int i = 1; i < 8; i++) {
            float mx = fmaxf(M, sm[i]);
            S = S * __expf(M - mx) + ss[i] * __expf(sm[i] - mx);
            M = mx;
        }
        bM = M; bS = S;
    }
    __syncthreads();
    const float M = bM;
    const float Sinv = 1.f / bS;
    const float lg = __logf(bS);
    for (int i = threadIdx.x; i < VOC / 4; i += 256) {
        float4 v = x4[i];
        float4 l4, p4;
        l4.x = v.x - M - lg; p4.x = __expf(v.x - M) * Sinv;
        l4.y = v.y - M - lg; p4.y = __expf(v.y - M) * Sinv;
        l4.z = v.z - M - lg; p4.z = __expf(v.z - M) * Sinv;
        l4.w = v.w - M - lg; p4.w = __expf(v.w - M) * Sinv;
        ols[i] = l4;
        osm[i] = p4;
    }
}

// ---------------- launch ----------------
extern "C" void kernel_launch(void* const* d_in, const int* in_sizes, int n_in,
                              void* d_out, int out_size) {
    (void)in_sizes; (void)n_in; (void)out_size;
    const float* features = (const float*)d_in[0];
    const int*   captions = (const int*)  d_in[1];
    const float* W_init_h = (const float*)d_in[2];
    const float* W_init_c = (const float*)d_in[3];
    const float* W_av     = (const float*)d_in[4];
    // d_in[5] b_av, d_in[6] W_ah, d_in[7] b_ah : dead (softmax shift-invariance)
    const float* embed    = (const float*)d_in[8];
    const float* W_ih     = (const float*)d_in[9];
    const float* W_hh     = (const float*)d_in[10];
    const float* b_ih     = (const float*)d_in[11];
    const float* b_hh     = (const float*)d_in[12];
    const float* W_out    = (const float*)d_in[13];
    const float* b_out    = (const float*)d_in[14];
    float* out = (float*)d_out;

    float *gpre, *words;
    __half *wout_hi, *wih_hi, *a_hi, *a_lo, *hall_hi, *hall_lo;
    cudaGetSymbolAddress((void**)&gpre,    g_gpre);
    cudaGetSymbolAddress((void**)&words,   g_words);
    cudaGetSymbolAddress((void**)&wout_hi, g_Wout_hi);
    cudaGetSymbolAddress((void**)&wih_hi,  g_Wih_hi);
    cudaGetSymbolAddress((void**)&a_hi,    g_A_hi);
    cudaGetSymbolAddress((void**)&a_lo,    g_A_lo);
    cudaGetSymbolAddress((void**)&hall_hi, g_hall_hi);
    cudaGetSymbolAddress((void**)&hall_lo, g_hall_lo);

    const int LSTM_SMEM = (BB * 512 + 16 * 64) * 4;   // 135168 B
    cudaFuncSetAttribute(lstm_kernel, cudaFuncAttributeMaxDynamicSharedMemorySize, LSTM_SMEM);
    const int GEMM_SMEM = 2 * STAGEB;                 // 61440 B
    cudaFuncSetAttribute(gemm_mma, cudaFuncAttributeMaxDynamicSharedMemorySize, GEMM_SMEM);

    // 1-3) attention weights, ctx+fmean, rowmap
    attn_logits<<<BB, 256>>>(features, W_av);
    attn_ctx<<<dim3(BB, 4), 128>>>(features);
    rowmap_kernel<<<(TT * BB + 255) / 256, 256>>>(captions);

    // 4-5) concat A + W_ih conversion (hi only on B side)
    cvt_concat8<<<(TT * BB * 1024 / 8 + 255) / 256, 256>>>(embed);
    cvt_hi8<<<(G4 * 1024 / 8 + 255) / 256, 256>>>(W_ih, wih_hi, G4 * 1024);

    // 6) gpre = [ctx|emb] @ W_ih^T + b_ih + b_hh   (K=1024)
    gemm_mma<<<dim3(TT * BB / 128, G4 / 128), 256, GEMM_SMEM>>>(
        a_hi, a_lo, wih_hi, gpre, G4, G4, 1024, b_ih, b_hh);

    // 7) persistent LSTM
    lstm_kernel<<<NBLK, 256, LSTM_SMEM>>>(W_init_h, W_init_c, W_hh);

    // 8) W_out conversion (hi only)
    cvt_hi8<<<(VOC * 512 / 8 + 255) / 256, 256>>>(W_out, wout_hi, VOC * 512);

    // 9) words = hall @ W_out^T + b_out (K=512)
    gemm_mma<<<dim3(TT * BB / 128, (VOC + 127) / 128), 256, GEMM_SMEM>>>(
        hall_hi, hall_lo, wout_hi, words, VOC, VOC, 512, b_out, nullptr);

    // 10) fused log_softmax + softmax
    softmax_kernel<<<TT * BB, 256>>>(out);
}

// round 9
// speedup vs baseline: 4.2057x; 1.9383x over previous
#include <cuda_runtime.h>
#include <cuda_fp16.h>
#include <cstdint>
#include <cstddef>

#define TT   20
#define BB   64
#define NNF  196
#define VOC  10000
#define G4   2048
#define NBLK 128          // persistent LSTM grid

// ---------------- static device scratch ----------------
__device__ float g_fmean[BB * 512];
__device__ float g_ctx  [BB * 512];
__device__ float g_attw [BB * NNF];
__device__ float g_gpre [TT * BB * G4];
__device__ float g_words[TT * BB * VOC];
__device__ int   g_rowmap[TT * BB];
__device__ unsigned long long g_bar;   // monotonic across replays

__device__ __half g_Wout16[VOC * 512];
__device__ __half g_Wih16 [G4 * 1024];
__device__ __half g_A16   [TT * BB * 1024];
__device__ __half g_hall  [TT * BB * 512];
__device__ __half g_hb16  [2][BB * 512];

// ---------------- helpers ----------------
__device__ __forceinline__ uint32_t smem_u32(const void* p) {
    uint32_t a;
    asm("{ .reg .u64 t; cvta.to.shared.u64 t, %1; cvt.u32.u64 %0, t; }"
        : "=r"(a) : "l"(p));
    return a;
}
__device__ __forceinline__ void ldm_x4(uint32_t* r, uint32_t addr) {
    asm volatile("ldmatrix.sync.aligned.m8n8.x4.shared.b16 {%0,%1,%2,%3}, [%4];"
                 : "=r"(r[0]), "=r"(r[1]), "=r"(r[2]), "=r"(r[3]) : "r"(addr));
}
__device__ __forceinline__ void mma_fp16(float* d, const uint32_t* a, const uint32_t* b) {
    asm volatile(
        "mma.sync.aligned.m16n8k16.row.col.f32.f16.f16.f32 "
        "{%0,%1,%2,%3}, {%4,%5,%6,%7}, {%8,%9}, {%0,%1,%2,%3};"
        : "+f"(d[0]), "+f"(d[1]), "+f"(d[2]), "+f"(d[3])
        : "r"(a[0]), "r"(a[1]), "r"(a[2]), "r"(a[3]), "r"(b[0]), "r"(b[1]));
}
__device__ __forceinline__ void cpa16(uint32_t dst, const void* src, int srcsz) {
    asm volatile("cp.async.cg.shared.global [%0], [%1], 16, %2;"
                 :: "r"(dst), "l"(src), "r"(srcsz));
}
__device__ __forceinline__ void cpa_commit() {
    asm volatile("cp.async.commit_group;");
}
template<int NG> __device__ __forceinline__ void cpa_wait() {
    asm volatile("cp.async.wait_group %0;" :: "n"(NG));
}

// ============ single-pass fp16 GEMM: C[m,n] = sum_k A[m,k]*B[n,k] ==========
// BM=128, BN=128, BK=32; 8 warps (4x2); warp tile 32x64.
#define ASTR 40                         // padded fp16 row stride (80B)
#define BUFB (128 * ASTR * 2)           // one operand buffer: 10240 bytes
#define STAGEB (2 * BUFB)               // A|B per stage: 20480 bytes

__global__ void __launch_bounds__(256) gemm_mma(
    const __half* __restrict__ A, const __half* __restrict__ B,
    float* __restrict__ C, int N, int ldc, int K,
    const float* __restrict__ bias0, const float* __restrict__ bias1)
{
    extern __shared__ __align__(16) __half dsm[];
    const uint32_t smb = smem_u32(dsm);

    const int tid  = threadIdx.x;
    const int lane = tid & 31;
    const int w    = tid >> 5;
    const int wm   = w >> 1;
    const int wn   = w & 1;
    const int m0   = blockIdx.x * 128;
    const int n0   = blockIdx.y * 128;
    const int mbase = wm * 32;
    const int nbase = wn * 64;
    const int g = lane >> 2;
    const int q = lane & 3;

    const int i0 = tid, i1 = tid + 256;
    const int r0s = i0 >> 2, k0s = (i0 & 3) * 8;
    const int r1s = i1 >> 2, k1s = (i1 & 3) * 8;
    const int bsz0 = (n0 + r0s) < N ? 16 : 0;
    const int bsz1 = (n0 + r1s) < N ? 16 : 0;
    const uint32_t d0 = (uint32_t)(r0s * ASTR + k0s) * 2;
    const uint32_t d1 = (uint32_t)(r1s * ASTR + k1s) * 2;

    const int l7 = lane & 7;
    const uint32_t aRow = mbase + l7 + ((lane >> 3) & 1) * 8;
    const uint32_t aKof = (lane >> 4) * 16;
    const uint32_t bRow = nbase + l7 + (lane >> 4) * 8;
    const uint32_t bKof = ((lane >> 3) & 1) * 16;

    float acc[2][8][4];
    #pragma unroll
    for (int mt = 0; mt < 2; mt++)
        #pragma unroll
        for (int nt = 0; nt < 8; nt++)
            #pragma unroll
            for (int r = 0; r < 4; r++) acc[mt][nt][r] = 0.f;

    const int nk = K / 32;

    auto load_stage = [&](int kt, int s) {
        const int k0 = kt * 32;
        const uint32_t sb = smb + (uint32_t)s * STAGEB;
        cpa16(sb + d0,        A + (size_t)(m0 + r0s) * K + k0 + k0s, 16);
        cpa16(sb + d1,        A + (size_t)(m0 + r1s) * K + k0 + k1s, 16);
        cpa16(sb + BUFB + d0, B + (size_t)(n0 + r0s) * K + k0 + k0s, bsz0);
        cpa16(sb + BUFB + d1, B + (size_t)(n0 + r1s) * K + k0 + k1s, bsz1);
        cpa_commit();
    };

    load_stage(0, 0);

    for (int kt = 0; kt < nk; kt++) {
        if (kt + 1 < nk) load_stage(kt + 1, (kt + 1) & 1);
        if (kt + 1 < nk) cpa_wait<1>(); else cpa_wait<0>();
        __syncthreads();

        const uint32_t sb = smb + (uint32_t)(kt & 1) * STAGEB;
        const uint32_t bA = sb, bB = sb + BUFB;

        #pragma unroll
        for (int kk = 0; kk < 2; kk++) {
            const uint32_t kb = kk * 32;
            uint32_t ah[2][4];
            #pragma unroll
            for (int mt = 0; mt < 2; mt++) {
                const uint32_t ro = (aRow + mt * 16) * (ASTR * 2) + kb + aKof;
                ldm_x4(ah[mt], bA + ro);
            }
            #pragma unroll
            for (int np = 0; np < 4; np++) {
                const uint32_t ro = (bRow + np * 16) * (ASTR * 2) + kb + bKof;
                uint32_t tb[4];
                ldm_x4(tb, bB + ro);
                uint32_t bh0[2] = {tb[0], tb[1]}, bh1[2] = {tb[2], tb[3]};
                #pragma unroll
                for (int mt = 0; mt < 2; mt++) {
                    mma_fp16(acc[mt][np * 2 + 0], ah[mt], bh0);
                    mma_fp16(acc[mt][np * 2 + 1], ah[mt], bh1);
                }
            }
        }
        __syncthreads();
    }

    #pragma unroll
    for (int mt = 0; mt < 2; mt++) {
        #pragma unroll
        for (int nt = 0; nt < 8; nt++) {
            const int n = n0 + nbase + nt * 8 + q * 2;
            if (n < N) {
                #pragma unroll
                for (int half = 0; half < 2; half++) {
                    const int m = m0 + mbase + mt * 16 + g + half * 8;
                    float v0 = acc[mt][nt][half * 2 + 0];
                    float v1 = acc[mt][nt][half * 2 + 1];
                    if (bias0) { v0 += bias0[n]; v1 += bias0[n + 1]; }
                    if (bias1) { v0 += bias1[n]; v1 += bias1[n + 1]; }
                    *(float2*)(C + (size_t)m * ldc + n) = make_float2(v0, v1);
                }
            }
        }
    }
}

// ---------------- fp32 -> fp16, 8 elems/thread ----------------
__global__ void __launch_bounds__(256) cvt_hi8(
    const float* __restrict__ src, __half* __restrict__ hi, int total)
{
    const int i = (blockIdx.x * 256 + threadIdx.x) * 8;
    if (i < total) {
        float4 x0 = *(const float4*)(src + i);
        float4 x1 = *(const float4*)(src + i + 4);
        float xs[8] = {x0.x, x0.y, x0.z, x0.w, x1.x, x1.y, x1.z, x1.w};
        __half h8[8];
        #pragma unroll
        for (int j = 0; j < 8; j++) h8[j] = __float2half_rn(xs[j]);
        *(uint4*)(hi + i) = *(const uint4*)h8;
    }
}

// ---------------- concat A = [ctx(b) | embed(tok)] fp16, 8/thread ----------------
__global__ void __launch_bounds__(256) cvt_concat8(const float* __restrict__ embed) {
    const int i = (blockIdx.x * 256 + threadIdx.x) * 8;
    if (i < TT * BB * 1024) {
        const int r = i >> 10, k = i & 1023;
        const float* sp = (k < 512)
            ? (g_ctx + (r & 63) * 512 + k)
            : (embed + (size_t)g_rowmap[r] * 512 + (k - 512));
        float4 x0 = *(const float4*)sp;
        float4 x1 = *(const float4*)(sp + 4);
        float xs[8] = {x0.x, x0.y, x0.z, x0.w, x1.x, x1.y, x1.z, x1.w};
        __half h8[8];
        #pragma unroll
        for (int j = 0; j < 8; j++) h8[j] = __float2half_rn(xs[j]);
        *(uint4*)(g_A16 + i) = *(const uint4*)h8;
    }
}

// ---------------- attention logits + softmax weights ----------------
__global__ void __launch_bounds__(256) attn_logits(const float* __restrict__ features,
                                                   const float* __restrict__ W_av) {
    const int b = blockIdx.x;
    __shared__ float sW[512];
    __shared__ float sA[NNF];
    __shared__ float sred[8];
    __shared__ float s_max, s_inv;
    const int tid = threadIdx.x;
    const int wid = tid >> 5, lane = tid & 31;

    for (int i = tid; i < 512; i += 256) sW[i] = W_av[i];
    __syncthreads();

    const float* fb = features + (size_t)b * NNF * 512;

    for (int n = wid; n < NNF; n += 8) {
        const float* fr = fb + (size_t)n * 512;
        float s0 = 0.f, s1 = 0.f, s2 = 0.f, s3 = 0.f;
        #pragma unroll
        for (int i = 0; i < 4; i++) {
            const int o = lane + i * 128;
            s0 = fmaf(fr[o],      sW[o],      s0);
            s1 = fmaf(fr[o + 32], sW[o + 32], s1);
            s2 = fmaf(fr[o + 64], sW[o + 64], s2);
            s3 = fmaf(fr[o + 96], sW[o + 96], s3);
        }
        float s = (s0 + s1) + (s2 + s3);
        #pragma unroll
        for (int o = 16; o; o >>= 1) s += __shfl_down_sync(0xffffffffu, s, o);
        if (!lane) sA[n] = s;
    }
    __syncthreads();

    float m = -3.0e38f;
    for (int n = tid; n < NNF; n += 256) m = fmaxf(m, sA[n]);
    #pragma unroll
    for (int o = 16; o; o >>= 1) m = fmaxf(m, __shfl_down_sync(0xffffffffu, m, o));
    if (!lane) sred[wid] = m;
    __syncthreads();
    if (tid == 0) {
        float mm = sred[0];
        #pragma unroll
        for (int i = 1; i < 8; i++) mm = fmaxf(mm, sred[i]);
        s_max = mm;
    }
    __syncthreads();
    const float mm = s_max;

    float s = 0.f;
    for (int n = tid; n < NNF; n += 256) { float e = __expf(sA[n] - mm); sA[n] = e; s += e; }
    #pragma unroll
    for (int o = 16; o; o >>= 1) s += __shfl_down_sync(0xffffffffu, s, o);
    if (!lane) sred[wid] = s;
    __syncthreads();
    if (tid == 0) {
        float ss = 0.f;
        #pragma unroll
        for (int i = 0; i < 8; i++) ss += sred[i];
        s_inv = 1.f / ss;
    }
    __syncthreads();
    const float inv = s_inv;
    for (int n = tid; n < NNF; n += 256) g_attw[b * NNF + n] = sA[n] * inv;
}

// ---------------- ctx + fmean (wide, ILP) ----------------
__global__ void __launch_bounds__(128) attn_ctx(const float* __restrict__ features) {
    const int b = blockIdx.x;
    const int v = blockIdx.y * 128 + threadIdx.x;
    __shared__ float sw[NNF];
    for (int i = threadIdx.x; i < NNF; i += 128) sw[i] = g_attw[b * NNF + i];
    __syncthreads();

    const float* fp = features + (size_t)b * NNF * 512 + v;
    float ac0 = 0.f, ac1 = 0.f, ac2 = 0.f, ac3 = 0.f;
    float am0 = 0.f, am1 = 0.f, am2 = 0.f, am3 = 0.f;
    #pragma unroll 4
    for (int n = 0; n < NNF; n += 4) {
        float f0 = fp[(size_t)(n + 0) * 512];
        float f1 = fp[(size_t)(n + 1) * 512];
        float f2 = fp[(size_t)(n + 2) * 512];
        float f3 = fp[(size_t)(n + 3) * 512];
        ac0 = fmaf(sw[n + 0], f0, ac0); am0 += f0;
        ac1 = fmaf(sw[n + 1], f1, ac1); am1 += f1;
        ac2 = fmaf(sw[n + 2], f2, ac2); am2 += f2;
        ac3 = fmaf(sw[n + 3], f3, ac3); am3 += f3;
    }
    g_ctx  [b * 512 + v] = (ac0 + ac1) + (ac2 + ac3);
    g_fmean[b * 512 + v] = ((am0 + am1) + (am2 + am3)) * (1.f / (float)NNF);
}

// ---------------- rowmap ----------------
__global__ void rowmap_kernel(const int* __restrict__ captions) {
    int r = blockIdx.x * 256 + threadIdx.x;
    if (r < TT * BB) {
        int b = r & 63, t = r >> 6;
        g_rowmap[r] = captions[b * TT + t];
    }
}

// ================= persistent HMMA LSTM (phase0 + 20 steps, 1 launch) =========
__device__ __forceinline__ void gbar() {
    __syncthreads();
    if (threadIdx.x == 0) {
        unsigned long long old = atomicAdd(&g_bar, 1ULL);
        unsigned long long tgt = old - (old & (unsigned long long)(NBLK - 1)) + (unsigned long long)NBLK;
        unsigned long long cur;
        do {
            asm volatile("ld.global.acquire.gpu.u64 %0, [%1];" : "=l"(cur) : "l"(&g_bar));
        } while (cur < tgt);
    }
    __syncthreads();
}

#define STRH 520   // fp16 row stride for sW/sH (1040 B, conflict-free ldmatrix)

__global__ void __launch_bounds__(256, 1) lstm_kernel(
    const float* __restrict__ Winit_h, const float* __restrict__ Winit_c,
    const float* __restrict__ Whh)
{
    extern __shared__ __half smh[];
    __half* sW = smh;                 // [16][STRH]  gate-row weights
    __half* sH = smh + 16 * STRH;     // [64][STRH]  h (fp16)

    const int tid  = threadIdx.x;
    const int w    = tid >> 5;
    const int lane = tid & 31;
    const int l7   = lane & 7;
    const int r    = lane >> 2;       // 0..7
    const int q    = lane & 3;
    const int u0   = blockIdx.x * 4;

    const uint32_t sWb = smem_u32(sW);
    const uint32_t sHb = smem_u32(sH);
    // A fragment addressing (validated mapping from gemm_mma)
    const uint32_t aOff = (uint32_t)((l7 + ((lane >> 3) & 1) * 8) * (STRH * 2) + (lane >> 4) * 16);
    // B fragment addressing: one n-tile (8 batches), x4 covers k32
    const uint32_t bOff = (uint32_t)((w * 8 + l7) * (STRH * 2) + (lane >> 3) * 16);

    // ---- phase 0: sW rows 0-3 = Winit_h[u0+j], 4-7 = Winit_c[u0+j], 8-15 = 0
    for (int idx = tid; idx < 2048; idx += 256) {
        const int m = idx >> 7, c4 = idx & 127;
        __half2 p0 = __float2half2_rn(0.f), p1 = p0;
        if (m < 8) {
            const float* src = (m < 4) ? (Winit_h + (size_t)(u0 + m) * 512)
                                       : (Winit_c + (size_t)(u0 + m - 4) * 512);
            float4 v = *(const float4*)(src + c4 * 4);
            p0 = __floats2half2_rn(v.x, v.y);
            p1 = __floats2half2_rn(v.z, v.w);
        }
        *(__half2*)(sW + m * STRH + c4 * 4)     = p0;
        *(__half2*)(sW + m * STRH + c4 * 4 + 2) = p1;
    }
    // sH = fmean (fp32 -> fp16)
    for (int idx = tid; idx < 8192; idx += 256) {
        const int row = idx >> 7, c4 = idx & 127;
        float4 v = *(const float4*)(g_fmean + row * 512 + c4 * 4);
        *(__half2*)(sH + row * STRH + c4 * 4)     = __floats2half2_rn(v.x, v.y);
        *(__half2*)(sH + row * STRH + c4 * 4 + 2) = __floats2half2_rn(v.z, v.w);
    }
    __syncthreads();

    float acc[4] = {0.f, 0.f, 0.f, 0.f};
    #pragma unroll
    for (int kt2 = 0; kt2 < 16; kt2++) {
        uint32_t a0[4], a1[4], tb[4];
        ldm_x4(a0, sWb + aOff + kt2 * 64);
        ldm_x4(a1, sWb + aOff + kt2 * 64 + 32);
        ldm_x4(tb, sHb + bOff + kt2 * 64);
        uint32_t b0v[2] = {tb[0], tb[1]}, b1v[2] = {tb[2], tb[3]};
        mma_fp16(acc, a0, b0v);
        mma_fp16(acc, a1, b1v);
    }
    const int b0i = w * 8 + q * 2;
    float c2[2] = {0.f, 0.f};
    {
        const float cc0 = __shfl_xor_sync(0xffffffffu, acc[0], 16);
        const float cc1 = __shfl_xor_sync(0xffffffffu, acc[1], 16);
        if (lane < 16) {
            c2[0] = cc0; c2[1] = cc1;
            g_hb16[0][b0i * 512 + u0 + r]       = __float2half_rn(acc[0]);
            g_hb16[0][(b0i + 1) * 512 + u0 + r] = __float2half_rn(acc[1]);
        }
    }
    __syncthreads();   // phase-0 sW reads complete

    // ---- steady-state weights: sW row m = Whh[(m>>2)*512 + u0 + (m&3)]
    for (int idx = tid; idx < 2048; idx += 256) {
        const int m = idx >> 7, c4 = idx & 127;
        const int grow = (m >> 2) * 512 + u0 + (m & 3);
        float4 v = *(const float4*)(Whh + (size_t)grow * 512 + c4 * 4);
        *(__half2*)(sW + m * STRH + c4 * 4)     = __floats2half2_rn(v.x, v.y);
        *(__half2*)(sW + m * STRH + c4 * 4 + 2) = __floats2half2_rn(v.z, v.w);
    }

    // gpre columns for this thread's D coords
    const int m1 = r, m2 = r + 8;
    const int col1 = (m1 >> 2) * 512 + u0 + (m1 & 3);
    const int col2 = (m2 >> 2) * 512 + u0 + (m2 & 3);
    float gp[4];
    {
        const float* gr = g_gpre;
        gp[0] = gr[(size_t)b0i * G4 + col1];
        gp[1] = gr[(size_t)(b0i + 1) * G4 + col1];
        gp[2] = gr[(size_t)b0i * G4 + col2];
        gp[3] = gr[(size_t)(b0i + 1) * G4 + col2];
    }
    __threadfence();
    gbar();

    for (int t = 0; t < TT; t++) {
        // refill sH from ping-pong fp16 buffer
        {
            const uint4* src = (const uint4*)g_hb16[t & 1];
            for (int idx = tid; idx < 4096; idx += 256) {
                const int row = idx >> 6, c8 = idx & 63;
                *(uint4*)(sH + row * STRH + c8 * 8) = src[row * 64 + c8];
            }
        }
        __syncthreads();

        acc[0] = gp[0]; acc[1] = gp[1]; acc[2] = gp[2]; acc[3] = gp[3];
        #pragma unroll
        for (int kt2 = 0; kt2 < 16; kt2++) {
            uint32_t a0[4], a1[4], tb[4];
            ldm_x4(a0, sWb + aOff + kt2 * 64);
            ldm_x4(a1, sWb + aOff + kt2 * 64 + 32);
            ldm_x4(tb, sHb + bOff + kt2 * 64);
            uint32_t b0v[2] = {tb[0], tb[1]}, b1v[2] = {tb[2], tb[3]};
            mma_fp16(acc, a0, b0v);
            mma_fp16(acc, a1, b1v);
        }

        // lanes<16 hold (i,g) rows; partner lane+16 holds (f,o) for same j
        const float f0 = __shfl_xor_sync(0xffffffffu, acc[0], 16);
        const float f1 = __shfl_xor_sync(0xffffffffu, acc[1], 16);
        const float o0 = __shfl_xor_sync(0xffffffffu, acc[2], 16);
        const float o1 = __shfl_xor_sync(0xffffffffu, acc[3], 16);
        if (lane < 16) {
            #pragma unroll
            for (int ii = 0; ii < 2; ii++) {
                const float gi = acc[ii];
                const float gg = acc[2 + ii];
                const float gf = ii ? f1 : f0;
                const float go = ii ? o1 : o0;
                const float si = 1.f / (1.f + __expf(-gi));
                const float sf = 1.f / (1.f + __expf(-gf));
                const float so = 1.f / (1.f + __expf(-go));
                c2[ii] = sf * c2[ii] + si * tanhf(gg);
                const float hnew = so * tanhf(c2[ii]);
                const __half hh = __float2half_rn(hnew);
                const int b = b0i + ii;
                g_hb16[(t + 1) & 1][b * 512 + u0 + r] = hh;
                g_hall[(size_t)(t * 64 + b) * 512 + u0 + r] = hh;
            }
        }

        if (t < TT - 1) {
            const float* gr = g_gpre + (size_t)(t + 1) * BB * G4;
            gp[0] = gr[(size_t)b0i * G4 + col1];
            gp[1] = gr[(size_t)(b0i + 1) * G4 + col1];
            gp[2] = gr[(size_t)b0i * G4 + col2];
            gp[3] = gr[(size_t)(b0i + 1) * G4 + col2];
            __threadfence();
            gbar();
        }
    }
}

// ---------------- fused log_softmax + softmax over V=10000 (float4) ----------------
__global__ void __launch_bounds__(256) softmax_kernel(float* __restrict__ out) {
    const int r = blockIdx.x;
    const float4* x4 = (const float4*)(g_words + (size_t)r * VOC);
    float4* ols = (float4*)(out + (size_t)r * VOC);
    float4* osm = (float4*)(out + (size_t)TT * BB * VOC + (size_t)r * VOC);

    float m = -3.0e38f, s = 0.f;
    for (int i = threadIdx.x; i < VOC / 4; i += 256) {
        float4 v = x4[i];
        float m4 = fmaxf(fmaxf(v.x, v.y), fmaxf(v.z, v.w));
        float mn = fmaxf(m, m4);
        s = s * __expf(m - mn) + __expf(v.x - mn) + __expf(v.y - mn)
                               + __expf(v.z - mn) + __expf(v.w - mn);
        m = mn;
    }
    #pragma unroll
    for (int o = 16; o; o >>= 1) {
        float m2 = __shfl_down_sync(0xffffffffu, m, o);
        float s2 = __shfl_down_sync(0xffffffffu, s, o);
        float mx = fmaxf(m, m2);
        s = s * __expf(m - mx) + s2 * __expf(m2 - mx);
        m = mx;
    }
    __shared__ float sm[8], ss[8];
    __shared__ float bM, bS;
    const int wid = threadIdx.x >> 5, lane = threadIdx.x & 31;
    if (!lane) { sm[wid] = m; ss[wid] = s; }
    __syncthreads();
    if (threadIdx.x == 0) {
        float M = sm[0], S = ss[0];
        #pragma unroll
        for (int i = 1; i < 8; i++) {
            float mx = fmaxf(M, sm[i]);
            S = S * __expf(M - mx) + ss[i] * __expf(sm[i] - mx);
            M = mx;
        }
        bM = M; bS = S;
    }
    __syncthreads();
    const float M = bM;
    const float Sinv = 1.f / bS;
    const float lg = __logf(bS);
    for (int i = threadIdx.x; i < VOC / 4; i += 256) {
        float4 v = x4[i];
        float4 l4, p4;
        l4.x = v.x - M - lg; p4.x = __expf(v.x - M) * Sinv;
        l4.y = v.y - M - lg; p4.y = __expf(v.y - M) * Sinv;
        l4.z = v.z - M - lg; p4.z = __expf(v.z - M) * Sinv;
        l4.w = v.w - M - lg; p4.w = __expf(v.w - M) * Sinv;
        ols[i] = l4;
        osm[i] = p4;
    }
}

// ---------------- launch ----------------
extern "C" void kernel_launch(void* const* d_in, const int* in_sizes, int n_in,
                              void* d_out, int out_size) {
    (void)in_sizes; (void)n_in; (void)out_size;
    const float* features = (const float*)d_in[0];
    const int*   captions = (const int*)  d_in[1];
    const float* W_init_h = (const float*)d_in[2];
    const float* W_init_c = (const float*)d_in[3];
    const float* W_av     = (const float*)d_in[4];
    // d_in[5] b_av, d_in[6] W_ah, d_in[7] b_ah : dead (softmax shift-invariance)
    const float* embed    = (const float*)d_in[8];
    const float* W_ih     = (const float*)d_in[9];
    const float* W_hh     = (const float*)d_in[10];
    const float* b_ih     = (const float*)d_in[11];
    const float* b_hh     = (const float*)d_in[12];
    const float* W_out    = (const float*)d_in[13];
    const float* b_out    = (const float*)d_in[14];
    float* out = (float*)d_out;

    float *gpre, *words;
    __half *wout16, *wih16, *a16, *hall;
    cudaGetSymbolAddress((void**)&gpre,   g_gpre);
    cudaGetSymbolAddress((void**)&words,  g_words);
    cudaGetSymbolAddress((void**)&wout16, g_Wout16);
    cudaGetSymbolAddress((void**)&wih16,  g_Wih16);
    cudaGetSymbolAddress((void**)&a16,    g_A16);
    cudaGetSymbolAddress((void**)&hall,   g_hall);

    const int LSTM_SMEM = (16 + 64) * STRH * 2;       // 83200 B
    cudaFuncSetAttribute(lstm_kernel, cudaFuncAttributeMaxDynamicSharedMemorySize, LSTM_SMEM);
    const int GEMM_SMEM = 2 * STAGEB;                 // 40960 B
    cudaFuncSetAttribute(gemm_mma, cudaFuncAttributeMaxDynamicSharedMemorySize, GEMM_SMEM);

    // 1-3) attention weights, ctx+fmean, rowmap
    attn_logits<<<BB, 256>>>(features, W_av);
    attn_ctx<<<dim3(BB, 4), 128>>>(features);
    rowmap_kernel<<<(TT * BB + 255) / 256, 256>>>(captions);

    // 4-5) concat A + W_ih conversion
    cvt_concat8<<<(TT * BB * 1024 / 8 + 255) / 256, 256>>>(embed);
    cvt_hi8<<<(G4 * 1024 / 8 + 255) / 256, 256>>>(W_ih, wih16, G4 * 1024);

    // 6) gpre = [ctx|emb] @ W_ih^T + b_ih + b_hh   (K=1024)
    gemm_mma<<<dim3(TT * BB / 128, G4 / 128), 256, GEMM_SMEM>>>(
        a16, wih16, gpre, G4, G4, 1024, b_ih, b_hh);

    // 7) persistent HMMA LSTM
    lstm_kernel<<<NBLK, 256, LSTM_SMEM>>>(W_init_h, W_init_c, W_hh);

    // 8) W_out conversion
    cvt_hi8<<<(VOC * 512 / 8 + 255) / 256, 256>>>(W_out, wout16, VOC * 512);

    // 9) words = hall @ W_out^T + b_out (K=512)
    gemm_mma<<<dim3(TT * BB / 128, (VOC + 127) / 128), 256, GEMM_SMEM>>>(
        hall, wout16, words, VOC, VOC, 512, b_out, nullptr);

    // 10) fused log_softmax + softmax
    softmax_kernel<<<TT * BB, 256>>>(out);
}

// round 10
// speedup vs baseline: 4.7584x; 1.1314x over previous
#include <cuda_runtime.h>
#include <cuda_fp16.h>
#include <cstdint>
#include <cstddef>

#define TT   20
#define BB   64
#define NNF  196
#define VOC  10000
#define G4   2048
#define NBLK 128          // persistent LSTM grid

// ---------------- static device scratch ----------------
__device__ float g_fmean[BB * 512];
__device__ float g_ctx  [BB * 512];
__device__ float g_attl [BB * NNF];
__device__ float g_attw [BB * NNF];
__device__ float g_gpre [TT * BB * G4];
__device__ float g_words[TT * BB * VOC];
__device__ unsigned long long g_bar;   // monotonic across replays

__device__ __half g_Wout16[VOC * 512];
__device__ __half g_Wih16 [G4 * 1024];
__device__ __half g_A16   [TT * BB * 1024];
__device__ __half g_hall  [TT * BB * 512];
__device__ __half g_hb16  [2][BB * 512];

// ---------------- helpers ----------------
__device__ __forceinline__ uint32_t smem_u32(const void* p) {
    uint32_t a;
    asm("{ .reg .u64 t; cvta.to.shared.u64 t, %1; cvt.u32.u64 %0, t; }"
        : "=r"(a) : "l"(p));
    return a;
}
__device__ __forceinline__ void ldm_x4(uint32_t* r, uint32_t addr) {
    asm volatile("ldmatrix.sync.aligned.m8n8.x4.shared.b16 {%0,%1,%2,%3}, [%4];"
                 : "=r"(r[0]), "=r"(r[1]), "=r"(r[2]), "=r"(r[3]) : "r"(addr));
}
__device__ __forceinline__ void mma_fp16(float* d, const uint32_t* a, const uint32_t* b) {
    asm volatile(
        "mma.sync.aligned.m16n8k16.row.col.f32.f16.f16.f32 "
        "{%0,%1,%2,%3}, {%4,%5,%6,%7}, {%8,%9}, {%0,%1,%2,%3};"
        : "+f"(d[0]), "+f"(d[1]), "+f"(d[2]), "+f"(d[3])
        : "r"(a[0]), "r"(a[1]), "r"(a[2]), "r"(a[3]), "r"(b[0]), "r"(b[1]));
}
__device__ __forceinline__ void cpa16(uint32_t dst, const void* src, int srcsz) {
    asm volatile("cp.async.cg.shared.global [%0], [%1], 16, %2;"
                 :: "r"(dst), "l"(src), "r"(srcsz));
}
__device__ __forceinline__ void cpa_commit() {
    asm volatile("cp.async.commit_group;");
}
template<int NG> __device__ __forceinline__ void cpa_wait() {
    asm volatile("cp.async.wait_group %0;" :: "n"(NG));
}

// ============ single-pass fp16 GEMM: C[m,n] = sum_k A[m,k]*B[n,k] ==========
// BM=128, BN=128, BK=32; 8 warps (4x2); warp tile 32x64.
#define ASTR 40                         // padded fp16 row stride (80B)
#define BUFB (128 * ASTR * 2)           // one operand buffer: 10240 bytes
#define STAGEB (2 * BUFB)               // A|B per stage: 20480 bytes

__global__ void __launch_bounds__(256) gemm_mma(
    const __half* __restrict__ A, const __half* __restrict__ B,
    float* __restrict__ C, int N, int ldc, int K,
    const float* __restrict__ bias0, const float* __restrict__ bias1)
{
    extern __shared__ __align__(16) __half dsm[];
    const uint32_t smb = smem_u32(dsm);

    const int tid  = threadIdx.x;
    const int lane = tid & 31;
    const int w    = tid >> 5;
    const int wm   = w >> 1;
    const int wn   = w & 1;
    const int m0   = blockIdx.x * 128;
    const int n0   = blockIdx.y * 128;
    const int mbase = wm * 32;
    const int nbase = wn * 64;
    const int g = lane >> 2;
    const int q = lane & 3;

    const int i0 = tid, i1 = tid + 256;
    const int r0s = i0 >> 2, k0s = (i0 & 3) * 8;
    const int r1s = i1 >> 2, k1s = (i1 & 3) * 8;
    const int bsz0 = (n0 + r0s) < N ? 16 : 0;
    const int bsz1 = (n0 + r1s) < N ? 16 : 0;
    const uint32_t d0 = (uint32_t)(r0s * ASTR + k0s) * 2;
    const uint32_t d1 = (uint32_t)(r1s * ASTR + k1s) * 2;

    const int l7 = lane & 7;
    const uint32_t aRow = mbase + l7 + ((lane >> 3) & 1) * 8;
    const uint32_t aKof = (lane >> 4) * 16;
    const uint32_t bRow = nbase + l7 + (lane >> 4) * 8;
    const uint32_t bKof = ((lane >> 3) & 1) * 16;

    float acc[2][8][4];
    #pragma unroll
    for (int mt = 0; mt < 2; mt++)
        #pragma unroll
        for (int nt = 0; nt < 8; nt++)
            #pragma unroll
            for (int r = 0; r < 4; r++) acc[mt][nt][r] = 0.f;

    const int nk = K / 32;

    auto load_stage = [&](int kt, int s) {
        const int k0 = kt * 32;
        const uint32_t sb = smb + (uint32_t)s * STAGEB;
        cpa16(sb + d0,        A + (size_t)(m0 + r0s) * K + k0 + k0s, 16);
        cpa16(sb + d1,        A + (size_t)(m0 + r1s) * K + k0 + k1s, 16);
        cpa16(sb + BUFB + d0, B + (size_t)(n0 + r0s) * K + k0 + k0s, bsz0);
        cpa16(sb + BUFB + d1, B + (size_t)(n0 + r1s) * K + k0 + k1s, bsz1);
        cpa_commit();
    };

    load_stage(0, 0);

    for (int kt = 0; kt < nk; kt++) {
        if (kt + 1 < nk) load_stage(kt + 1, (kt + 1) & 1);
        if (kt + 1 < nk) cpa_wait<1>(); else cpa_wait<0>();
        __syncthreads();

        const uint32_t sb = smb + (uint32_t)(kt & 1) * STAGEB;
        const uint32_t bA = sb, bB = sb + BUFB;

        #pragma unroll
        for (int kk = 0; kk < 2; kk++) {
            const uint32_t kb = kk * 32;
            uint32_t ah[2][4];
            #pragma unroll
            for (int mt = 0; mt < 2; mt++) {
                const uint32_t ro = (aRow + mt * 16) * (ASTR * 2) + kb + aKof;
                ldm_x4(ah[mt], bA + ro);
            }
            #pragma unroll
            for (int np = 0; np < 4; np++) {
                const uint32_t ro = (bRow + np * 16) * (ASTR * 2) + kb + bKof;
                uint32_t tb[4];
                ldm_x4(tb, bB + ro);
                uint32_t bh0[2] = {tb[0], tb[1]}, bh1[2] = {tb[2], tb[3]};
                #pragma unroll
                for (int mt = 0; mt < 2; mt++) {
                    mma_fp16(acc[mt][np * 2 + 0], ah[mt], bh0);
                    mma_fp16(acc[mt][np * 2 + 1], ah[mt], bh1);
                }
            }
        }
        __syncthreads();
    }

    #pragma unroll
    for (int mt = 0; mt < 2; mt++) {
        #pragma unroll
        for (int nt = 0; nt < 8; nt++) {
            const int n = n0 + nbase + nt * 8 + q * 2;
            if (n < N) {
                #pragma unroll
                for (int half = 0; half < 2; half++) {
                    const int m = m0 + mbase + mt * 16 + g + half * 8;
                    float v0 = acc[mt][nt][half * 2 + 0];
                    float v1 = acc[mt][nt][half * 2 + 1];
                    if (bias0) { v0 += bias0[n]; v1 += bias0[n + 1]; }
                    if (bias1) { v0 += bias1[n]; v1 += bias1[n + 1]; }
                    *(float2*)(C + (size_t)m * ldc + n) = make_float2(v0, v1);
                }
            }
        }
    }
}

// ---------------- fp32 -> fp16, 8 elems/thread ----------------
__global__ void __launch_bounds__(256) cvt_hi8(
    const float* __restrict__ src, __half* __restrict__ hi, int total)
{
    const int i = (blockIdx.x * 256 + threadIdx.x) * 8;
    if (i < total) {
        float4 x0 = *(const float4*)(src + i);
        float4 x1 = *(const float4*)(src + i + 4);
        float xs[8] = {x0.x, x0.y, x0.z, x0.w, x1.x, x1.y, x1.z, x1.w};
        __half h8[8];
        #pragma unroll
        for (int j = 0; j < 8; j++) h8[j] = __float2half_rn(xs[j]);
        *(uint4*)(hi + i) = *(const uint4*)h8;
    }
}

// ---------------- concat A = [ctx(b) | embed(tok)] fp16 (rowmap inline) ------
__global__ void __launch_bounds__(256) cvt_concat8(const float* __restrict__ embed,
                                                   const int* __restrict__ captions) {
    const int i = (blockIdx.x * 256 + threadIdx.x) * 8;
    if (i < TT * BB * 1024) {
        const int r = i >> 10, k = i & 1023;
        const int b = r & 63, t = r >> 6;
        const float* sp;
        if (k < 512) {
            sp = g_ctx + b * 512 + k;
        } else {
            const int tok = captions[b * TT + t];
            sp = embed + (size_t)tok * 512 + (k - 512);
        }
        float4 x0 = *(const float4*)sp;
        float4 x1 = *(const float4*)(sp + 4);
        float xs[8] = {x0.x, x0.y, x0.z, x0.w, x1.x, x1.y, x1.z, x1.w};
        __half h8[8];
        #pragma unroll
        for (int j = 0; j < 8; j++) h8[j] = __float2half_rn(xs[j]);
        *(uint4*)(g_A16 + i) = *(const uint4*)h8;
    }
}

// ---------------- attention logits (parallel over 448 blocks) ----------------
__global__ void __launch_bounds__(256) attn_dot(const float* __restrict__ features,
                                                const float* __restrict__ W_av) {
    const int b   = blockIdx.x;
    const int n0  = blockIdx.y * 28;
    __shared__ float sW[512];
    const int tid = threadIdx.x;
    const int wid = tid >> 5, lane = tid & 31;
    for (int i = tid; i < 512; i += 256) sW[i] = W_av[i];
    __syncthreads();

    const float* fb = features + (size_t)b * NNF * 512;
    for (int n = n0 + wid; n < n0 + 28 && n < NNF; n += 8) {
        const float* fr = fb + (size_t)n * 512;
        float s0 = 0.f, s1 = 0.f, s2 = 0.f, s3 = 0.f;
        #pragma unroll
        for (int i = 0; i < 4; i++) {
            const int o = lane + i * 128;
            s0 = fmaf(fr[o],      sW[o],      s0);
            s1 = fmaf(fr[o + 32], sW[o + 32], s1);
            s2 = fmaf(fr[o + 64], sW[o + 64], s2);
            s3 = fmaf(fr[o + 96], sW[o + 96], s3);
        }
        float s = (s0 + s1) + (s2 + s3);
        #pragma unroll
        for (int o = 16; o; o >>= 1) s += __shfl_down_sync(0xffffffffu, s, o);
        if (!lane) g_attl[b * NNF + n] = s;
    }
}

// ---------------- softmax over N=196 -> weights ----------------
__global__ void __launch_bounds__(256) attn_wsm() {
    const int b = blockIdx.x;
    __shared__ float sA[NNF];
    __shared__ float sred[8];
    __shared__ float s_max, s_inv;
    const int tid = threadIdx.x;
    const int wid = tid >> 5, lane = tid & 31;

    for (int n = tid; n < NNF; n += 256) sA[n] = g_attl[b * NNF + n];
    __syncthreads();

    float m = -3.0e38f;
    for (int n = tid; n < NNF; n += 256) m = fmaxf(m, sA[n]);
    #pragma unroll
    for (int o = 16; o; o >>= 1) m = fmaxf(m, __shfl_down_sync(0xffffffffu, m, o));
    if (!lane) sred[wid] = m;
    __syncthreads();
    if (tid == 0) {
        float mm = sred[0];
        #pragma unroll
        for (int i = 1; i < 8; i++) mm = fmaxf(mm, sred[i]);
        s_max = mm;
    }
    __syncthreads();
    const float mm = s_max;

    float s = 0.f;
    for (int n = tid; n < NNF; n += 256) { float e = __expf(sA[n] - mm); sA[n] = e; s += e; }
    #pragma unroll
    for (int o = 16; o; o >>= 1) s += __shfl_down_sync(0xffffffffu, s, o);
    if (!lane) sred[wid] = s;
    __syncthreads();
    if (tid == 0) {
        float ss = 0.f;
        #pragma unroll
        for (int i = 0; i < 8; i++) ss += sred[i];
        s_inv = 1.f / ss;
    }
    __syncthreads();
    const float inv = s_inv;
    for (int n = tid; n < NNF; n += 256) g_attw[b * NNF + n] = sA[n] * inv;
}

// ---------------- ctx + fmean (wide, ILP) ----------------
__global__ void __launch_bounds__(128) attn_ctx(const float* __restrict__ features) {
    const int b = blockIdx.x;
    const int v = blockIdx.y * 128 + threadIdx.x;
    __shared__ float sw[NNF];
    for (int i = threadIdx.x; i < NNF; i += 128) sw[i] = g_attw[b * NNF + i];
    __syncthreads();

    const float* fp = features + (size_t)b * NNF * 512 + v;
    float ac0 = 0.f, ac1 = 0.f, ac2 = 0.f, ac3 = 0.f;
    float am0 = 0.f, am1 = 0.f, am2 = 0.f, am3 = 0.f;
    #pragma unroll 4
    for (int n = 0; n < NNF; n += 4) {
        float f0 = fp[(size_t)(n + 0) * 512];
        float f1 = fp[(size_t)(n + 1) * 512];
        float f2 = fp[(size_t)(n + 2) * 512];
        float f3 = fp[(size_t)(n + 3) * 512];
        ac0 = fmaf(sw[n + 0], f0, ac0); am0 += f0;
        ac1 = fmaf(sw[n + 1], f1, ac1); am1 += f1;
        ac2 = fmaf(sw[n + 2], f2, ac2); am2 += f2;
        ac3 = fmaf(sw[n + 3], f3, ac3); am3 += f3;
    }
    g_ctx  [b * 512 + v] = (ac0 + ac1) + (ac2 + ac3);
    g_fmean[b * 512 + v] = ((am0 + am1) + (am2 + am3)) * (1.f / (float)NNF);
}

// ================= persistent HMMA LSTM (phase0 + 20 steps, 1 launch) =========
// release-arrive / acquire-spin barrier (no threadfence on the critical path)
__device__ __forceinline__ void gbar() {
    __syncthreads();
    if (threadIdx.x == 0) {
        unsigned long long old;
        asm volatile("atom.release.gpu.global.add.u64 %0, [%1], %2;"
                     : "=l"(old) : "l"(&g_bar), "l"(1ULL) : "memory");
        unsigned long long tgt = old - (old & (unsigned long long)(NBLK - 1)) + (unsigned long long)NBLK;
        unsigned long long cur;
        do {
            asm volatile("ld.global.acquire.gpu.u64 %0, [%1];" : "=l"(cur) : "l"(&g_bar));
        } while (cur < tgt);
    }
    __syncthreads();
}

#define STRH 520   // fp16 row stride for sW/sH (1040 B, conflict-free ldmatrix)

__global__ void __launch_bounds__(256, 1) lstm_kernel(
    const float* __restrict__ Winit_h, const float* __restrict__ Winit_c,
    const float* __restrict__ Whh)
{
    extern __shared__ __half smh[];
    __half* sW = smh;                 // [16][STRH]  gate-row weights
    __half* sH = smh + 16 * STRH;     // [64][STRH]  h (fp16)

    const int tid  = threadIdx.x;
    const int w    = tid >> 5;
    const int lane = tid & 31;
    const int l7   = lane & 7;
    const int r    = lane >> 2;       // 0..7
    const int q    = lane & 3;
    const int u0   = blockIdx.x * 4;

    const uint32_t sWb = smem_u32(sW);
    const uint32_t sHb = smem_u32(sH);
    const uint32_t aOff = (uint32_t)((l7 + ((lane >> 3) & 1) * 8) * (STRH * 2) + (lane >> 4) * 16);
    const uint32_t bOff = (uint32_t)((w * 8 + l7) * (STRH * 2) + (lane >> 3) * 16);

    // ---- phase 0: sW rows 0-3 = Winit_h[u0+j], 4-7 = Winit_c[u0+j], 8-15 = 0
    for (int idx = tid; idx < 2048; idx += 256) {
        const int m = idx >> 7, c4 = idx & 127;
        __half2 p0 = __float2half2_rn(0.f), p1 = p0;
        if (m < 8) {
            const float* src = (m < 4) ? (Winit_h + (size_t)(u0 + m) * 512)
                                       : (Winit_c + (size_t)(u0 + m - 4) * 512);
            float4 v = *(const float4*)(src + c4 * 4);
            p0 = __floats2half2_rn(v.x, v.y);
            p1 = __floats2half2_rn(v.z, v.w);
        }
        *(__half2*)(sW + m * STRH + c4 * 4)     = p0;
        *(__half2*)(sW + m * STRH + c4 * 4 + 2) = p1;
    }
    for (int idx = tid; idx < 8192; idx += 256) {
        const int row = idx >> 7, c4 = idx & 127;
        float4 v = *(const float4*)(g_fmean + row * 512 + c4 * 4);
        *(__half2*)(sH + row * STRH + c4 * 4)     = __floats2half2_rn(v.x, v.y);
        *(__half2*)(sH + row * STRH + c4 * 4 + 2) = __floats2half2_rn(v.z, v.w);
    }
    __syncthreads();

    float acc[4] = {0.f, 0.f, 0.f, 0.f};
    #pragma unroll
    for (int kt2 = 0; kt2 < 16; kt2++) {
        uint32_t a0[4], a1[4], tb[4];
        ldm_x4(a0, sWb + aOff + kt2 * 64);
        ldm_x4(a1, sWb + aOff + kt2 * 64 + 32);
        ldm_x4(tb, sHb + bOff + kt2 * 64);
        uint32_t b0v[2] = {tb[0], tb[1]}, b1v[2] = {tb[2], tb[3]};
        mma_fp16(acc, a0, b0v);
        mma_fp16(acc, a1, b1v);
    }
    const int b0i = w * 8 + q * 2;
    float c2[2] = {0.f, 0.f};
    {
        const float cc0 = __shfl_xor_sync(0xffffffffu, acc[0], 16);
        const float cc1 = __shfl_xor_sync(0xffffffffu, acc[1], 16);
        if (lane < 16) {
            c2[0] = cc0; c2[1] = cc1;
            g_hb16[0][b0i * 512 + u0 + r]       = __float2half_rn(acc[0]);
            g_hb16[0][(b0i + 1) * 512 + u0 + r] = __float2half_rn(acc[1]);
        }
    }
    __syncthreads();

    // ---- steady-state weights: sW row m = Whh[(m>>2)*512 + u0 + (m&3)]
    for (int idx = tid; idx < 2048; idx += 256) {
        const int m = idx >> 7, c4 = idx & 127;
        const int grow = (m >> 2) * 512 + u0 + (m & 3);
        float4 v = *(const float4*)(Whh + (size_t)grow * 512 + c4 * 4);
        *(__half2*)(sW + m * STRH + c4 * 4)     = __floats2half2_rn(v.x, v.y);
        *(__half2*)(sW + m * STRH + c4 * 4 + 2) = __floats2half2_rn(v.z, v.w);
    }

    const int m1 = r, m2 = r + 8;
    const int col1 = (m1 >> 2) * 512 + u0 + (m1 & 3);
    const int col2 = (m2 >> 2) * 512 + u0 + (m2 & 3);
    float gp[4];
    {
        const float* gr = g_gpre;
        gp[0] = gr[(size_t)b0i * G4 + col1];
        gp[1] = gr[(size_t)(b0i + 1) * G4 + col1];
        gp[2] = gr[(size_t)b0i * G4 + col2];
        gp[3] = gr[(size_t)(b0i + 1) * G4 + col2];
    }
    gbar();

    for (int t = 0; t < TT; t++) {
        {
            const uint4* src = (const uint4*)g_hb16[t & 1];
            for (int idx = tid; idx < 4096; idx += 256) {
                const int row = idx >> 6, c8 = idx & 63;
                *(uint4*)(sH + row * STRH + c8 * 8) = src[row * 64 + c8];
            }
        }
        __syncthreads();

        acc[0] = gp[0]; acc[1] = gp[1]; acc[2] = gp[2]; acc[3] = gp[3];
        #pragma unroll
        for (int kt2 = 0; kt2 < 16; kt2++) {
            uint32_t a0[4], a1[4], tb[4];
            ldm_x4(a0, sWb + aOff + kt2 * 64);
            ldm_x4(a1, sWb + aOff + kt2 * 64 + 32);
            ldm_x4(tb, sHb + bOff + kt2 * 64);
            uint32_t b0v[2] = {tb[0], tb[1]}, b1v[2] = {tb[2], tb[3]};
            mma_fp16(acc, a0, b0v);
            mma_fp16(acc, a1, b1v);
        }

        const float f0 = __shfl_xor_sync(0xffffffffu, acc[0], 16);
        const float f1 = __shfl_xor_sync(0xffffffffu, acc[1], 16);
        const float o0 = __shfl_xor_sync(0xffffffffu, acc[2], 16);
        const float o1 = __shfl_xor_sync(0xffffffffu, acc[3], 16);
        if (lane < 16) {
            #pragma unroll
            for (int ii = 0; ii < 2; ii++) {
                const float gi = acc[ii];
                const float gg = acc[2 + ii];
                const float gf = ii ? f1 : f0;
                const float go = ii ? o1 : o0;
                const float si = 1.f / (1.f + __expf(-gi));
                const float sf = 1.f / (1.f + __expf(-gf));
                const float so = 1.f / (1.f + __expf(-go));
                c2[ii] = sf * c2[ii] + si * tanhf(gg);
                const float hnew = so * tanhf(c2[ii]);
                const __half hh = __float2half_rn(hnew);
                const int b = b0i + ii;
                g_hb16[(t + 1) & 1][b * 512 + u0 + r] = hh;
                g_hall[(size_t)(t * 64 + b) * 512 + u0 + r] = hh;
            }
        }

        if (t < TT - 1) {
            const float* gr = g_gpre + (size_t)(t + 1) * BB * G4;
            gp[0] = gr[(size_t)b0i * G4 + col1];
            gp[1] = gr[(size_t)(b0i + 1) * G4 + col1];
            gp[2] = gr[(size_t)b0i * G4 + col2];
            gp[3] = gr[(size_t)(b0i + 1) * G4 + col2];
            gbar();
        }
    }
}

// ---------------- fused log_softmax + softmax over V=10000 (float4) ----------------
__global__ void __launch_bounds__(256) softmax_kernel(float* __restrict__ out) {
    const int r = blockIdx.x;
    const float4* x4 = (const float4*)(g_words + (size_t)r * VOC);
    float4* ols = (float4*)(out + (size_t)r * VOC);
    float4* osm = (float4*)(out + (size_t)TT * BB * VOC + (size_t)r * VOC);

    float m = -3.0e38f, s = 0.f;
    for (int i = threadIdx.x; i < VOC / 4; i += 256) {
        float4 v = x4[i];
        float m4 = fmaxf(fmaxf(v.x, v.y), fmaxf(v.z, v.w));
        float mn = fmaxf(m, m4);
        s = s * __expf(m - mn) + __expf(v.x - mn) + __expf(v.y - mn)
                               + __expf(v.z - mn) + __expf(v.w - mn);
        m = mn;
    }
    #pragma unroll
    for (int o = 16; o; o >>= 1) {
        float m2 = __shfl_down_sync(0xffffffffu, m, o);
        float s2 = __shfl_down_sync(0xffffffffu, s, o);
        float mx = fmaxf(m, m2);
        s = s * __expf(m - mx) + s2 * __expf(m2 - mx);
        m = mx;
    }
    __shared__ float sm[8], ss[8];
    __shared__ float bM, bS;
    const int wid = threadIdx.x >> 5, lane = threadIdx.x & 31;
    if (!lane) { sm[wid] = m; ss[wid] = s; }
    __syncthreads();
    if (threadIdx.x == 0) {
        float M = sm[0], S = ss[0];
        #pragma unroll
        for (int i = 1; i < 8; i++) {
            float mx = fmaxf(M, sm[i]);
            S = S * __expf(M - mx) + ss[i] * __expf(sm[i] - mx);
            M = mx;
        }
        bM = M; bS = S;
    }
    __syncthreads();
    const float M = bM;
    const float Sinv = 1.f / bS;
    const float lg = __logf(bS);
    for (int i = threadIdx.x; i < VOC / 4; i += 256) {
        float4 v = x4[i];
        float4 l4, p4;
        l4.x = v.x - M - lg; p4.x = __expf(v.x - M) * Sinv;
        l4.y = v.y - M - lg; p4.y = __expf(v.y - M) * Sinv;
        l4.z = v.z - M - lg; p4.z = __expf(v.z - M) * Sinv;
        l4.w = v.w - M - lg; p4.w = __expf(v.w - M) * Sinv;
        ols[i] = l4;
        osm[i] = p4;
    }
}

// ---------------- launch ----------------
extern "C" void kernel_launch(void* const* d_in, const int* in_sizes, int n_in,
                              void* d_out, int out_size) {
    (void)in_sizes; (void)n_in; (void)out_size;
    const float* features = (const float*)d_in[0];
    const int*   captions = (const int*)  d_in[1];
    const float* W_init_h = (const float*)d_in[2];
    const float* W_init_c = (const float*)d_in[3];
    const float* W_av     = (const float*)d_in[4];
    // d_in[5] b_av, d_in[6] W_ah, d_in[7] b_ah : dead (softmax shift-invariance)
    const float* embed    = (const float*)d_in[8];
    const float* W_ih     = (const float*)d_in[9];
    const float* W_hh     = (const float*)d_in[10];
    const float* b_ih     = (const float*)d_in[11];
    const float* b_hh     = (const float*)d_in[12];
    const float* W_out    = (const float*)d_in[13];
    const float* b_out    = (const float*)d_in[14];
    float* out = (float*)d_out;

    float *gpre, *words;
    __half *wout16, *wih16, *a16, *hall;
    cudaGetSymbolAddress((void**)&gpre,   g_gpre);
    cudaGetSymbolAddress((void**)&words,  g_words);
    cudaGetSymbolAddress((void**)&wout16, g_Wout16);
    cudaGetSymbolAddress((void**)&wih16,  g_Wih16);
    cudaGetSymbolAddress((void**)&a16,    g_A16);
    cudaGetSymbolAddress((void**)&hall,   g_hall);

    // lazy one-time setup (outside graph capture: first call is the correctness run)
    static bool init_done = false;
    static cudaStream_t sB;
    static cudaEvent_t evFork, evWout;
    if (!init_done) {
        const int LSTM_SMEM0 = (16 + 64) * STRH * 2;
        cudaFuncSetAttribute(lstm_kernel, cudaFuncAttributeMaxDynamicSharedMemorySize, LSTM_SMEM0);
        cudaFuncSetAttribute(gemm_mma, cudaFuncAttributeMaxDynamicSharedMemorySize, 2 * STAGEB);
        cudaStreamCreateWithFlags(&sB, cudaStreamNonBlocking);
        cudaEventCreateWithFlags(&evFork, cudaEventDisableTiming);
        cudaEventCreateWithFlags(&evWout, cudaEventDisableTiming);
        init_done = true;
    }
    const int LSTM_SMEM = (16 + 64) * STRH * 2;       // 83200 B
    const int GEMM_SMEM = 2 * STAGEB;                 // 40960 B

    // fork: W_out conversion runs concurrently with the attention/gpre/LSTM chain
    cudaEventRecord(evFork, 0);
    cudaStreamWaitEvent(sB, evFork, 0);
    cvt_hi8<<<(VOC * 512 / 8 + 255) / 256, 256, 0, sB>>>(W_out, wout16, VOC * 512);
    cudaEventRecord(evWout, sB);

    // attention: logits (448 blocks), softmax weights, ctx+fmean
    attn_dot<<<dim3(BB, 7), 256>>>(features, W_av);
    attn_wsm<<<BB, 256>>>();
    attn_ctx<<<dim3(BB, 4), 128>>>(features);

    // concat A (rowmap inline) + W_ih conversion
    cvt_concat8<<<(TT * BB * 1024 / 8 + 255) / 256, 256>>>(embed, captions);
    cvt_hi8<<<(G4 * 1024 / 8 + 255) / 256, 256>>>(W_ih, wih16, G4 * 1024);

    // gpre = [ctx|emb] @ W_ih^T + b_ih + b_hh   (K=1024)
    gemm_mma<<<dim3(TT * BB / 128, G4 / 128), 256, GEMM_SMEM>>>(
        a16, wih16, gpre, G4, G4, 1024, b_ih, b_hh);

    // persistent HMMA LSTM
    lstm_kernel<<<NBLK, 256, LSTM_SMEM>>>(W_init_h, W_init_c, W_hh);

    // join W_out conversion, then words = hall @ W_out^T + b_out (K=512)
    cudaStreamWaitEvent(0, evWout, 0);
    gemm_mma<<<dim3(TT * BB / 128, (VOC + 127) / 128), 256, GEMM_SMEM>>>(
        hall, wout16, words, VOC, VOC, 512, b_out, nullptr);

    // fused log_softmax + softmax
    softmax_kernel<<<TT * BB, 256>>>(out);
}

// round 11
// speedup vs baseline: 4.9580x; 1.0419x over previous
#include <cuda_runtime.h>
#include <cuda_fp16.h>
#include <cstdint>
#include <cstddef>

#define TT   20
#define BB   64
#define NNF  196
#define VOC  10000
#define G4   2048
#define NBLK 128          // persistent LSTM grid

// ---------------- static device scratch ----------------
__device__ float g_fmean[BB * 512];
__device__ float g_ctx  [BB * 512];
__device__ float g_attl [BB * NNF];
__device__ float g_attw [BB * NNF];
__device__ float g_gpre [TT * BB * G4];
__device__ float g_words[TT * BB * VOC];
__device__ unsigned long long g_bar;   // monotonic across replays

__device__ __half g_Wout16[VOC * 512];
__device__ __half g_Wih16 [G4 * 1024];
__device__ __half g_A16   [TT * BB * 1024];
__device__ __half g_hall  [TT * BB * 512];
__device__ __half g_hb16  [2][BB * 512];

// ---------------- helpers ----------------
__device__ __forceinline__ uint32_t smem_u32(const void* p) {
    uint32_t a;
    asm("{ .reg .u64 t; cvta.to.shared.u64 t, %1; cvt.u32.u64 %0, t; }"
        : "=r"(a) : "l"(p));
    return a;
}
__device__ __forceinline__ void ldm_x4(uint32_t* r, uint32_t addr) {
    asm volatile("ldmatrix.sync.aligned.m8n8.x4.shared.b16 {%0,%1,%2,%3}, [%4];"
                 : "=r"(r[0]), "=r"(r[1]), "=r"(r[2]), "=r"(r[3]) : "r"(addr));
}
__device__ __forceinline__ void mma_fp16(float* d, const uint32_t* a, const uint32_t* b) {
    asm volatile(
        "mma.sync.aligned.m16n8k16.row.col.f32.f16.f16.f32 "
        "{%0,%1,%2,%3}, {%4,%5,%6,%7}, {%8,%9}, {%0,%1,%2,%3};"
        : "+f"(d[0]), "+f"(d[1]), "+f"(d[2]), "+f"(d[3])
        : "r"(a[0]), "r"(a[1]), "r"(a[2]), "r"(a[3]), "r"(b[0]), "r"(b[1]));
}
__device__ __forceinline__ void cpa16(uint32_t dst, const void* src, int srcsz) {
    asm volatile("cp.async.cg.shared.global [%0], [%1], 16, %2;"
                 :: "r"(dst), "l"(src), "r"(srcsz));
}
__device__ __forceinline__ void cpa_commit() {
    asm volatile("cp.async.commit_group;");
}
template<int NG> __device__ __forceinline__ void cpa_wait() {
    asm volatile("cp.async.wait_group %0;" :: "n"(NG));
}

// ============ single-pass fp16 GEMM: C[m,n] = sum_k A[m,k]*B[n,k] ==========
// BM=128, BN=128, BK=32; 8 warps (4x2); warp tile 32x64.
#define ASTR 40                         // padded fp16 row stride (80B)
#define BUFB (128 * ASTR * 2)           // one operand buffer: 10240 bytes
#define STAGEB (2 * BUFB)               // A|B per stage: 20480 bytes

__global__ void __launch_bounds__(256) gemm_mma(
    const __half* __restrict__ A, const __half* __restrict__ B,
    float* __restrict__ C, int N, int ldc, int K,
    const float* __restrict__ bias0, const float* __restrict__ bias1)
{
    extern __shared__ __align__(16) __half dsm[];
    const uint32_t smb = smem_u32(dsm);

    const int tid  = threadIdx.x;
    const int lane = tid & 31;
    const int w    = tid >> 5;
    const int wm   = w >> 1;
    const int wn   = w & 1;
    const int m0   = blockIdx.x * 128;
    const int n0   = blockIdx.y * 128;
    const int mbase = wm * 32;
    const int nbase = wn * 64;
    const int g = lane >> 2;
    const int q = lane & 3;

    const int i0 = tid, i1 = tid + 256;
    const int r0s = i0 >> 2, k0s = (i0 & 3) * 8;
    const int r1s = i1 >> 2, k1s = (i1 & 3) * 8;
    const int bsz0 = (n0 + r0s) < N ? 16 : 0;
    const int bsz1 = (n0 + r1s) < N ? 16 : 0;
    const uint32_t d0 = (uint32_t)(r0s * ASTR + k0s) * 2;
    const uint32_t d1 = (uint32_t)(r1s * ASTR + k1s) * 2;

    const int l7 = lane & 7;
    const uint32_t aRow = mbase + l7 + ((lane >> 3) & 1) * 8;
    const uint32_t aKof = (lane >> 4) * 16;
    const uint32_t bRow = nbase + l7 + (lane >> 4) * 8;
    const uint32_t bKof = ((lane >> 3) & 1) * 16;

    float acc[2][8][4];
    #pragma unroll
    for (int mt = 0; mt < 2; mt++)
        #pragma unroll
        for (int nt = 0; nt < 8; nt++)
            #pragma unroll
            for (int r = 0; r < 4; r++) acc[mt][nt][r] = 0.f;

    const int nk = K / 32;

    auto load_stage = [&](int kt, int s) {
        const int k0 = kt * 32;
        const uint32_t sb = smb + (uint32_t)s * STAGEB;
        cpa16(sb + d0,        A + (size_t)(m0 + r0s) * K + k0 + k0s, 16);
        cpa16(sb + d1,        A + (size_t)(m0 + r1s) * K + k0 + k1s, 16);
        cpa16(sb + BUFB + d0, B + (size_t)(n0 + r0s) * K + k0 + k0s, bsz0);
        cpa16(sb + BUFB + d1, B + (size_t)(n0 + r1s) * K + k0 + k1s, bsz1);
        cpa_commit();
    };

    load_stage(0, 0);

    for (int kt = 0; kt < nk; kt++) {
        if (kt + 1 < nk) load_stage(kt + 1, (kt + 1) & 1);
        if (kt + 1 < nk) cpa_wait<1>(); else cpa_wait<0>();
        __syncthreads();

        const uint32_t sb = smb + (uint32_t)(kt & 1) * STAGEB;
        const uint32_t bA = sb, bB = sb + BUFB;

        #pragma unroll
        for (int kk = 0; kk < 2; kk++) {
            const uint32_t kb = kk * 32;
            uint32_t ah[2][4];
            #pragma unroll
            for (int mt = 0; mt < 2; mt++) {
                const uint32_t ro = (aRow + mt * 16) * (ASTR * 2) + kb + aKof;
                ldm_x4(ah[mt], bA + ro);
            }
            #pragma unroll
            for (int np = 0; np < 4; np++) {
                const uint32_t ro = (bRow + np * 16) * (ASTR * 2) + kb + bKof;
                uint32_t tb[4];
                ldm_x4(tb, bB + ro);
                uint32_t bh0[2] = {tb[0], tb[1]}, bh1[2] = {tb[2], tb[3]};
                #pragma unroll
                for (int mt = 0; mt < 2; mt++) {
                    mma_fp16(acc[mt][np * 2 + 0], ah[mt], bh0);
                    mma_fp16(acc[mt][np * 2 + 1], ah[mt], bh1);
                }
            }
        }
        __syncthreads();
    }

    #pragma unroll
    for (int mt = 0; mt < 2; mt++) {
        #pragma unroll
        for (int nt = 0; nt < 8; nt++) {
            const int n = n0 + nbase + nt * 8 + q * 2;
            if (n < N) {
                #pragma unroll
                for (int half = 0; half < 2; half++) {
                    const int m = m0 + mbase + mt * 16 + g + half * 8;
                    float v0 = acc[mt][nt][half * 2 + 0];
                    float v1 = acc[mt][nt][half * 2 + 1];
                    if (bias0) { v0 += bias0[n]; v1 += bias0[n + 1]; }
                    if (bias1) { v0 += bias1[n]; v1 += bias1[n + 1]; }
                    *(float2*)(C + (size_t)m * ldc + n) = make_float2(v0, v1);
                }
            }
        }
    }
}

// ---------------- fp32 -> fp16, 8 elems/thread ----------------
__global__ void __launch_bounds__(256) cvt_hi8(
    const float* __restrict__ src, __half* __restrict__ hi, int total)
{
    const int i = (blockIdx.x * 256 + threadIdx.x) * 8;
    if (i < total) {
        float4 x0 = *(const float4*)(src + i);
        float4 x1 = *(const float4*)(src + i + 4);
        float xs[8] = {x0.x, x0.y, x0.z, x0.w, x1.x, x1.y, x1.z, x1.w};
        __half h8[8];
        #pragma unroll
        for (int j = 0; j < 8; j++) h8[j] = __float2half_rn(xs[j]);
        *(uint4*)(hi + i) = *(const uint4*)h8;
    }
}

// ---------------- concat A = [ctx(b) | embed(tok)] fp16 (rowmap inline) ------
__global__ void __launch_bounds__(256) cvt_concat8(const float* __restrict__ embed,
                                                   const int* __restrict__ captions) {
    const int i = (blockIdx.x * 256 + threadIdx.x) * 8;
    if (i < TT * BB * 1024) {
        const int r = i >> 10, k = i & 1023;
        const int b = r & 63, t = r >> 6;
        const float* sp;
        if (k < 512) {
            sp = g_ctx + b * 512 + k;
        } else {
            const int tok = captions[b * TT + t];
            sp = embed + (size_t)tok * 512 + (k - 512);
        }
        float4 x0 = *(const float4*)sp;
        float4 x1 = *(const float4*)(sp + 4);
        float xs[8] = {x0.x, x0.y, x0.z, x0.w, x1.x, x1.y, x1.z, x1.w};
        __half h8[8];
        #pragma unroll
        for (int j = 0; j < 8; j++) h8[j] = __float2half_rn(xs[j]);
        *(uint4*)(g_A16 + i) = *(const uint4*)h8;
    }
}

// ---------------- attention logits (parallel, 896 blocks) ----------------
__global__ void __launch_bounds__(256) attn_dot(const float* __restrict__ features,
                                                const float* __restrict__ W_av) {
    const int b   = blockIdx.x;
    const int n0  = blockIdx.y * 14;
    __shared__ float sW[512];
    const int tid = threadIdx.x;
    const int wid = tid >> 5, lane = tid & 31;
    for (int i = tid; i < 512; i += 256) sW[i] = W_av[i];
    __syncthreads();

    const float* fb = features + (size_t)b * NNF * 512;
    for (int n = n0 + wid; n < n0 + 14 && n < NNF; n += 8) {
        const float* fr = fb + (size_t)n * 512;
        float s0 = 0.f, s1 = 0.f, s2 = 0.f, s3 = 0.f;
        #pragma unroll
        for (int i = 0; i < 4; i++) {
            const int o = lane + i * 128;
            s0 = fmaf(fr[o],      sW[o],      s0);
            s1 = fmaf(fr[o + 32], sW[o + 32], s1);
            s2 = fmaf(fr[o + 64], sW[o + 64], s2);
            s3 = fmaf(fr[o + 96], sW[o + 96], s3);
        }
        float s = (s0 + s1) + (s2 + s3);
        #pragma unroll
        for (int o = 16; o; o >>= 1) s += __shfl_down_sync(0xffffffffu, s, o);
        if (!lane) g_attl[b * NNF + n] = s;
    }
}

// ---------------- softmax over N=196 -> weights ----------------
__global__ void __launch_bounds__(256) attn_wsm() {
    const int b = blockIdx.x;
    __shared__ float sA[NNF];
    __shared__ float sred[8];
    __shared__ float s_max, s_inv;
    const int tid = threadIdx.x;
    const int wid = tid >> 5, lane = tid & 31;

    for (int n = tid; n < NNF; n += 256) sA[n] = g_attl[b * NNF + n];
    __syncthreads();

    float m = -3.0e38f;
    for (int n = tid; n < NNF; n += 256) m = fmaxf(m, sA[n]);
    #pragma unroll
    for (int o = 16; o; o >>= 1) m = fmaxf(m, __shfl_down_sync(0xffffffffu, m, o));
    if (!lane) sred[wid] = m;
    __syncthreads();
    if (tid == 0) {
        float mm = sred[0];
        #pragma unroll
        for (int i = 1; i < 8; i++) mm = fmaxf(mm, sred[i]);
        s_max = mm;
    }
    __syncthreads();
    const float mm = s_max;

    float s = 0.f;
    for (int n = tid; n < NNF; n += 256) { float e = __expf(sA[n] - mm); sA[n] = e; s += e; }
    #pragma unroll
    for (int o = 16; o; o >>= 1) s += __shfl_down_sync(0xffffffffu, s, o);
    if (!lane) sred[wid] = s;
    __syncthreads();
    if (tid == 0) {
        float ss = 0.f;
        #pragma unroll
        for (int i = 0; i < 8; i++) ss += sred[i];
        s_inv = 1.f / ss;
    }
    __syncthreads();
    const float inv = s_inv;
    for (int n = tid; n < NNF; n += 256) g_attw[b * NNF + n] = sA[n] * inv;
}

// ---------------- ctx + fmean: grid (BB, 8), 4-way row split ----------------
__global__ void __launch_bounds__(256) attn_ctx(const float* __restrict__ features) {
    const int b  = blockIdx.x;
    const int v0 = blockIdx.y * 64;
    const int c  = threadIdx.x & 63;
    const int rg = threadIdx.x >> 6;          // 0..3, rows rg*49..+48
    __shared__ float sw[NNF];
    __shared__ float pac[4][64];
    __shared__ float pam[4][64];
    for (int i = threadIdx.x; i < NNF; i += 256) sw[i] = g_attw[b * NNF + i];
    __syncthreads();

    const float* fp = features + (size_t)b * NNF * 512 + v0 + c;
    float ac = 0.f, am = 0.f;
    const int nb = rg * 49;
    #pragma unroll 7
    for (int j = 0; j < 49; j++) {
        const int n = nb + j;
        const float f = fp[(size_t)n * 512];
        ac = fmaf(sw[n], f, ac);
        am += f;
    }
    pac[rg][c] = ac;
    pam[rg][c] = am;
    __syncthreads();
    if (rg == 0) {
        const float a = pac[0][c] + pac[1][c] + pac[2][c] + pac[3][c];
        const float m = pam[0][c] + pam[1][c] + pam[2][c] + pam[3][c];
        g_ctx  [b * 512 + v0 + c] = a;
        g_fmean[b * 512 + v0 + c] = m * (1.f / (float)NNF);
    }
}

// ================= persistent HMMA LSTM (phase0 + 20 steps, 1 launch) =========
__device__ __forceinline__ void gbar() {
    __syncthreads();
    if (threadIdx.x == 0) {
        unsigned long long old;
        asm volatile("atom.release.gpu.global.add.u64 %0, [%1], %2;"
                     : "=l"(old) : "l"(&g_bar), "l"(1ULL) : "memory");
        unsigned long long tgt = old - (old & (unsigned long long)(NBLK - 1)) + (unsigned long long)NBLK;
        unsigned long long cur;
        do {
            asm volatile("ld.global.acquire.gpu.u64 %0, [%1];" : "=l"(cur) : "l"(&g_bar));
        } while (cur < tgt);
    }
    __syncthreads();
}

#define STRH 520   // fp16 row stride for sW/sH (1040 B, conflict-free ldmatrix)

__global__ void __launch_bounds__(256, 1) lstm_kernel(
    const float* __restrict__ Winit_h, const float* __restrict__ Winit_c,
    const float* __restrict__ Whh)
{
    extern __shared__ __half smh[];
    __half* sW = smh;                 // [16][STRH]  gate-row weights
    __half* sH = smh + 16 * STRH;     // [64][STRH]  h (fp16)

    const int tid  = threadIdx.x;
    const int w    = tid >> 5;
    const int lane = tid & 31;
    const int l7   = lane & 7;
    const int r    = lane >> 2;       // 0..7
    const int q    = lane & 3;
    const int u0   = blockIdx.x * 4;

    const uint32_t sWb = smem_u32(sW);
    const uint32_t sHb = smem_u32(sH);
    const uint32_t aOff = (uint32_t)((l7 + ((lane >> 3) & 1) * 8) * (STRH * 2) + (lane >> 4) * 16);
    const uint32_t bOff = (uint32_t)((w * 8 + l7) * (STRH * 2) + (lane >> 3) * 16);

    // ---- phase 0: sW rows 0-3 = Winit_h[u0+j], 4-7 = Winit_c[u0+j], 8-15 = 0
    for (int idx = tid; idx < 2048; idx += 256) {
        const int m = idx >> 7, c4 = idx & 127;
        __half2 p0 = __float2half2_rn(0.f), p1 = p0;
        if (m < 8) {
            const float* src = (m < 4) ? (Winit_h + (size_t)(u0 + m) * 512)
                                       : (Winit_c + (size_t)(u0 + m - 4) * 512);
            float4 v = *(const float4*)(src + c4 * 4);
            p0 = __floats2half2_rn(v.x, v.y);
            p1 = __floats2half2_rn(v.z, v.w);
        }
        *(__half2*)(sW + m * STRH + c4 * 4)     = p0;
        *(__half2*)(sW + m * STRH + c4 * 4 + 2) = p1;
    }
    for (int idx = tid; idx < 8192; idx += 256) {
        const int row = idx >> 7, c4 = idx & 127;
        float4 v = *(const float4*)(g_fmean + row * 512 + c4 * 4);
        *(__half2*)(sH + row * STRH + c4 * 4)     = __floats2half2_rn(v.x, v.y);
        *(__half2*)(sH + row * STRH + c4 * 4 + 2) = __floats2half2_rn(v.z, v.w);
    }
    __syncthreads();

    float acc[4] = {0.f, 0.f, 0.f, 0.f};
    #pragma unroll
    for (int kt2 = 0; kt2 < 16; kt2++) {
        uint32_t a0[4], a1[4], tb[4];
        ldm_x4(a0, sWb + aOff + kt2 * 64);
        ldm_x4(a1, sWb + aOff + kt2 * 64 + 32);
        ldm_x4(tb, sHb + bOff + kt2 * 64);
        uint32_t b0v[2] = {tb[0], tb[1]}, b1v[2] = {tb[2], tb[3]};
        mma_fp16(acc, a0, b0v);
        mma_fp16(acc, a1, b1v);
    }
    const int b0i = w * 8 + q * 2;
    float c2[2] = {0.f, 0.f};
    {
        const float cc0 = __shfl_xor_sync(0xffffffffu, acc[0], 16);
        const float cc1 = __shfl_xor_sync(0xffffffffu, acc[1], 16);
        if (lane < 16) {
            c2[0] = cc0; c2[1] = cc1;
            g_hb16[0][b0i * 512 + u0 + r]       = __float2half_rn(acc[0]);
            g_hb16[0][(b0i + 1) * 512 + u0 + r] = __float2half_rn(acc[1]);
        }
    }
    __syncthreads();

    // ---- steady-state weights: sW row m = Whh[(m>>2)*512 + u0 + (m&3)]
    for (int idx = tid; idx < 2048; idx += 256) {
        const int m = idx >> 7, c4 = idx & 127;
        const int grow = (m >> 2) * 512 + u0 + (m & 3);
        float4 v = *(const float4*)(Whh + (size_t)grow * 512 + c4 * 4);
        *(__half2*)(sW + m * STRH + c4 * 4)     = __floats2half2_rn(v.x, v.y);
        *(__half2*)(sW + m * STRH + c4 * 4 + 2) = __floats2half2_rn(v.z, v.w);
    }

    const int m1 = r, m2 = r + 8;
    const int col1 = (m1 >> 2) * 512 + u0 + (m1 & 3);
    const int col2 = (m2 >> 2) * 512 + u0 + (m2 & 3);
    float gp[4];
    {
        const float* gr = g_gpre;
        gp[0] = gr[(size_t)b0i * G4 + col1];
        gp[1] = gr[(size_t)(b0i + 1) * G4 + col1];
        gp[2] = gr[(size_t)b0i * G4 + col2];
        gp[3] = gr[(size_t)(b0i + 1) * G4 + col2];
    }
    gbar();

    for (int t = 0; t < TT; t++) {
        {
            const uint4* src = (const uint4*)g_hb16[t & 1];
            for (int idx = tid; idx < 4096; idx += 256) {
                const int row = idx >> 6, c8 = idx & 63;
                *(uint4*)(sH + row * STRH + c8 * 8) = src[row * 64 + c8];
            }
        }
        __syncthreads();

        acc[0] = gp[0]; acc[1] = gp[1]; acc[2] = gp[2]; acc[3] = gp[3];
        #pragma unroll
        for (int kt2 = 0; kt2 < 16; kt2++) {
            uint32_t a0[4], a1[4], tb[4];
            ldm_x4(a0, sWb + aOff + kt2 * 64);
            ldm_x4(a1, sWb + aOff + kt2 * 64 + 32);
            ldm_x4(tb, sHb + bOff + kt2 * 64);
            uint32_t b0v[2] = {tb[0], tb[1]}, b1v[2] = {tb[2], tb[3]};
            mma_fp16(acc, a0, b0v);
            mma_fp16(acc, a1, b1v);
        }

        const float f0 = __shfl_xor_sync(0xffffffffu, acc[0], 16);
        const float f1 = __shfl_xor_sync(0xffffffffu, acc[1], 16);
        const float o0 = __shfl_xor_sync(0xffffffffu, acc[2], 16);
        const float o1 = __shfl_xor_sync(0xffffffffu, acc[3], 16);
        if (lane < 16) {
            #pragma unroll
            for (int ii = 0; ii < 2; ii++) {
                const float gi = acc[ii];
                const float gg = acc[2 + ii];
                const float gf = ii ? f1 : f0;
                const float go = ii ? o1 : o0;
                const float si = 1.f / (1.f + __expf(-gi));
                const float sf = 1.f / (1.f + __expf(-gf));
                const float so = 1.f / (1.f + __expf(-go));
                c2[ii] = sf * c2[ii] + si * tanhf(gg);
                const float hnew = so * tanhf(c2[ii]);
                const __half hh = __float2half_rn(hnew);
                const int b = b0i + ii;
                g_hb16[(t + 1) & 1][b * 512 + u0 + r] = hh;
                g_hall[(size_t)(t * 64 + b) * 512 + u0 + r] = hh;
            }
        }

        if (t < TT - 1) {
            const float* gr = g_gpre + (size_t)(t + 1) * BB * G4;
            gp[0] = gr[(size_t)b0i * G4 + col1];
            gp[1] = gr[(size_t)(b0i + 1) * G4 + col1];
            gp[2] = gr[(size_t)b0i * G4 + col2];
            gp[3] = gr[(size_t)(b0i + 1) * G4 + col2];
            gbar();
        }
    }
}

// ---------------- fused log_softmax + softmax, 512 threads/row ----------------
__global__ void __launch_bounds__(512) softmax_kernel(float* __restrict__ out) {
    const int r = blockIdx.x;
    const float4* x4 = (const float4*)(g_words + (size_t)r * VOC);
    float4* ols = (float4*)(out + (size_t)r * VOC);
    float4* osm = (float4*)(out + (size_t)TT * BB * VOC + (size_t)r * VOC);

    float m = -3.0e38f, s = 0.f;
    for (int i = threadIdx.x; i < VOC / 4; i += 512) {
        float4 v = x4[i];
        float m4 = fmaxf(fmaxf(v.x, v.y), fmaxf(v.z, v.w));
        float mn = fmaxf(m, m4);
        s = s * __expf(m - mn) + __expf(v.x - mn) + __expf(v.y - mn)
                               + __expf(v.z - mn) + __expf(v.w - mn);
        m = mn;
    }
    #pragma unroll
    for (int o = 16; o; o >>= 1) {
        float m2 = __shfl_down_sync(0xffffffffu, m, o);
        float s2 = __shfl_down_sync(0xffffffffu, s, o);
        float mx = fmaxf(m, m2);
        s = s * __expf(m - mx) + s2 * __expf(m2 - mx);
        m = mx;
    }
    __shared__ float sm[16], ss[16];
    __shared__ float bM, bS;
    const int wid = threadIdx.x >> 5, lane = threadIdx.x & 31;
    if (!lane) { sm[wid] = m; ss[wid] = s; }
    __syncthreads();
    if (threadIdx.x == 0) {
        float M = sm[0], S = ss[0];
        #pragma unroll
        for (int i = 1; i < 16; i++) {
            float mx = fmaxf(M, sm[i]);
            S = S * __expf(M - mx) + ss[i] * __expf(sm[i] - mx);
            M = mx;
        }
        bM = M; bS = S;
    }
    __syncthreads();
    const float M = bM;
    const float Sinv = 1.f / bS;
    const float lg = __logf(bS);
    for (int i = threadIdx.x; i < VOC / 4; i += 512) {
        float4 v = x4[i];
        float4 l4, p4;
        l4.x = v.x - M - lg; p4.x = __expf(v.x - M) * Sinv;
        l4.y = v.y - M - lg; p4.y = __expf(v.y - M) * Sinv;
        l4.z = v.z - M - lg; p4.z = __expf(v.z - M) * Sinv;
        l4.w = v.w - M - lg; p4.w = __expf(v.w - M) * Sinv;
        ols[i] = l4;
        osm[i] = p4;
    }
}

// ---------------- launch ----------------
extern "C" void kernel_launch(void* const* d_in, const int* in_sizes, int n_in,
                              void* d_out, int out_size) {
    (void)in_sizes; (void)n_in; (void)out_size;
    const float* features = (const float*)d_in[0];
    const int*   captions = (const int*)  d_in[1];
    const float* W_init_h = (const float*)d_in[2];
    const float* W_init_c = (const float*)d_in[3];
    const float* W_av     = (const float*)d_in[4];
    // d_in[5] b_av, d_in[6] W_ah, d_in[7] b_ah : dead (softmax shift-invariance)
    const float* embed    = (const float*)d_in[8];
    const float* W_ih     = (const float*)d_in[9];
    const float* W_hh     = (const float*)d_in[10];
    const float* b_ih     = (const float*)d_in[11];
    const float* b_hh     = (const float*)d_in[12];
    const float* W_out    = (const float*)d_in[13];
    const float* b_out    = (const float*)d_in[14];
    float* out = (float*)d_out;

    float *gpre, *words;
    __half *wout16, *wih16, *a16, *hall;
    cudaGetSymbolAddress((void**)&gpre,   g_gpre);
    cudaGetSymbolAddress((void**)&words,  g_words);
    cudaGetSymbolAddress((void**)&wout16, g_Wout16);
    cudaGetSymbolAddress((void**)&wih16,  g_Wih16);
    cudaGetSymbolAddress((void**)&a16,    g_A16);
    cudaGetSymbolAddress((void**)&hall,   g_hall);

    // lazy one-time setup (outside graph capture: first call is the correctness run)
    static bool init_done = false;
    static cudaStream_t sB;
    static cudaEvent_t evFork, evWout;
    if (!init_done) {
        const int LSTM_SMEM0 = (16 + 64) * STRH * 2;
        cudaFuncSetAttribute(lstm_kernel, cudaFuncAttributeMaxDynamicSharedMemorySize, LSTM_SMEM0);
        cudaFuncSetAttribute(gemm_mma, cudaFuncAttributeMaxDynamicSharedMemorySize, 2 * STAGEB);
        cudaStreamCreateWithFlags(&sB, cudaStreamNonBlocking);
        cudaEventCreateWithFlags(&evFork, cudaEventDisableTiming);
        cudaEventCreateWithFlags(&evWout, cudaEventDisableTiming);
        init_done = true;
    }
    const int LSTM_SMEM = (16 + 64) * STRH * 2;       // 83200 B
    const int GEMM_SMEM = 2 * STAGEB;                 // 40960 B

    // fork: W_out conversion runs concurrently with the attention/gpre/LSTM chain
    cudaEventRecord(evFork, 0);
    cudaStreamWaitEvent(sB, evFork, 0);
    cvt_hi8<<<(VOC * 512 / 8 + 255) / 256, 256, 0, sB>>>(W_out, wout16, VOC * 512);
    cudaEventRecord(evWout, sB);

    // attention: logits (896 blocks), softmax weights, ctx+fmean (512 blocks)
    attn_dot<<<dim3(BB, 14), 256>>>(features, W_av);
    attn_wsm<<<BB, 256>>>();
    attn_ctx<<<dim3(BB, 8), 256>>>(features);

    // concat A (rowmap inline) + W_ih conversion
    cvt_concat8<<<(TT * BB * 1024 / 8 + 255) / 256, 256>>>(embed, captions);
    cvt_hi8<<<(G4 * 1024 / 8 + 255) / 256, 256>>>(W_ih, wih16, G4 * 1024);

    // gpre = [ctx|emb] @ W_ih^T + b_ih + b_hh   (K=1024)
    gemm_mma<<<dim3(TT * BB / 128, G4 / 128), 256, GEMM_SMEM>>>(
        a16, wih16, gpre, G4, G4, 1024, b_ih, b_hh);

    // persistent HMMA LSTM
    lstm_kernel<<<NBLK, 256, LSTM_SMEM>>>(W_init_h, W_init_c, W_hh);

    // join W_out conversion, then words = hall @ W_out^T + b_out (K=512)
    cudaStreamWaitEvent(0, evWout, 0);
    gemm_mma<<<dim3(TT * BB / 128, (VOC + 127) / 128), 256, GEMM_SMEM>>>(
        hall, wout16, words, VOC, VOC, 512, b_out, nullptr);

    // fused log_softmax + softmax
    softmax_kernel<<<TT * BB, 512>>>(out);
}